// round 7
// baseline (speedup 1.0000x reference)
#include <cuda_runtime.h>
#include <math.h>
#include <stdint.h>

#define Bv 2
#define Lv 2048
#define Dv 1024
#define Hv 16
#define HDv 64
#define ML (Bv*Lv)     // 4096
#define N3D (3*Dv)     // 3072

// ---------------- scratch (device globals; no allocation allowed) ----------
__device__ float g_qkv[2][ML][N3D];    // [branch][b*L+l][3D]  ~100MB
__device__ float g_attn[2][ML][Dv];    // [branch][b*L+l][D]   ~33MB
__device__ float g_cos[Bv][Lv][32];
__device__ float g_sin[Bv][Lv][32];
__device__ int   g_cidq[Bv][Lv];       // chain id; Lv for invalid positions
__device__ int   g_cidk[Bv][Lv];       // chain id; -1 for invalid positions

// ---------------- metadata: chain ids, positions, rope tables --------------
__global__ void meta_kernel(const void* __restrict__ maskraw)
{
    const int b   = blockIdx.x;
    const int tid = threadIdx.x;   // 256 threads

    __shared__ int slen[Lv];
    __shared__ int scs[Lv];
    __shared__ int spart[257];
    __shared__ int sis64;

    if (tid == 0) {
        // int64 little-endian small positive values => every odd int32 word 0
        const int* w = (const int*)maskraw;
        bool odd_zero = true, even_nz = false;
        for (int i = 0; i < 32; i++) {
            if (w[2*i+1] != 0) odd_zero = false;
            if (w[2*i]   != 0) even_nz  = true;
        }
        sis64 = (odd_zero && even_nz) ? 1 : 0;
    }
    __syncthreads();
    const int is64 = sis64;

    for (int i = tid; i < Lv; i += 256) {
        long long v;
        if (is64) v = ((const long long*)maskraw)[b*Lv + i];
        else      v = ((const int*)maskraw)[b*Lv + i];
        slen[i] = (int)v;
    }
    __syncthreads();

    // two-level inclusive scan
    int base = tid * 8;
    int s = 0, loc[8];
    #pragma unroll
    for (int k = 0; k < 8; k++) { s += slen[base + k]; loc[k] = s; }
    spart[tid] = s;
    __syncthreads();
    if (tid == 0) {
        int acc = 0;
        for (int i = 0; i < 256; i++) { int t = spart[i]; spart[i] = acc; acc += t; }
        spart[256] = acc;
    }
    __syncthreads();
    int off = spart[tid];
    #pragma unroll
    for (int k = 0; k < 8; k++) scs[base + k] = off + loc[k];
    __syncthreads();

    const int total = scs[Lv - 1];

    for (int p = tid; p < Lv; p += 256) {
        // upper_bound: first idx with scs[idx] > p  (== jnp.searchsorted side='right')
        int lo = 0, hi = Lv;
        while (lo < hi) { int mid = (lo + hi) >> 1; if (scs[mid] > p) hi = mid; else lo = mid + 1; }
        const int cid = lo;                    // == Lv for p >= total
        const bool valid = (p < total);
        const int prev = (cid > 0 && cid <= Lv) ? scs[(cid - 1 < Lv) ? cid - 1 : Lv - 1] : 0;
        const float pos = valid ? (float)(p - prev) : 0.0f;

        g_cidq[b][p] = valid ? cid : Lv;
        g_cidk[b][p] = valid ? cid : -1;

        for (int d2 = 0; d2 < 32; d2++) {
            float inv = powf(10000.0f, -((float)(2 * d2)) / 64.0f);
            float a = pos * inv;
            float sn, cs;
            sincosf(a, &sn, &cs);
            g_cos[b][p][d2] = cs;
            g_sin[b][p][d2] = sn;
        }
    }
}

// ---------------- QKV GEMM: C[m][n] = X[m][:] . W[n][:] + bias[n] -----------
// M=4096, N=3072, K=1024.  BM=128, BN=64, BK=32, 256 threads, 8x4 frags.
#define GBM 128
#define GBN 64
#define GBK 32

__global__ void __launch_bounds__(256) qkv_gemm(
    const float* __restrict__ X,
    const float* __restrict__ W0, const float* __restrict__ b0,
    const float* __restrict__ W1, const float* __restrict__ b1)
{
    const int br = blockIdx.z;
    const float* __restrict__ W    = br ? W1 : W0;
    const float* __restrict__ bias = br ? b1 : b0;

    const int m0 = blockIdx.y * GBM;
    const int n0 = blockIdx.x * GBN;

    __shared__ __align__(16) float As[GBK][GBM + 4];
    __shared__ __align__(16) float Bs[GBK][GBN + 4];

    const int tid = threadIdx.x;
    const int tx = tid % 16, ty = tid / 16;
    const int lk = tid % 32, lr = tid / 32;   // loader coords

    float acc[8][4];
    #pragma unroll
    for (int i = 0; i < 8; i++)
        #pragma unroll
        for (int j = 0; j < 4; j++) acc[i][j] = 0.0f;

    for (int kt = 0; kt < Dv; kt += GBK) {
        #pragma unroll
        for (int r0 = 0; r0 < GBM; r0 += 8)
            As[lk][r0 + lr] = X[(size_t)(m0 + r0 + lr) * Dv + kt + lk];
        #pragma unroll
        for (int r0 = 0; r0 < GBN; r0 += 8)
            Bs[lk][r0 + lr] = W[(size_t)(n0 + r0 + lr) * Dv + kt + lk];
        __syncthreads();

        #pragma unroll
        for (int k = 0; k < GBK; k++) {
            float a[8], bb[4];
            *(float4*)&a[0] = *(const float4*)&As[k][ty * 8];
            *(float4*)&a[4] = *(const float4*)&As[k][ty * 8 + 4];
            *(float4*)&bb[0] = *(const float4*)&Bs[k][tx * 4];
            #pragma unroll
            for (int i = 0; i < 8; i++)
                #pragma unroll
                for (int j = 0; j < 4; j++)
                    acc[i][j] = fmaf(a[i], bb[j], acc[i][j]);
        }
        __syncthreads();
    }

    #pragma unroll
    for (int i = 0; i < 8; i++) {
        const int row = m0 + ty * 8 + i;
        #pragma unroll
        for (int j = 0; j < 4; j++) {
            const int col = n0 + tx * 4 + j;
            g_qkv[br][row][col] = acc[i][j] + bias[col];
        }
    }
}

// ---------------- attention: flash-style, 64x64 tiles ----------------------
// grid: (L/64, H, 2*B)  z: b = z&1, branch = z>>1 ; 256 threads
#define TQ 64
#define TK 64
#define QSTR 68
#define SSTR 65

__global__ void __launch_bounds__(256) attn_kernel()
{
    const int qt = blockIdx.x;
    const int h  = blockIdx.y;
    const int z  = blockIdx.z;
    const int b  = z & 1;
    const int br = z >> 1;
    const bool intra = (br == 0);

    extern __shared__ __align__(16) float sm[];
    float* Qst   = sm;                         // [64][68]  (d-major)
    float* Kst   = Qst + 64 * QSTR;            // [64][68]  (d-major)
    float* Vs    = Kst + 64 * QSTR;            // [64][68]  (j-major)
    float* Ssh   = Vs  + 64 * QSTR;            // [64][65]
    float* alpha = Ssh + 64 * SSTR;            // [64]
    float* lsh   = alpha + 64;                 // [64]
    int*   qcid  = (int*)(lsh + 64);           // [64]
    int*   kcid  = qcid + 64;                  // [64]

    const int tid = threadIdx.x;
    const int tx = tid % 16, ty = tid / 16;
    const float* __restrict__ qkv = &g_qkv[br][(size_t)b * Lv][0];

    // ---- load Q tile with scale + rope (d-major transposed layout)
    #pragma unroll
    for (int it = 0; it < 8; it++) {
        const int idx = it * 256 + tid;
        const int i = idx >> 5, dp = idx & 31;
        const int row = qt * TQ + i;
        const float q1 = qkv[(size_t)row * N3D + h * HDv + dp]      * 0.125f;
        const float q2 = qkv[(size_t)row * N3D + h * HDv + dp + 32] * 0.125f;
        const float c = g_cos[b][row][dp], s = g_sin[b][row][dp];
        Qst[dp * QSTR + i]        = q1 * c - q2 * s;
        Qst[(dp + 32) * QSTR + i] = q2 * c + q1 * s;
    }
    if (tid < 64) qcid[tid] = g_cidq[b][qt * TQ + tid];

    float acc[4][4];
    #pragma unroll
    for (int i = 0; i < 4; i++)
        #pragma unroll
        for (int j = 0; j < 4; j++) acc[i][j] = 0.0f;

    float mrow = -INFINITY, lrow = 0.0f;
    const int r  = tid >> 2;   // softmax row owned (replicated x4)
    const int q4 = tid & 3;

    for (int kt = 0; kt < Lv / TK; kt++) {
        // ---- load K tile with rope (d-major)
        #pragma unroll
        for (int it = 0; it < 8; it++) {
            const int idx = it * 256 + tid;
            const int j = idx >> 5, dp = idx & 31;
            const int krow = kt * TK + j;
            const float k1 = qkv[(size_t)krow * N3D + Dv + h * HDv + dp];
            const float k2 = qkv[(size_t)krow * N3D + Dv + h * HDv + dp + 32];
            const float c = g_cos[b][krow][dp], s = g_sin[b][krow][dp];
            Kst[dp * QSTR + j]        = k1 * c - k2 * s;
            Kst[(dp + 32) * QSTR + j] = k2 * c + k1 * s;
        }
        // ---- load V tile (j-major, vectorized)
        {
            const int dd4 = (tid % 16) * 4;
            const int j0  = tid / 16;
            #pragma unroll
            for (int jj0 = 0; jj0 < TK; jj0 += 16) {
                const int j = j0 + jj0;
                const int krow = kt * TK + j;
                float4 v = *(const float4*)&qkv[(size_t)krow * N3D + 2 * Dv + h * HDv + dd4];
                *(float4*)&Vs[j * QSTR + dd4] = v;
            }
        }
        if (tid < 64) kcid[tid] = g_cidk[b][kt * TK + tid];
        __syncthreads();

        // ---- S = Q K^T (64x64), 4x4 frags
        float sv[4][4];
        #pragma unroll
        for (int i = 0; i < 4; i++)
            #pragma unroll
            for (int j = 0; j < 4; j++) sv[i][j] = 0.0f;
        #pragma unroll
        for (int d = 0; d < HDv; d++) {
            float a[4], bb[4];
            *(float4*)&a[0]  = *(const float4*)&Qst[d * QSTR + ty * 4];
            *(float4*)&bb[0] = *(const float4*)&Kst[d * QSTR + tx * 4];
            #pragma unroll
            for (int i = 0; i < 4; i++)
                #pragma unroll
                for (int j = 0; j < 4; j++)
                    sv[i][j] = fmaf(a[i], bb[j], sv[i][j]);
        }
        // ---- mask & write S to shared
        #pragma unroll
        for (int ii = 0; ii < 4; ii++) {
            const int i = ty * 4 + ii;
            const int qc = qcid[i];
            #pragma unroll
            for (int jj = 0; jj < 4; jj++) {
                const int j = tx * 4 + jj;
                const int kc = kcid[j];
                const bool allowed = (kc >= 0) && ((kc == qc) == intra);
                Ssh[i * SSTR + j] = allowed ? sv[ii][jj] : -INFINITY;
            }
        }
        __syncthreads();

        // ---- online softmax: 4 threads per row, 16 entries each
        {
            float tmax = -INFINITY;
            #pragma unroll
            for (int jj = 0; jj < 16; jj++)
                tmax = fmaxf(tmax, Ssh[r * SSTR + q4 * 16 + jj]);
            tmax = fmaxf(tmax, __shfl_xor_sync(0xffffffffu, tmax, 1));
            tmax = fmaxf(tmax, __shfl_xor_sync(0xffffffffu, tmax, 2));

            const float mnew = fmaxf(mrow, tmax);
            float af, tsum = 0.0f;
            if (mnew == -INFINITY) {
                af = 1.0f;
                #pragma unroll
                for (int jj = 0; jj < 16; jj++)
                    Ssh[r * SSTR + q4 * 16 + jj] = 0.0f;
            } else {
                af = __expf(mrow - mnew);   // exp(-inf)=0 fine
                #pragma unroll
                for (int jj = 0; jj < 16; jj++) {
                    float p = __expf(Ssh[r * SSTR + q4 * 16 + jj] - mnew);
                    tsum += p;
                    Ssh[r * SSTR + q4 * 16 + jj] = p;
                }
            }
            tsum += __shfl_xor_sync(0xffffffffu, tsum, 1);
            tsum += __shfl_xor_sync(0xffffffffu, tsum, 2);
            lrow = lrow * af + tsum;
            mrow = mnew;
            if (q4 == 0) alpha[r] = af;
        }
        __syncthreads();

        // ---- O = O*alpha + P V
        {
            float al[4];
            #pragma unroll
            for (int ii = 0; ii < 4; ii++) al[ii] = alpha[ty * 4 + ii];
            #pragma unroll
            for (int ii = 0; ii < 4; ii++)
                #pragma unroll
                for (int jj = 0; jj < 4; jj++) acc[ii][jj] *= al[ii];

            #pragma unroll
            for (int j = 0; j < TK; j++) {
                float v[4], p[4];
                *(float4*)&v[0] = *(const float4*)&Vs[j * QSTR + tx * 4];
                #pragma unroll
                for (int ii = 0; ii < 4; ii++) p[ii] = Ssh[(ty * 4 + ii) * SSTR + j];
                #pragma unroll
                for (int ii = 0; ii < 4; ii++)
                    #pragma unroll
                    for (int jj = 0; jj < 4; jj++)
                        acc[ii][jj] = fmaf(p[ii], v[jj], acc[ii][jj]);
            }
        }
        __syncthreads();
    }

    if (q4 == 0) lsh[r] = lrow;
    __syncthreads();

    #pragma unroll
    for (int ii = 0; ii < 4; ii++) {
        const int i = ty * 4 + ii;
        const int row = qt * TQ + i;
        const float lv = lsh[i];
        const float inv = (lv > 0.0f) ? (1.0f / lv) : 0.0f;
        #pragma unroll
        for (int jj = 0; jj < 4; jj++) {
            const int dd = tx * 4 + jj;
            g_attn[br][(size_t)b * Lv + row][h * HDv + dd] = acc[ii][jj] * inv;
        }
    }
}

// ---------------- output GEMM: Y = (A0+A1) Wout^T + bout -------------------
__global__ void __launch_bounds__(256) out_gemm(
    const float* __restrict__ W, const float* __restrict__ bias,
    float* __restrict__ Y)
{
    const int m0 = blockIdx.y * GBM;
    const int n0 = blockIdx.x * GBN;

    __shared__ __align__(16) float As[GBK][GBM + 4];
    __shared__ __align__(16) float Bs[GBK][GBN + 4];

    const int tid = threadIdx.x;
    const int tx = tid % 16, ty = tid / 16;
    const int lk = tid % 32, lr = tid / 32;

    float acc[8][4];
    #pragma unroll
    for (int i = 0; i < 8; i++)
        #pragma unroll
        for (int j = 0; j < 4; j++) acc[i][j] = 0.0f;

    for (int kt = 0; kt < Dv; kt += GBK) {
        #pragma unroll
        for (int r0 = 0; r0 < GBM; r0 += 8) {
            const int m = m0 + r0 + lr;
            As[lk][r0 + lr] = g_attn[0][m][kt + lk] + g_attn[1][m][kt + lk];
        }
        #pragma unroll
        for (int r0 = 0; r0 < GBN; r0 += 8)
            Bs[lk][r0 + lr] = W[(size_t)(n0 + r0 + lr) * Dv + kt + lk];
        __syncthreads();

        #pragma unroll
        for (int k = 0; k < GBK; k++) {
            float a[8], bb[4];
            *(float4*)&a[0] = *(const float4*)&As[k][ty * 8];
            *(float4*)&a[4] = *(const float4*)&As[k][ty * 8 + 4];
            *(float4*)&bb[0] = *(const float4*)&Bs[k][tx * 4];
            #pragma unroll
            for (int i = 0; i < 8; i++)
                #pragma unroll
                for (int j = 0; j < 4; j++)
                    acc[i][j] = fmaf(a[i], bb[j], acc[i][j]);
        }
        __syncthreads();
    }

    #pragma unroll
    for (int i = 0; i < 8; i++) {
        const int row = m0 + ty * 8 + i;
        #pragma unroll
        for (int j = 0; j < 4; j++) {
            const int col = n0 + tx * 4 + j;
            Y[(size_t)row * Dv + col] = acc[i][j] + bias[col];
        }
    }
}

// ---------------- launcher --------------------------------------------------
extern "C" void kernel_launch(void* const* d_in, const int* in_sizes, int n_in,
                              void* d_out, int out_size)
{
    const float* hidden = (const float*)d_in[0];
    const void*  mask   = d_in[1];
    const float* Wi = (const float*)d_in[2];
    const float* bi = (const float*)d_in[3];
    const float* We = (const float*)d_in[4];
    const float* be = (const float*)d_in[5];
    const float* Wo = (const float*)d_in[6];
    const float* bo = (const float*)d_in[7];
    float* out = (float*)d_out;

    // metadata + rope tables
    meta_kernel<<<Bv, 256>>>(mask);

    // qkv for both branches
    dim3 g1(N3D / GBN, ML / GBM, 2);
    qkv_gemm<<<g1, 256>>>(hidden, Wi, bi, We, be);

    // attention (dynamic smem ~70KB)
    const size_t smem = (size_t)(3 * 64 * QSTR + 64 * SSTR + 128) * sizeof(float)
                      + 128 * sizeof(int);
    cudaFuncSetAttribute(attn_kernel, cudaFuncAttributeMaxDynamicSharedMemorySize, (int)smem);
    dim3 g2(Lv / TQ, Hv, 2 * Bv);
    attn_kernel<<<g2, 256, smem>>>();

    // output projection
    dim3 g3(Dv / GBN, ML / GBM);
    out_gemm<<<g3, 256>>>(Wo, bo, out);
}

// round 8
// speedup vs baseline: 2.4074x; 2.4074x over previous
#include <cuda_runtime.h>
#include <math.h>
#include <stdint.h>

#define Bv 2
#define Lv 2048
#define Dv 1024
#define Hv 16
#define HDv 64
#define ML (Bv*Lv)     // 4096
#define N3D (3*Dv)     // 3072

// ---------------- scratch (device globals; no allocation allowed) ----------
__device__ float g_qkv[2][ML][N3D];                 // un-roped qkv, both branches
__device__ float g_attn[2][ML][Dv];                 // attention outputs
__device__ __align__(16) float g_q[2*2*16*2048*64]; // roped+scaled, tf32, [br][b][h][l][d]
__device__ __align__(16) float g_k[2*2*16*2048*64];
__device__ __align__(16) float g_v[2*2*16*2048*64];
__device__ float g_cos[Bv][Lv][32];
__device__ float g_sin[Bv][Lv][32];
__device__ int   g_cidq[Bv][Lv];   // chain id; Lv for invalid positions
__device__ int   g_cidk[Bv][Lv];   // chain id; -1 for invalid positions

// ---------------- helpers ---------------------------------------------------
__device__ __forceinline__ float to_tf32(float x) {
    uint32_t u;
    asm("cvt.rna.tf32.f32 %0, %1;" : "=r"(u) : "f"(x));
    return __uint_as_float(u);
}

__device__ __forceinline__ void mma8(float c[4], const uint32_t a[4], const uint32_t b[2]) {
    asm volatile(
        "mma.sync.aligned.m16n8k8.row.col.f32.tf32.tf32.f32 "
        "{%0,%1,%2,%3},{%4,%5,%6,%7},{%8,%9},{%0,%1,%2,%3};"
        : "+f"(c[0]), "+f"(c[1]), "+f"(c[2]), "+f"(c[3])
        : "r"(a[0]), "r"(a[1]), "r"(a[2]), "r"(a[3]), "r"(b[0]), "r"(b[1]));
}

// ---------------- metadata: chain ids, positions, rope tables --------------
__global__ void meta_kernel(const void* __restrict__ maskraw)
{
    const int b   = blockIdx.x;
    const int tid = threadIdx.x;   // 256 threads

    __shared__ int slen[Lv];
    __shared__ int scs[Lv];
    __shared__ int spart[257];
    __shared__ int sis64;

    if (tid == 0) {
        const int* w = (const int*)maskraw;
        bool odd_zero = true, even_nz = false;
        for (int i = 0; i < 32; i++) {
            if (w[2*i+1] != 0) odd_zero = false;
            if (w[2*i]   != 0) even_nz  = true;
        }
        sis64 = (odd_zero && even_nz) ? 1 : 0;
    }
    __syncthreads();
    const int is64 = sis64;

    for (int i = tid; i < Lv; i += 256) {
        long long v;
        if (is64) v = ((const long long*)maskraw)[b*Lv + i];
        else      v = ((const int*)maskraw)[b*Lv + i];
        slen[i] = (int)v;
    }
    __syncthreads();

    int base = tid * 8;
    int s = 0, loc[8];
    #pragma unroll
    for (int k = 0; k < 8; k++) { s += slen[base + k]; loc[k] = s; }
    spart[tid] = s;
    __syncthreads();
    if (tid == 0) {
        int acc = 0;
        for (int i = 0; i < 256; i++) { int t = spart[i]; spart[i] = acc; acc += t; }
        spart[256] = acc;
    }
    __syncthreads();
    int off = spart[tid];
    #pragma unroll
    for (int k = 0; k < 8; k++) scs[base + k] = off + loc[k];
    __syncthreads();

    const int total = scs[Lv - 1];

    for (int p = tid; p < Lv; p += 256) {
        int lo = 0, hi = Lv;
        while (lo < hi) { int mid = (lo + hi) >> 1; if (scs[mid] > p) hi = mid; else lo = mid + 1; }
        const int cid = lo;
        const bool valid = (p < total);
        const int prev = (cid > 0 && cid <= Lv) ? scs[(cid - 1 < Lv) ? cid - 1 : Lv - 1] : 0;
        const float pos = valid ? (float)(p - prev) : 0.0f;

        g_cidq[b][p] = valid ? cid : Lv;
        g_cidk[b][p] = valid ? cid : -1;

        for (int d2 = 0; d2 < 32; d2++) {
            float inv = powf(10000.0f, -((float)(2 * d2)) / 64.0f);
            float a = pos * inv;
            float sn, cs;
            sincosf(a, &sn, &cs);
            g_cos[b][p][d2] = cs;
            g_sin[b][p][d2] = sn;
        }
    }
}

// ---------------- QKV GEMM (tf32 tensor core) -------------------------------
// C[m][n] = X[m][:].W[n][:] + bias[n].  Block 128x64, BK=32, 8 warps (4x2),
// warp tile 32x32 = 2(mi) x 4(ni) m16n8k8 mmas.
#define GBM 128
#define GBN 64
#define GBK 32
#define GSTR 36

__global__ void __launch_bounds__(256) qkv_gemm(
    const float* __restrict__ X,
    const float* __restrict__ W0, const float* __restrict__ b0,
    const float* __restrict__ W1, const float* __restrict__ b1)
{
    const int br = blockIdx.z;
    const float* __restrict__ W    = br ? W1 : W0;
    const float* __restrict__ bias = br ? b1 : b0;

    const int m0 = blockIdx.y * GBM;
    const int n0 = blockIdx.x * GBN;

    __shared__ float As[GBM][GSTR];
    __shared__ float Bs[GBN][GSTR];

    const int tid  = threadIdx.x;
    const int lane = tid & 31;
    const int wid  = tid >> 5;
    const int wm   = (wid >> 1) * 32;
    const int wn   = (wid & 1) * 32;
    const int lk   = tid & 31;
    const int lr   = tid >> 5;     // 0..7

    float acc[2][4][4];
    #pragma unroll
    for (int i = 0; i < 2; i++)
        #pragma unroll
        for (int j = 0; j < 4; j++)
            #pragma unroll
            for (int k = 0; k < 4; k++) acc[i][j][k] = 0.0f;

    for (int kt = 0; kt < Dv; kt += GBK) {
        #pragma unroll
        for (int r0 = 0; r0 < GBM; r0 += 8)
            As[r0 + lr][lk] = to_tf32(X[(size_t)(m0 + r0 + lr) * Dv + kt + lk]);
        #pragma unroll
        for (int r0 = 0; r0 < GBN; r0 += 8)
            Bs[r0 + lr][lk] = to_tf32(W[(size_t)(n0 + r0 + lr) * Dv + kt + lk]);
        __syncthreads();

        #pragma unroll
        for (int ks = 0; ks < 4; ks++) {
            const int kc = ks * 8 + (lane & 3);
            uint32_t af[2][4];
            #pragma unroll
            for (int mi = 0; mi < 2; mi++) {
                const int ar = wm + mi * 16 + (lane >> 2);
                af[mi][0] = __float_as_uint(As[ar][kc]);
                af[mi][1] = __float_as_uint(As[ar + 8][kc]);
                af[mi][2] = __float_as_uint(As[ar][kc + 4]);
                af[mi][3] = __float_as_uint(As[ar + 8][kc + 4]);
            }
            uint32_t bf[4][2];
            #pragma unroll
            for (int ni = 0; ni < 4; ni++) {
                const int brr = wn + ni * 8 + (lane >> 2);
                bf[ni][0] = __float_as_uint(Bs[brr][kc]);
                bf[ni][1] = __float_as_uint(Bs[brr][kc + 4]);
            }
            #pragma unroll
            for (int mi = 0; mi < 2; mi++)
                #pragma unroll
                for (int ni = 0; ni < 4; ni++)
                    mma8(acc[mi][ni], af[mi], bf[ni]);
        }
        __syncthreads();
    }

    #pragma unroll
    for (int mi = 0; mi < 2; mi++)
        #pragma unroll
        for (int ni = 0; ni < 4; ni++) {
            const int r = m0 + wm + mi * 16 + (lane >> 2);
            const int c = n0 + wn + ni * 8 + 2 * (lane & 3);
            const float bx = bias[c], by = bias[c + 1];
            float2 v;
            v.x = acc[mi][ni][0] + bx; v.y = acc[mi][ni][1] + by;
            *(float2*)&g_qkv[br][r][c] = v;
            v.x = acc[mi][ni][2] + bx; v.y = acc[mi][ni][3] + by;
            *(float2*)&g_qkv[br][r + 8][c] = v;
        }
}

// ---------------- prep: rope + scale + dense [br][b][h][l][64] layout ------
__global__ void __launch_bounds__(1024) prep_kernel()
{
    const int idx = blockIdx.x * 1024 + threadIdx.x;   // 2^22 threads
    const int d  = idx & 31;
    const int l  = (idx >> 5) & 2047;
    const int h  = (idx >> 16) & 15;
    const int b  = (idx >> 20) & 1;
    const int br = (idx >> 21) & 1;

    const float* src = &g_qkv[br][(size_t)b * Lv + l][0];
    const float c = g_cos[b][l][d], s = g_sin[b][l][d];

    const float q1 = src[h * 64 + d],            q2 = src[h * 64 + d + 32];
    const float k1 = src[Dv + h * 64 + d],       k2 = src[Dv + h * 64 + d + 32];
    const float v1 = src[2 * Dv + h * 64 + d],   v2 = src[2 * Dv + h * 64 + d + 32];

    const size_t o = ((((size_t)(br * 2 + b) * 16 + h) * 2048) + l) * 64 + d;
    g_q[o]      = to_tf32((q1 * c - q2 * s) * 0.125f);
    g_q[o + 32] = to_tf32((q2 * c + q1 * s) * 0.125f);
    g_k[o]      = to_tf32(k1 * c - k2 * s);
    g_k[o + 32] = to_tf32(k2 * c + k1 * s);
    g_v[o]      = to_tf32(v1);
    g_v[o + 32] = to_tf32(v2);
}

// ---------------- attention: flash-style 64x64 tiles, tf32 mma -------------
// grid (32 qtiles, 16 h, 4 z=b+2*br); 256 threads = 8 warps (4 M x 2 N).
// Warp tile: 16 q-rows x 32 cols.
#define KSTR 68
#define VSTR 72
#define SSTR 68

__global__ void __launch_bounds__(256) attn_kernel()
{
    const int qt = blockIdx.x;
    const int h  = blockIdx.y;
    const int z  = blockIdx.z;
    const int b  = z & 1;
    const int br = z >> 1;
    const bool intra = (br == 0);

    extern __shared__ __align__(16) float sm[];
    float* Ks    = sm;                      // [64][68]
    float* Vs    = Ks + 64 * KSTR;          // [64][72]
    float* Ssh   = Vs + 64 * VSTR;          // [64][68]
    float* alpha = Ssh + 64 * SSTR;         // [64]
    float* lsh   = alpha + 64;              // [64]
    int*   qcid  = (int*)(lsh + 64);        // [64]
    int*   kcid  = qcid + 64;               // [64]

    const int tid  = threadIdx.x;
    const int lane = tid & 31;
    const int wid  = tid >> 5;
    const int wm   = wid >> 1;      // 0..3
    const int wn   = wid & 1;       // 0..1

    const size_t hbase = (((size_t)(br * 2 + b) * 16 + h) * 2048) * 64;
    const float* __restrict__ qg = g_q + hbase + (size_t)qt * 64 * 64;
    const float* __restrict__ kg = g_k + hbase;
    const float* __restrict__ vg = g_v + hbase;

    // ---- stage Q tile via Ssh, pull A-fragments into registers
    #pragma unroll
    for (int it = 0; it < 4; it++) {
        const int v = it * 256 + tid;
        const int flat = v * 4;
        const int i = flat >> 6, d = flat & 63;
        *(float4*)&Ssh[i * SSTR + d] = *(const float4*)(qg + flat);
    }
    if (tid < 64) qcid[tid] = g_cidq[b][qt * 64 + tid];
    __syncthreads();

    const int r0 = wm * 16 + (lane >> 2);
    const int r1 = r0 + 8;
    uint32_t qf[8][4];
    {
        const float* p0 = &Ssh[r0 * SSTR];
        const float* p1 = &Ssh[r1 * SSTR];
        #pragma unroll
        for (int ks = 0; ks < 8; ks++) {
            const int c = ks * 8 + (lane & 3);
            qf[ks][0] = __float_as_uint(p0[c]);
            qf[ks][1] = __float_as_uint(p1[c]);
            qf[ks][2] = __float_as_uint(p0[c + 4]);
            qf[ks][3] = __float_as_uint(p1[c + 4]);
        }
    }
    const int qc0 = qcid[r0], qc1 = qcid[r1];
    __syncthreads();

    float o[4][4];
    #pragma unroll
    for (int i = 0; i < 4; i++)
        #pragma unroll
        for (int j = 0; j < 4; j++) o[i][j] = 0.0f;

    float mrow = -INFINITY, lrow = 0.0f;
    const int sr = tid >> 2;   // softmax row (0..63)
    const int q4 = tid & 3;

    for (int kt = 0; kt < Lv / 64; kt++) {
        // ---- load K,V tiles (contiguous float4)
        #pragma unroll
        for (int it = 0; it < 4; it++) {
            const int v = it * 256 + tid;
            const int flat = v * 4;
            const int i = flat >> 6, d = flat & 63;
            *(float4*)&Ks[i * KSTR + d] = *(const float4*)(kg + (size_t)kt * 4096 + flat);
            *(float4*)&Vs[i * VSTR + d] = *(const float4*)(vg + (size_t)kt * 4096 + flat);
        }
        if (tid < 64) kcid[tid] = g_cidk[b][kt * 64 + tid];
        __syncthreads();

        // ---- S = Q K^T
        float sv[4][4];
        #pragma unroll
        for (int i = 0; i < 4; i++)
            #pragma unroll
            for (int j = 0; j < 4; j++) sv[i][j] = 0.0f;

        #pragma unroll
        for (int ks = 0; ks < 8; ks++) {
            const int c = ks * 8 + (lane & 3);
            uint32_t bf[4][2];
            #pragma unroll
            for (int ni = 0; ni < 4; ni++) {
                const int brr = wn * 32 + ni * 8 + (lane >> 2);
                bf[ni][0] = __float_as_uint(Ks[brr * KSTR + c]);
                bf[ni][1] = __float_as_uint(Ks[brr * KSTR + c + 4]);
            }
            #pragma unroll
            for (int ni = 0; ni < 4; ni++)
                mma8(sv[ni], qf[ks], bf[ni]);
        }

        // ---- mask & store S
        #pragma unroll
        for (int ni = 0; ni < 4; ni++) {
            const int cc = wn * 32 + ni * 8 + 2 * (lane & 3);
            const int kc0 = kcid[cc], kc1 = kcid[cc + 1];
            const bool m00 = (kc0 >= 0) && ((kc0 == qc0) == intra);
            const bool m01 = (kc1 >= 0) && ((kc1 == qc0) == intra);
            const bool m10 = (kc0 >= 0) && ((kc0 == qc1) == intra);
            const bool m11 = (kc1 >= 0) && ((kc1 == qc1) == intra);
            float2 u;
            u.x = m00 ? sv[ni][0] : -INFINITY;
            u.y = m01 ? sv[ni][1] : -INFINITY;
            *(float2*)&Ssh[r0 * SSTR + cc] = u;
            u.x = m10 ? sv[ni][2] : -INFINITY;
            u.y = m11 ? sv[ni][3] : -INFINITY;
            *(float2*)&Ssh[r1 * SSTR + cc] = u;
        }
        __syncthreads();

        // ---- online softmax: 4 threads/row, 16 entries each
        {
            float tmax = -INFINITY;
            #pragma unroll
            for (int jj = 0; jj < 16; jj++)
                tmax = fmaxf(tmax, Ssh[sr * SSTR + q4 * 16 + jj]);
            tmax = fmaxf(tmax, __shfl_xor_sync(0xffffffffu, tmax, 1));
            tmax = fmaxf(tmax, __shfl_xor_sync(0xffffffffu, tmax, 2));

            const float mnew = fmaxf(mrow, tmax);
            float af_, tsum = 0.0f;
            if (mnew == -INFINITY) {
                af_ = 1.0f;
                #pragma unroll
                for (int jj = 0; jj < 16; jj++)
                    Ssh[sr * SSTR + q4 * 16 + jj] = 0.0f;
            } else {
                af_ = __expf(mrow - mnew);
                #pragma unroll
                for (int jj = 0; jj < 16; jj++) {
                    float p = to_tf32(__expf(Ssh[sr * SSTR + q4 * 16 + jj] - mnew));
                    tsum += p;
                    Ssh[sr * SSTR + q4 * 16 + jj] = p;
                }
            }
            tsum += __shfl_xor_sync(0xffffffffu, tsum, 1);
            tsum += __shfl_xor_sync(0xffffffffu, tsum, 2);
            lrow = lrow * af_ + tsum;
            mrow = mnew;
            if (q4 == 0) alpha[sr] = af_;
        }
        __syncthreads();

        // ---- O = O*alpha + P V
        {
            const float al0 = alpha[r0], al1 = alpha[r1];
            #pragma unroll
            for (int ni = 0; ni < 4; ni++) {
                o[ni][0] *= al0; o[ni][1] *= al0;
                o[ni][2] *= al1; o[ni][3] *= al1;
            }
            #pragma unroll
            for (int ks = 0; ks < 8; ks++) {
                const int c = ks * 8 + (lane & 3);
                uint32_t af[4];
                af[0] = __float_as_uint(Ssh[r0 * SSTR + c]);
                af[1] = __float_as_uint(Ssh[r1 * SSTR + c]);
                af[2] = __float_as_uint(Ssh[r0 * SSTR + c + 4]);
                af[3] = __float_as_uint(Ssh[r1 * SSTR + c + 4]);
                const int jrow = ks * 8 + (lane & 3);
                #pragma unroll
                for (int ni = 0; ni < 4; ni++) {
                    const int dn = wn * 32 + ni * 8 + (lane >> 2);
                    uint32_t bf2[2];
                    bf2[0] = __float_as_uint(Vs[jrow * VSTR + dn]);
                    bf2[1] = __float_as_uint(Vs[(jrow + 4) * VSTR + dn]);
                    mma8(o[ni], af, bf2);
                }
            }
        }
        __syncthreads();
    }

    if (q4 == 0) lsh[sr] = lrow;
    __syncthreads();

    const float lv0 = lsh[r0], lv1 = lsh[r1];
    const float inv0 = (lv0 > 0.0f) ? (1.0f / lv0) : 0.0f;
    const float inv1 = (lv1 > 0.0f) ? (1.0f / lv1) : 0.0f;
    #pragma unroll
    for (int ni = 0; ni < 4; ni++) {
        const int cc = h * 64 + wn * 32 + ni * 8 + 2 * (lane & 3);
        float2 u;
        u.x = o[ni][0] * inv0; u.y = o[ni][1] * inv0;
        *(float2*)&g_attn[br][(size_t)b * Lv + qt * 64 + r0][cc] = u;
        u.x = o[ni][2] * inv1; u.y = o[ni][3] * inv1;
        *(float2*)&g_attn[br][(size_t)b * Lv + qt * 64 + r1][cc] = u;
    }
}

// ---------------- output GEMM (tf32): Y = (A0+A1) Wout^T + bout ------------
__global__ void __launch_bounds__(256) out_gemm(
    const float* __restrict__ W, const float* __restrict__ bias,
    float* __restrict__ Y)
{
    const int m0 = blockIdx.y * GBM;
    const int n0 = blockIdx.x * GBN;

    __shared__ float As[GBM][GSTR];
    __shared__ float Bs[GBN][GSTR];

    const int tid  = threadIdx.x;
    const int lane = tid & 31;
    const int wid  = tid >> 5;
    const int wm   = (wid >> 1) * 32;
    const int wn   = (wid & 1) * 32;
    const int lk   = tid & 31;
    const int lr   = tid >> 5;

    float acc[2][4][4];
    #pragma unroll
    for (int i = 0; i < 2; i++)
        #pragma unroll
        for (int j = 0; j < 4; j++)
            #pragma unroll
            for (int k = 0; k < 4; k++) acc[i][j][k] = 0.0f;

    for (int kt = 0; kt < Dv; kt += GBK) {
        #pragma unroll
        for (int r0 = 0; r0 < GBM; r0 += 8) {
            const int m = m0 + r0 + lr;
            As[r0 + lr][lk] = to_tf32(g_attn[0][m][kt + lk] + g_attn[1][m][kt + lk]);
        }
        #pragma unroll
        for (int r0 = 0; r0 < GBN; r0 += 8)
            Bs[r0 + lr][lk] = to_tf32(W[(size_t)(n0 + r0 + lr) * Dv + kt + lk]);
        __syncthreads();

        #pragma unroll
        for (int ks = 0; ks < 4; ks++) {
            const int kc = ks * 8 + (lane & 3);
            uint32_t af[2][4];
            #pragma unroll
            for (int mi = 0; mi < 2; mi++) {
                const int ar = wm + mi * 16 + (lane >> 2);
                af[mi][0] = __float_as_uint(As[ar][kc]);
                af[mi][1] = __float_as_uint(As[ar + 8][kc]);
                af[mi][2] = __float_as_uint(As[ar][kc + 4]);
                af[mi][3] = __float_as_uint(As[ar + 8][kc + 4]);
            }
            uint32_t bf[4][2];
            #pragma unroll
            for (int ni = 0; ni < 4; ni++) {
                const int brr = wn + ni * 8 + (lane >> 2);
                bf[ni][0] = __float_as_uint(Bs[brr][kc]);
                bf[ni][1] = __float_as_uint(Bs[brr][kc + 4]);
            }
            #pragma unroll
            for (int mi = 0; mi < 2; mi++)
                #pragma unroll
                for (int ni = 0; ni < 4; ni++)
                    mma8(acc[mi][ni], af[mi], bf[ni]);
        }
        __syncthreads();
    }

    #pragma unroll
    for (int mi = 0; mi < 2; mi++)
        #pragma unroll
        for (int ni = 0; ni < 4; ni++) {
            const int r = m0 + wm + mi * 16 + (lane >> 2);
            const int c = n0 + wn + ni * 8 + 2 * (lane & 3);
            const float bx = bias[c], by = bias[c + 1];
            float2 v;
            v.x = acc[mi][ni][0] + bx; v.y = acc[mi][ni][1] + by;
            *(float2*)&Y[(size_t)r * Dv + c] = v;
            v.x = acc[mi][ni][2] + bx; v.y = acc[mi][ni][3] + by;
            *(float2*)&Y[(size_t)(r + 8) * Dv + c] = v;
        }
}

// ---------------- launcher --------------------------------------------------
extern "C" void kernel_launch(void* const* d_in, const int* in_sizes, int n_in,
                              void* d_out, int out_size)
{
    const float* hidden = (const float*)d_in[0];
    const void*  mask   = d_in[1];
    const float* Wi = (const float*)d_in[2];
    const float* bi = (const float*)d_in[3];
    const float* We = (const float*)d_in[4];
    const float* be = (const float*)d_in[5];
    const float* Wo = (const float*)d_in[6];
    const float* bo = (const float*)d_in[7];
    float* out = (float*)d_out;

    meta_kernel<<<Bv, 256>>>(mask);

    dim3 g1(N3D / GBN, ML / GBM, 2);
    qkv_gemm<<<g1, 256>>>(hidden, Wi, bi, We, be);

    prep_kernel<<<4096, 1024>>>();

    const size_t smem = (size_t)(64 * KSTR + 64 * VSTR + 64 * SSTR + 128) * sizeof(float)
                      + 128 * sizeof(int);
    cudaFuncSetAttribute(attn_kernel, cudaFuncAttributeMaxDynamicSharedMemorySize, (int)smem);
    dim3 g2(Lv / 64, Hv, 2 * Bv);
    attn_kernel<<<g2, 256, smem>>>();

    dim3 g3(Dv / GBN, ML / GBM);
    out_gemm<<<g3, 256>>>(Wo, bo, out);
}

// round 9
// speedup vs baseline: 2.9708x; 1.2340x over previous
#include <cuda_runtime.h>
#include <math.h>
#include <stdint.h>

#define Bv 2
#define Lv 2048
#define Dv 1024
#define Hv 16
#define HDv 64
#define ML (Bv*Lv)     // 4096
#define N3D (3*Dv)     // 3072

// ---------------- scratch (device globals; no allocation allowed) ----------
__device__ float g_qkv[2][ML][N3D];                 // un-roped qkv, both branches
__device__ float g_attn[2][ML][Dv];                 // attention outputs
__device__ __align__(16) float g_q[2*2*16*2048*64]; // roped+scaled tf32 [br][b][h][l][d]
__device__ __align__(16) float g_k[2*2*16*2048*64];
__device__ __align__(16) float g_v[2*2*16*2048*64];
__device__ float g_cos[Bv][Lv][32];
__device__ float g_sin[Bv][Lv][32];
__device__ int   g_cidq[Bv][Lv];   // chain id; Lv for invalid positions
__device__ int   g_cidk[Bv][Lv];   // chain id; -1 for invalid positions

// ---------------- helpers ---------------------------------------------------
__device__ __forceinline__ float to_tf32(float x) {
    uint32_t u;
    asm("cvt.rna.tf32.f32 %0, %1;" : "=r"(u) : "f"(x));
    return __uint_as_float(u);
}

__device__ __forceinline__ void mma8(float c[4], const uint32_t a[4], const uint32_t b[2]) {
    asm volatile(
        "mma.sync.aligned.m16n8k8.row.col.f32.tf32.tf32.f32 "
        "{%0,%1,%2,%3},{%4,%5,%6,%7},{%8,%9},{%0,%1,%2,%3};"
        : "+f"(c[0]), "+f"(c[1]), "+f"(c[2]), "+f"(c[3])
        : "r"(a[0]), "r"(a[1]), "r"(a[2]), "r"(a[3]), "r"(b[0]), "r"(b[1]));
}

// ---------------- metadata: chain ids, positions, rope tables --------------
__global__ void meta_kernel(const void* __restrict__ maskraw)
{
    const int b   = blockIdx.x;
    const int tid = threadIdx.x;   // 256 threads

    __shared__ int slen[Lv];
    __shared__ int scs[Lv];
    __shared__ int spart[257];
    __shared__ int sis64;

    if (tid == 0) {
        const int* w = (const int*)maskraw;
        bool odd_zero = true, even_nz = false;
        for (int i = 0; i < 32; i++) {
            if (w[2*i+1] != 0) odd_zero = false;
            if (w[2*i]   != 0) even_nz  = true;
        }
        sis64 = (odd_zero && even_nz) ? 1 : 0;
    }
    __syncthreads();
    const int is64 = sis64;

    for (int i = tid; i < Lv; i += 256) {
        long long v;
        if (is64) v = ((const long long*)maskraw)[b*Lv + i];
        else      v = ((const int*)maskraw)[b*Lv + i];
        slen[i] = (int)v;
    }
    __syncthreads();

    int base = tid * 8;
    int s = 0, loc[8];
    #pragma unroll
    for (int k = 0; k < 8; k++) { s += slen[base + k]; loc[k] = s; }
    spart[tid] = s;
    __syncthreads();
    if (tid == 0) {
        int acc = 0;
        for (int i = 0; i < 256; i++) { int t = spart[i]; spart[i] = acc; acc += t; }
        spart[256] = acc;
    }
    __syncthreads();
    int off = spart[tid];
    #pragma unroll
    for (int k = 0; k < 8; k++) scs[base + k] = off + loc[k];
    __syncthreads();

    const int total = scs[Lv - 1];

    for (int p = tid; p < Lv; p += 256) {
        int lo = 0, hi = Lv;
        while (lo < hi) { int mid = (lo + hi) >> 1; if (scs[mid] > p) hi = mid; else lo = mid + 1; }
        const int cid = lo;
        const bool valid = (p < total);
        const int prev = (cid > 0 && cid <= Lv) ? scs[(cid - 1 < Lv) ? cid - 1 : Lv - 1] : 0;
        const float pos = valid ? (float)(p - prev) : 0.0f;

        g_cidq[b][p] = valid ? cid : Lv;
        g_cidk[b][p] = valid ? cid : -1;

        for (int d2 = 0; d2 < 32; d2++) {
            float inv = powf(10000.0f, -((float)(2 * d2)) / 64.0f);
            float a = pos * inv;
            float sn, cs;
            sincosf(a, &sn, &cs);
            g_cos[b][p][d2] = cs;
            g_sin[b][p][d2] = sn;
        }
    }
}

// ---------------- QKV GEMM (tf32): block 128x128, BK=32, 8 warps (2x4) -----
#define GBM 128
#define GBN 128
#define GBK 32
#define GSTR 36

__global__ void __launch_bounds__(256) qkv_gemm(
    const float* __restrict__ X,
    const float* __restrict__ W0, const float* __restrict__ b0,
    const float* __restrict__ W1, const float* __restrict__ b1)
{
    const int br = blockIdx.z;
    const float* __restrict__ W    = br ? W1 : W0;
    const float* __restrict__ bias = br ? b1 : b0;

    const int m0 = blockIdx.y * GBM;
    const int n0 = blockIdx.x * GBN;

    __shared__ __align__(16) float As[GBM][GSTR];
    __shared__ __align__(16) float Bs[GBN][GSTR];

    const int tid  = threadIdx.x;
    const int lane = tid & 31;
    const int wid  = tid >> 5;
    const int wm   = (wid >> 2) * 64;   // 0 or 64
    const int wn   = (wid & 3) * 32;    // 0,32,64,96
    const int lk   = tid & 31;
    const int lr   = tid >> 5;

    float acc[4][4][4];
    #pragma unroll
    for (int i = 0; i < 4; i++)
        #pragma unroll
        for (int j = 0; j < 4; j++)
            #pragma unroll
            for (int k = 0; k < 4; k++) acc[i][j][k] = 0.0f;

    for (int kt = 0; kt < Dv; kt += GBK) {
        #pragma unroll
        for (int r0 = 0; r0 < GBM; r0 += 8)
            As[r0 + lr][lk] = to_tf32(X[(size_t)(m0 + r0 + lr) * Dv + kt + lk]);
        #pragma unroll
        for (int r0 = 0; r0 < GBN; r0 += 8)
            Bs[r0 + lr][lk] = to_tf32(W[(size_t)(n0 + r0 + lr) * Dv + kt + lk]);
        __syncthreads();

        #pragma unroll
        for (int ks = 0; ks < 4; ks++) {
            const int kc = ks * 8 + (lane & 3);
            uint32_t af[4][4];
            #pragma unroll
            for (int mi = 0; mi < 4; mi++) {
                const int ar = wm + mi * 16 + (lane >> 2);
                af[mi][0] = __float_as_uint(As[ar][kc]);
                af[mi][1] = __float_as_uint(As[ar + 8][kc]);
                af[mi][2] = __float_as_uint(As[ar][kc + 4]);
                af[mi][3] = __float_as_uint(As[ar + 8][kc + 4]);
            }
            uint32_t bf[4][2];
            #pragma unroll
            for (int ni = 0; ni < 4; ni++) {
                const int brr = wn + ni * 8 + (lane >> 2);
                bf[ni][0] = __float_as_uint(Bs[brr][kc]);
                bf[ni][1] = __float_as_uint(Bs[brr][kc + 4]);
            }
            #pragma unroll
            for (int mi = 0; mi < 4; mi++)
                #pragma unroll
                for (int ni = 0; ni < 4; ni++)
                    mma8(acc[mi][ni], af[mi], bf[ni]);
        }
        __syncthreads();
    }

    #pragma unroll
    for (int mi = 0; mi < 4; mi++)
        #pragma unroll
        for (int ni = 0; ni < 4; ni++) {
            const int r = m0 + wm + mi * 16 + (lane >> 2);
            const int c = n0 + wn + ni * 8 + 2 * (lane & 3);
            const float bx = bias[c], by = bias[c + 1];
            float2 v;
            v.x = acc[mi][ni][0] + bx; v.y = acc[mi][ni][1] + by;
            *(float2*)&g_qkv[br][r][c] = v;
            v.x = acc[mi][ni][2] + bx; v.y = acc[mi][ni][3] + by;
            *(float2*)&g_qkv[br][r + 8][c] = v;
        }
}

// ---------------- prep: rope + scale + dense [br][b][h][l][64] layout ------
__global__ void __launch_bounds__(1024) prep_kernel()
{
    const int idx = blockIdx.x * 1024 + threadIdx.x;   // 2^22 threads
    const int d  = idx & 31;
    const int l  = (idx >> 5) & 2047;
    const int h  = (idx >> 16) & 15;
    const int b  = (idx >> 20) & 1;
    const int br = (idx >> 21) & 1;

    const float* src = &g_qkv[br][(size_t)b * Lv + l][0];
    const float c = g_cos[b][l][d], s = g_sin[b][l][d];

    const float q1 = src[h * 64 + d],            q2 = src[h * 64 + d + 32];
    const float k1 = src[Dv + h * 64 + d],       k2 = src[Dv + h * 64 + d + 32];
    const float v1 = src[2 * Dv + h * 64 + d],   v2 = src[2 * Dv + h * 64 + d + 32];

    const size_t o = ((((size_t)(br * 2 + b) * 16 + h) * 2048) + l) * 64 + d;
    g_q[o]      = to_tf32((q1 * c - q2 * s) * 0.125f);
    g_q[o + 32] = to_tf32((q2 * c + q1 * s) * 0.125f);
    g_k[o]      = to_tf32(k1 * c - k2 * s);
    g_k[o + 32] = to_tf32(k2 * c + k1 * s);
    g_v[o]      = to_tf32(v1);
    g_v[o + 32] = to_tf32(v2);
}

// ---------------- attention: TQ=128, 8 M-warps, register softmax -----------
// Warp = 16 q-rows x all 64 kv cols. P stays in registers; the PV mma reads V
// B-fragments from permuted rows (8ks+2k, 8ks+2k+1) so the S C-fragment feeds
// the A operand directly (zero shuffles). VSTR=68 is bank-conflict-free.
#define KSTR 68

__global__ void __launch_bounds__(256) attn_kernel()
{
    const int qt = blockIdx.x;       // 0..15 (128 q rows each)
    const int h  = blockIdx.y;
    const int z  = blockIdx.z;
    const int b  = z & 1;
    const int br = z >> 1;
    const bool intra = (br == 0);

    __shared__ __align__(16) float smbuf[2][64][KSTR];
    __shared__ int kcs[64];
    float* smQ = &smbuf[0][0][0];          // 128 rows x stride 68 (spans both)

    const int tid  = threadIdx.x;
    const int lane = tid & 31;
    const int wid  = tid >> 5;             // 0..7 : q-row group
    const int rr   = lane >> 2;            // 0..7
    const int qj   = lane & 3;             // 0..3

    const size_t hbase = (((size_t)(br * 2 + b) * 16 + h) * 2048) * 64;
    const float* __restrict__ qg = g_q + hbase + (size_t)qt * 128 * 64;
    const float* __restrict__ kg = g_k + hbase;
    const float* __restrict__ vg = g_v + hbase;

    // ---- stage Q tile (128x64) and extract A fragments into registers
    #pragma unroll
    for (int it = 0; it < 8; it++) {
        const int v = it * 256 + tid;
        const int flat = v * 4;
        const int i = flat >> 6, d = flat & 63;
        *(float4*)&smQ[i * KSTR + d] = *(const float4*)(qg + flat);
    }
    __syncthreads();

    const int rowa = wid * 16 + rr;        // row within 128-tile
    uint32_t qf[8][4];
    #pragma unroll
    for (int ks = 0; ks < 8; ks++) {
        const int c = ks * 8 + qj;
        qf[ks][0] = __float_as_uint(smQ[rowa * KSTR + c]);
        qf[ks][1] = __float_as_uint(smQ[(rowa + 8) * KSTR + c]);
        qf[ks][2] = __float_as_uint(smQ[rowa * KSTR + c + 4]);
        qf[ks][3] = __float_as_uint(smQ[(rowa + 8) * KSTR + c + 4]);
    }
    const int qrow0 = qt * 128 + rowa;
    const int qrow1 = qrow0 + 8;
    const int qc0 = g_cidq[b][qrow0];
    const int qc1 = g_cidq[b][qrow1];
    __syncthreads();

    float o[8][4];
    #pragma unroll
    for (int i = 0; i < 8; i++)
        #pragma unroll
        for (int j = 0; j < 4; j++) o[i][j] = 0.0f;

    float m0 = -INFINITY, m1 = -INFINITY, l0 = 0.0f, l1 = 0.0f;

    for (int kt = 0; kt < Lv / 64; kt++) {
        // ---- load K,V tiles (contiguous float4)
        #pragma unroll
        for (int it = 0; it < 4; it++) {
            const int v = it * 256 + tid;
            const int flat = v * 4;
            const int i = flat >> 6, d = flat & 63;
            *(float4*)&smbuf[0][i][d] = *(const float4*)(kg + (size_t)kt * 4096 + flat);
            *(float4*)&smbuf[1][i][d] = *(const float4*)(vg + (size_t)kt * 4096 + flat);
        }
        if (tid < 64) kcs[tid] = g_cidk[b][kt * 64 + tid];
        __syncthreads();

        // ---- S = Q K^T  (16 x 64 per warp)
        float sv[8][4];
        #pragma unroll
        for (int i = 0; i < 8; i++)
            #pragma unroll
            for (int j = 0; j < 4; j++) sv[i][j] = 0.0f;

        #pragma unroll
        for (int ks = 0; ks < 8; ks++) {
            const int c = ks * 8 + qj;
            #pragma unroll
            for (int ni = 0; ni < 8; ni++) {
                const int brr = ni * 8 + rr;
                uint32_t bf[2];
                bf[0] = __float_as_uint(smbuf[0][brr][c]);
                bf[1] = __float_as_uint(smbuf[0][brr][c + 4]);
                mma8(sv[ni], qf[ks], bf);
            }
        }

        // ---- mask
        #pragma unroll
        for (int ni = 0; ni < 8; ni++) {
            const int cc = ni * 8 + 2 * qj;
            const int kc0 = kcs[cc], kc1 = kcs[cc + 1];
            const bool a00 = (kc0 >= 0) && ((kc0 == qc0) == intra);
            const bool a01 = (kc1 >= 0) && ((kc1 == qc0) == intra);
            const bool a10 = (kc0 >= 0) && ((kc0 == qc1) == intra);
            const bool a11 = (kc1 >= 0) && ((kc1 == qc1) == intra);
            sv[ni][0] = a00 ? sv[ni][0] : -INFINITY;
            sv[ni][1] = a01 ? sv[ni][1] : -INFINITY;
            sv[ni][2] = a10 ? sv[ni][2] : -INFINITY;
            sv[ni][3] = a11 ? sv[ni][3] : -INFINITY;
        }

        // ---- register online softmax (rows fully within warp)
        float tmax0 = -INFINITY, tmax1 = -INFINITY;
        #pragma unroll
        for (int ni = 0; ni < 8; ni++) {
            tmax0 = fmaxf(tmax0, fmaxf(sv[ni][0], sv[ni][1]));
            tmax1 = fmaxf(tmax1, fmaxf(sv[ni][2], sv[ni][3]));
        }
        tmax0 = fmaxf(tmax0, __shfl_xor_sync(0xffffffffu, tmax0, 1));
        tmax0 = fmaxf(tmax0, __shfl_xor_sync(0xffffffffu, tmax0, 2));
        tmax1 = fmaxf(tmax1, __shfl_xor_sync(0xffffffffu, tmax1, 1));
        tmax1 = fmaxf(tmax1, __shfl_xor_sync(0xffffffffu, tmax1, 2));

        const float mn0 = fmaxf(m0, tmax0);
        const float mn1 = fmaxf(m1, tmax1);
        float af0, af1, ts0 = 0.0f, ts1 = 0.0f;

        if (mn0 == -INFINITY) {
            af0 = 1.0f;
            #pragma unroll
            for (int ni = 0; ni < 8; ni++) { sv[ni][0] = 0.0f; sv[ni][1] = 0.0f; }
        } else {
            af0 = __expf(m0 - mn0);
            #pragma unroll
            for (int ni = 0; ni < 8; ni++) {
                float p0 = to_tf32(__expf(sv[ni][0] - mn0));
                float p1 = to_tf32(__expf(sv[ni][1] - mn0));
                ts0 += p0 + p1;
                sv[ni][0] = p0; sv[ni][1] = p1;
            }
        }
        if (mn1 == -INFINITY) {
            af1 = 1.0f;
            #pragma unroll
            for (int ni = 0; ni < 8; ni++) { sv[ni][2] = 0.0f; sv[ni][3] = 0.0f; }
        } else {
            af1 = __expf(m1 - mn1);
            #pragma unroll
            for (int ni = 0; ni < 8; ni++) {
                float p2 = to_tf32(__expf(sv[ni][2] - mn1));
                float p3 = to_tf32(__expf(sv[ni][3] - mn1));
                ts1 += p2 + p3;
                sv[ni][2] = p2; sv[ni][3] = p3;
            }
        }
        ts0 += __shfl_xor_sync(0xffffffffu, ts0, 1);
        ts0 += __shfl_xor_sync(0xffffffffu, ts0, 2);
        ts1 += __shfl_xor_sync(0xffffffffu, ts1, 1);
        ts1 += __shfl_xor_sync(0xffffffffu, ts1, 2);
        l0 = l0 * af0 + ts0;  m0 = mn0;
        l1 = l1 * af1 + ts1;  m1 = mn1;

        // ---- rescale O, then O += P V  (P fed straight from sv registers)
        #pragma unroll
        for (int ni = 0; ni < 8; ni++) {
            o[ni][0] *= af0; o[ni][1] *= af0;
            o[ni][2] *= af1; o[ni][3] *= af1;
        }
        #pragma unroll
        for (int ks = 0; ks < 8; ks++) {
            uint32_t pa[4];
            pa[0] = __float_as_uint(sv[ks][0]);   // (r,   2k)
            pa[1] = __float_as_uint(sv[ks][2]);   // (r+8, 2k)
            pa[2] = __float_as_uint(sv[ks][1]);   // (r,   2k+1)
            pa[3] = __float_as_uint(sv[ks][3]);   // (r+8, 2k+1)
            const int vr0 = ks * 8 + 2 * qj;      // permuted V rows
            #pragma unroll
            for (int ni = 0; ni < 8; ni++) {
                const int dn = ni * 8 + rr;
                uint32_t bf[2];
                bf[0] = __float_as_uint(smbuf[1][vr0][dn]);
                bf[1] = __float_as_uint(smbuf[1][vr0 + 1][dn]);
                mma8(o[ni], pa, bf);
            }
        }
        __syncthreads();
    }

    // ---- epilogue: normalize and store
    const float inv0 = (l0 > 0.0f) ? (1.0f / l0) : 0.0f;
    const float inv1 = (l1 > 0.0f) ? (1.0f / l1) : 0.0f;
    float* __restrict__ out0 = &g_attn[br][(size_t)b * Lv + qrow0][h * 64];
    float* __restrict__ out1 = &g_attn[br][(size_t)b * Lv + qrow1][h * 64];
    #pragma unroll
    for (int ni = 0; ni < 8; ni++) {
        const int cc = ni * 8 + 2 * qj;
        float2 u;
        u.x = o[ni][0] * inv0; u.y = o[ni][1] * inv0;
        *(float2*)&out0[cc] = u;
        u.x = o[ni][2] * inv1; u.y = o[ni][3] * inv1;
        *(float2*)&out1[cc] = u;
    }
}

// ---------------- output GEMM (tf32): Y = (A0+A1) Wout^T + bout ------------
__global__ void __launch_bounds__(256) out_gemm(
    const float* __restrict__ W, const float* __restrict__ bias,
    float* __restrict__ Y)
{
    const int m0 = blockIdx.y * GBM;
    const int n0 = blockIdx.x * GBN;

    __shared__ __align__(16) float As[GBM][GSTR];
    __shared__ __align__(16) float Bs[GBN][GSTR];

    const int tid  = threadIdx.x;
    const int lane = tid & 31;
    const int wid  = tid >> 5;
    const int wm   = (wid >> 2) * 64;
    const int wn   = (wid & 3) * 32;
    const int lk   = tid & 31;
    const int lr   = tid >> 5;

    float acc[4][4][4];
    #pragma unroll
    for (int i = 0; i < 4; i++)
        #pragma unroll
        for (int j = 0; j < 4; j++)
            #pragma unroll
            for (int k = 0; k < 4; k++) acc[i][j][k] = 0.0f;

    for (int kt = 0; kt < Dv; kt += GBK) {
        #pragma unroll
        for (int r0 = 0; r0 < GBM; r0 += 8) {
            const int m = m0 + r0 + lr;
            As[r0 + lr][lk] = to_tf32(g_attn[0][m][kt + lk] + g_attn[1][m][kt + lk]);
        }
        #pragma unroll
        for (int r0 = 0; r0 < GBN; r0 += 8)
            Bs[r0 + lr][lk] = to_tf32(W[(size_t)(n0 + r0 + lr) * Dv + kt + lk]);
        __syncthreads();

        #pragma unroll
        for (int ks = 0; ks < 4; ks++) {
            const int kc = ks * 8 + (lane & 3);
            uint32_t af[4][4];
            #pragma unroll
            for (int mi = 0; mi < 4; mi++) {
                const int ar = wm + mi * 16 + (lane >> 2);
                af[mi][0] = __float_as_uint(As[ar][kc]);
                af[mi][1] = __float_as_uint(As[ar + 8][kc]);
                af[mi][2] = __float_as_uint(As[ar][kc + 4]);
                af[mi][3] = __float_as_uint(As[ar + 8][kc + 4]);
            }
            uint32_t bf[4][2];
            #pragma unroll
            for (int ni = 0; ni < 4; ni++) {
                const int brr = wn + ni * 8 + (lane >> 2);
                bf[ni][0] = __float_as_uint(Bs[brr][kc]);
                bf[ni][1] = __float_as_uint(Bs[brr][kc + 4]);
            }
            #pragma unroll
            for (int mi = 0; mi < 4; mi++)
                #pragma unroll
                for (int ni = 0; ni < 4; ni++)
                    mma8(acc[mi][ni], af[mi], bf[ni]);
        }
        __syncthreads();
    }

    #pragma unroll
    for (int mi = 0; mi < 4; mi++)
        #pragma unroll
        for (int ni = 0; ni < 4; ni++) {
            const int r = m0 + wm + mi * 16 + (lane >> 2);
            const int c = n0 + wn + ni * 8 + 2 * (lane & 3);
            const float bx = bias[c], by = bias[c + 1];
            float2 v;
            v.x = acc[mi][ni][0] + bx; v.y = acc[mi][ni][1] + by;
            *(float2*)&Y[(size_t)r * Dv + c] = v;
            v.x = acc[mi][ni][2] + bx; v.y = acc[mi][ni][3] + by;
            *(float2*)&Y[(size_t)(r + 8) * Dv + c] = v;
        }
}

// ---------------- launcher --------------------------------------------------
extern "C" void kernel_launch(void* const* d_in, const int* in_sizes, int n_in,
                              void* d_out, int out_size)
{
    const float* hidden = (const float*)d_in[0];
    const void*  mask   = d_in[1];
    const float* Wi = (const float*)d_in[2];
    const float* bi = (const float*)d_in[3];
    const float* We = (const float*)d_in[4];
    const float* be = (const float*)d_in[5];
    const float* Wo = (const float*)d_in[6];
    const float* bo = (const float*)d_in[7];
    float* out = (float*)d_out;

    meta_kernel<<<Bv, 256>>>(mask);

    dim3 g1(N3D / GBN, ML / GBM, 2);
    qkv_gemm<<<g1, 256>>>(hidden, Wi, bi, We, be);

    prep_kernel<<<4096, 1024>>>();

    dim3 g2(Lv / 128, Hv, 2 * Bv);
    attn_kernel<<<g2, 256>>>();

    dim3 g3(Dv / GBN, ML / GBM);
    out_gemm<<<g3, 256>>>(Wo, bo, out);
}

// round 10
// speedup vs baseline: 3.0760x; 1.0354x over previous
#include <cuda_runtime.h>
#include <math.h>
#include <stdint.h>

#define Bv 2
#define Lv 2048
#define Dv 1024
#define Hv 16
#define HDv 64
#define ML (Bv*Lv)     // 4096
#define N3D (3*Dv)     // 3072

// ---------------- scratch (device globals; no allocation allowed) ----------
__device__ float g_qkv[2][ML][N3D];                 // un-roped qkv, both branches
__device__ float g_attn[2][ML][Dv];                 // attention outputs
__device__ __align__(16) float g_q[2*2*16*2048*64]; // roped+scaled tf32 [br][b][h][l][d]
__device__ __align__(16) float g_k[2*2*16*2048*64];
__device__ __align__(16) float g_v[2*2*16*2048*64];
__device__ float g_cos[Bv][Lv][32];
__device__ float g_sin[Bv][Lv][32];
__device__ int   g_cidq[Bv][Lv];   // chain id; Lv for invalid positions
__device__ __align__(16) int g_cidk[Bv][Lv];   // chain id; -1 for invalid positions

// ---------------- helpers ---------------------------------------------------
__device__ __forceinline__ float to_tf32(float x) {
    uint32_t u;
    asm("cvt.rna.tf32.f32 %0, %1;" : "=r"(u) : "f"(x));
    return __uint_as_float(u);
}

__device__ __forceinline__ void mma8(float c[4], const uint32_t a[4], const uint32_t b[2]) {
    asm volatile(
        "mma.sync.aligned.m16n8k8.row.col.f32.tf32.tf32.f32 "
        "{%0,%1,%2,%3},{%4,%5,%6,%7},{%8,%9},{%0,%1,%2,%3};"
        : "+f"(c[0]), "+f"(c[1]), "+f"(c[2]), "+f"(c[3])
        : "r"(a[0]), "r"(a[1]), "r"(a[2]), "r"(a[3]), "r"(b[0]), "r"(b[1]));
}

__device__ __forceinline__ void cp16(void* s, const void* g) {
    uint32_t sa = (uint32_t)__cvta_generic_to_shared(s);
    asm volatile("cp.async.cg.shared.global [%0], [%1], 16;\n" :: "r"(sa), "l"(g));
}
#define CP_COMMIT() asm volatile("cp.async.commit_group;\n" ::: "memory")
#define CP_WAIT0()  asm volatile("cp.async.wait_group 0;\n" ::: "memory")

// ---------------- metadata: chain ids, positions, rope tables --------------
__global__ void meta_kernel(const void* __restrict__ maskraw)
{
    const int b   = blockIdx.x;
    const int tid = threadIdx.x;   // 256 threads

    __shared__ int slen[Lv];
    __shared__ int scs[Lv];
    __shared__ int spart[257];
    __shared__ int sis64;

    if (tid == 0) {
        const int* w = (const int*)maskraw;
        bool odd_zero = true, even_nz = false;
        for (int i = 0; i < 32; i++) {
            if (w[2*i+1] != 0) odd_zero = false;
            if (w[2*i]   != 0) even_nz  = true;
        }
        sis64 = (odd_zero && even_nz) ? 1 : 0;
    }
    __syncthreads();
    const int is64 = sis64;

    for (int i = tid; i < Lv; i += 256) {
        long long v;
        if (is64) v = ((const long long*)maskraw)[b*Lv + i];
        else      v = ((const int*)maskraw)[b*Lv + i];
        slen[i] = (int)v;
    }
    __syncthreads();

    int base = tid * 8;
    int s = 0, loc[8];
    #pragma unroll
    for (int k = 0; k < 8; k++) { s += slen[base + k]; loc[k] = s; }
    spart[tid] = s;
    __syncthreads();
    if (tid == 0) {
        int acc = 0;
        for (int i = 0; i < 256; i++) { int t = spart[i]; spart[i] = acc; acc += t; }
        spart[256] = acc;
    }
    __syncthreads();
    int off = spart[tid];
    #pragma unroll
    for (int k = 0; k < 8; k++) scs[base + k] = off + loc[k];
    __syncthreads();

    const int total = scs[Lv - 1];

    for (int p = tid; p < Lv; p += 256) {
        int lo = 0, hi = Lv;
        while (lo < hi) { int mid = (lo + hi) >> 1; if (scs[mid] > p) hi = mid; else lo = mid + 1; }
        const int cid = lo;
        const bool valid = (p < total);
        const int prev = (cid > 0 && cid <= Lv) ? scs[(cid - 1 < Lv) ? cid - 1 : Lv - 1] : 0;
        const float pos = valid ? (float)(p - prev) : 0.0f;

        g_cidq[b][p] = valid ? cid : Lv;
        g_cidk[b][p] = valid ? cid : -1;

        for (int d2 = 0; d2 < 32; d2++) {
            float inv = powf(10000.0f, -((float)(2 * d2)) / 64.0f);
            float a = pos * inv;
            float sn, cs;
            sincosf(a, &sn, &cs);
            g_cos[b][p][d2] = cs;
            g_sin[b][p][d2] = sn;
        }
    }
}

// ---------------- QKV GEMM (tf32): 128x128, BK=32, double-buffered ----------
#define GBM 128
#define GBN 128
#define GBK 32
#define GSTR 36
#define GEMM_SMEM (2 * (GBM + GBN) * GSTR * 4)

__global__ void __launch_bounds__(256) qkv_gemm(
    const float* __restrict__ X,
    const float* __restrict__ W0, const float* __restrict__ b0,
    const float* __restrict__ W1, const float* __restrict__ b1)
{
    const int br = blockIdx.z;
    const float* __restrict__ W    = br ? W1 : W0;
    const float* __restrict__ bias = br ? b1 : b0;

    const int m0 = blockIdx.y * GBM;
    const int n0 = blockIdx.x * GBN;

    extern __shared__ __align__(16) float gsm[];
    float* As = gsm;                         // [2][GBM][GSTR]
    float* Bs = gsm + 2 * GBM * GSTR;        // [2][GBN][GSTR]

    const int tid  = threadIdx.x;
    const int lane = tid & 31;
    const int wid  = tid >> 5;
    const int wm   = (wid >> 2) * 64;
    const int wn   = (wid & 3) * 32;

    // loader coords: 1024 float4 per tile, 4 per thread
    const int lrow0 = tid >> 3;          // tid/8: rows tid/8, +32, +64, +96
    const int lc4   = (tid & 7) * 4;

    float4 ra[4], rb[4];
    #pragma unroll
    for (int it = 0; it < 4; it++) {
        const int row = lrow0 + it * 32;
        ra[it] = *(const float4*)&X[(size_t)(m0 + row) * Dv + lc4];
        rb[it] = *(const float4*)&W[(size_t)(n0 + row) * Dv + lc4];
    }
    #pragma unroll
    for (int it = 0; it < 4; it++) {
        const int row = lrow0 + it * 32;
        float* a = &As[row * GSTR + lc4];
        a[0] = to_tf32(ra[it].x); a[1] = to_tf32(ra[it].y);
        a[2] = to_tf32(ra[it].z); a[3] = to_tf32(ra[it].w);
        float* bp = &Bs[row * GSTR + lc4];
        bp[0] = to_tf32(rb[it].x); bp[1] = to_tf32(rb[it].y);
        bp[2] = to_tf32(rb[it].z); bp[3] = to_tf32(rb[it].w);
    }
    __syncthreads();

    float acc[4][4][4];
    #pragma unroll
    for (int i = 0; i < 4; i++)
        #pragma unroll
        for (int j = 0; j < 4; j++)
            #pragma unroll
            for (int k = 0; k < 4; k++) acc[i][j][k] = 0.0f;

    int buf = 0;
    for (int kt = 0; kt < Dv; kt += GBK, buf ^= 1) {
        const bool more = (kt + GBK) < Dv;
        if (more) {
            #pragma unroll
            for (int it = 0; it < 4; it++) {
                const int row = lrow0 + it * 32;
                ra[it] = *(const float4*)&X[(size_t)(m0 + row) * Dv + kt + GBK + lc4];
                rb[it] = *(const float4*)&W[(size_t)(n0 + row) * Dv + kt + GBK + lc4];
            }
        }

        const float* Ac = As + buf * GBM * GSTR;
        const float* Bc = Bs + buf * GBN * GSTR;
        #pragma unroll
        for (int ks = 0; ks < 4; ks++) {
            const int kc = ks * 8 + (lane & 3);
            uint32_t af[4][4];
            #pragma unroll
            for (int mi = 0; mi < 4; mi++) {
                const int ar = wm + mi * 16 + (lane >> 2);
                af[mi][0] = __float_as_uint(Ac[ar * GSTR + kc]);
                af[mi][1] = __float_as_uint(Ac[(ar + 8) * GSTR + kc]);
                af[mi][2] = __float_as_uint(Ac[ar * GSTR + kc + 4]);
                af[mi][3] = __float_as_uint(Ac[(ar + 8) * GSTR + kc + 4]);
            }
            uint32_t bf[4][2];
            #pragma unroll
            for (int ni = 0; ni < 4; ni++) {
                const int brr = wn + ni * 8 + (lane >> 2);
                bf[ni][0] = __float_as_uint(Bc[brr * GSTR + kc]);
                bf[ni][1] = __float_as_uint(Bc[brr * GSTR + kc + 4]);
            }
            #pragma unroll
            for (int mi = 0; mi < 4; mi++)
                #pragma unroll
                for (int ni = 0; ni < 4; ni++)
                    mma8(acc[mi][ni], af[mi], bf[ni]);
        }

        if (more) {
            float* An = As + (buf ^ 1) * GBM * GSTR;
            float* Bn = Bs + (buf ^ 1) * GBN * GSTR;
            #pragma unroll
            for (int it = 0; it < 4; it++) {
                const int row = lrow0 + it * 32;
                float* a = &An[row * GSTR + lc4];
                a[0] = to_tf32(ra[it].x); a[1] = to_tf32(ra[it].y);
                a[2] = to_tf32(ra[it].z); a[3] = to_tf32(ra[it].w);
                float* bp = &Bn[row * GSTR + lc4];
                bp[0] = to_tf32(rb[it].x); bp[1] = to_tf32(rb[it].y);
                bp[2] = to_tf32(rb[it].z); bp[3] = to_tf32(rb[it].w);
            }
        }
        __syncthreads();
    }

    #pragma unroll
    for (int mi = 0; mi < 4; mi++)
        #pragma unroll
        for (int ni = 0; ni < 4; ni++) {
            const int r = m0 + wm + mi * 16 + (lane >> 2);
            const int c = n0 + wn + ni * 8 + 2 * (lane & 3);
            const float bx = bias[c], by = bias[c + 1];
            float2 v;
            v.x = acc[mi][ni][0] + bx; v.y = acc[mi][ni][1] + by;
            *(float2*)&g_qkv[br][r][c] = v;
            v.x = acc[mi][ni][2] + bx; v.y = acc[mi][ni][3] + by;
            *(float2*)&g_qkv[br][r + 8][c] = v;
        }
}

// ---------------- prep: rope + scale + dense [br][b][h][l][64] layout ------
__global__ void __launch_bounds__(1024) prep_kernel()
{
    const int idx = blockIdx.x * 1024 + threadIdx.x;   // 2^22 threads
    const int d  = idx & 31;
    const int l  = (idx >> 5) & 2047;
    const int h  = (idx >> 16) & 15;
    const int b  = (idx >> 20) & 1;
    const int br = (idx >> 21) & 1;

    const float* src = &g_qkv[br][(size_t)b * Lv + l][0];
    const float c = g_cos[b][l][d], s = g_sin[b][l][d];

    const float q1 = src[h * 64 + d],            q2 = src[h * 64 + d + 32];
    const float k1 = src[Dv + h * 64 + d],       k2 = src[Dv + h * 64 + d + 32];
    const float v1 = src[2 * Dv + h * 64 + d],   v2 = src[2 * Dv + h * 64 + d + 32];

    const size_t o = ((((size_t)(br * 2 + b) * 16 + h) * 2048) + l) * 64 + d;
    g_q[o]      = to_tf32((q1 * c - q2 * s) * 0.125f);
    g_q[o + 32] = to_tf32((q2 * c + q1 * s) * 0.125f);
    g_k[o]      = to_tf32(k1 * c - k2 * s);
    g_k[o + 32] = to_tf32(k2 * c + k1 * s);
    g_v[o]      = to_tf32(v1);
    g_v[o + 32] = to_tf32(v2);
}

// ---------------- attention: TQ=128, cp.async double-buffered KV ------------
#define KSTR 68
#define TSZ (64 * KSTR)
#define ATTN_SMEM (4 * TSZ * 4 + 2 * 64 * 4)

__global__ void __launch_bounds__(256) attn_kernel()
{
    const int qt = blockIdx.x;       // 0..15 (128 q rows each)
    const int h  = blockIdx.y;
    const int z  = blockIdx.z;
    const int b  = z & 1;
    const int br = z >> 1;
    const bool intra = (br == 0);

    extern __shared__ __align__(16) float sm[];
    // layout: K0 | V0 | K1 | V1 | kcs[2][64]
    int* kcs = (int*)(sm + 4 * TSZ);

    const int tid  = threadIdx.x;
    const int lane = tid & 31;
    const int wid  = tid >> 5;             // 0..7 : q-row group
    const int rr   = lane >> 2;            // 0..7
    const int qj   = lane & 3;             // 0..3

    const size_t hbase = (((size_t)(br * 2 + b) * 16 + h) * 2048) * 64;
    const float* __restrict__ qg = g_q + hbase + (size_t)qt * 128 * 64;
    const float* __restrict__ kg = g_k + hbase;
    const float* __restrict__ vg = g_v + hbase;
    const int*   __restrict__ cidk = &g_cidk[b][0];

    // loader coords: per tile 1024 float4, 4 per thread
    const int li0 = tid * 4;                       // flat float index base per it

    // ---- stage Q tile (128x64) in K0|V0 region, extract A fragments
    #pragma unroll
    for (int it = 0; it < 8; it++) {
        const int flat = it * 1024 + li0;
        const int i = flat >> 6, d = flat & 63;
        *(float4*)&sm[i * KSTR + d] = *(const float4*)(qg + flat);
    }
    __syncthreads();

    const int rowa = wid * 16 + rr;
    uint32_t qf[8][4];
    #pragma unroll
    for (int ks = 0; ks < 8; ks++) {
        const int c = ks * 8 + qj;
        qf[ks][0] = __float_as_uint(sm[rowa * KSTR + c]);
        qf[ks][1] = __float_as_uint(sm[(rowa + 8) * KSTR + c]);
        qf[ks][2] = __float_as_uint(sm[rowa * KSTR + c + 4]);
        qf[ks][3] = __float_as_uint(sm[(rowa + 8) * KSTR + c + 4]);
    }
    const int qrow0 = qt * 128 + rowa;
    const int qrow1 = qrow0 + 8;
    const int qc0 = g_cidq[b][qrow0];
    const int qc1 = g_cidq[b][qrow1];
    __syncthreads();

    // ---- prologue: async load tile 0
    {
        float* Kb = sm;
        float* Vb = sm + TSZ;
        #pragma unroll
        for (int it = 0; it < 4; it++) {
            const int flat = it * 1024 + li0;
            const int i = flat >> 6, d = flat & 63;
            cp16(&Kb[i * KSTR + d], kg + flat);
            cp16(&Vb[i * KSTR + d], vg + flat);
        }
        if (tid < 16) cp16(&kcs[tid * 4], cidk + tid * 4);
        CP_COMMIT();
    }

    float o[8][4];
    #pragma unroll
    for (int i = 0; i < 8; i++)
        #pragma unroll
        for (int j = 0; j < 4; j++) o[i][j] = 0.0f;

    float m0 = -INFINITY, m1 = -INFINITY, l0 = 0.0f, l1 = 0.0f;

    for (int kt = 0; kt < Lv / 64; kt++) {
        CP_WAIT0();
        __syncthreads();

        const int cur = kt & 1;
        if (kt + 1 < Lv / 64) {
            const int nxt = cur ^ 1;
            float* Kb = sm + (2 * nxt) * TSZ;
            float* Vb = sm + (2 * nxt + 1) * TSZ;
            #pragma unroll
            for (int it = 0; it < 4; it++) {
                const int flat = it * 1024 + li0;
                const int i = flat >> 6, d = flat & 63;
                cp16(&Kb[i * KSTR + d], kg + (size_t)(kt + 1) * 4096 + flat);
                cp16(&Vb[i * KSTR + d], vg + (size_t)(kt + 1) * 4096 + flat);
            }
            if (tid < 16) cp16(&kcs[nxt * 64 + tid * 4], cidk + (kt + 1) * 64 + tid * 4);
            CP_COMMIT();
        }

        const float* Kc = sm + (2 * cur) * TSZ;
        const float* Vc = sm + (2 * cur + 1) * TSZ;
        const int*   kcp = kcs + cur * 64;

        // ---- S = Q K^T  (16 x 64 per warp)
        float sv[8][4];
        #pragma unroll
        for (int i = 0; i < 8; i++)
            #pragma unroll
            for (int j = 0; j < 4; j++) sv[i][j] = 0.0f;

        #pragma unroll
        for (int ks = 0; ks < 8; ks++) {
            const int c = ks * 8 + qj;
            #pragma unroll
            for (int ni = 0; ni < 8; ni++) {
                const int brr = ni * 8 + rr;
                uint32_t bf[2];
                bf[0] = __float_as_uint(Kc[brr * KSTR + c]);
                bf[1] = __float_as_uint(Kc[brr * KSTR + c + 4]);
                mma8(sv[ni], qf[ks], bf);
            }
        }

        // ---- mask
        #pragma unroll
        for (int ni = 0; ni < 8; ni++) {
            const int cc = ni * 8 + 2 * qj;
            const int kc0 = kcp[cc], kc1 = kcp[cc + 1];
            const bool a00 = (kc0 >= 0) && ((kc0 == qc0) == intra);
            const bool a01 = (kc1 >= 0) && ((kc1 == qc0) == intra);
            const bool a10 = (kc0 >= 0) && ((kc0 == qc1) == intra);
            const bool a11 = (kc1 >= 0) && ((kc1 == qc1) == intra);
            sv[ni][0] = a00 ? sv[ni][0] : -INFINITY;
            sv[ni][1] = a01 ? sv[ni][1] : -INFINITY;
            sv[ni][2] = a10 ? sv[ni][2] : -INFINITY;
            sv[ni][3] = a11 ? sv[ni][3] : -INFINITY;
        }

        // ---- register online softmax
        float tmax0 = -INFINITY, tmax1 = -INFINITY;
        #pragma unroll
        for (int ni = 0; ni < 8; ni++) {
            tmax0 = fmaxf(tmax0, fmaxf(sv[ni][0], sv[ni][1]));
            tmax1 = fmaxf(tmax1, fmaxf(sv[ni][2], sv[ni][3]));
        }
        tmax0 = fmaxf(tmax0, __shfl_xor_sync(0xffffffffu, tmax0, 1));
        tmax0 = fmaxf(tmax0, __shfl_xor_sync(0xffffffffu, tmax0, 2));
        tmax1 = fmaxf(tmax1, __shfl_xor_sync(0xffffffffu, tmax1, 1));
        tmax1 = fmaxf(tmax1, __shfl_xor_sync(0xffffffffu, tmax1, 2));

        const float mn0 = fmaxf(m0, tmax0);
        const float mn1 = fmaxf(m1, tmax1);
        float af0, af1, ts0 = 0.0f, ts1 = 0.0f;

        if (mn0 == -INFINITY) {
            af0 = 1.0f;
            #pragma unroll
            for (int ni = 0; ni < 8; ni++) { sv[ni][0] = 0.0f; sv[ni][1] = 0.0f; }
        } else {
            af0 = __expf(m0 - mn0);
            #pragma unroll
            for (int ni = 0; ni < 8; ni++) {
                float p0 = to_tf32(__expf(sv[ni][0] - mn0));
                float p1 = to_tf32(__expf(sv[ni][1] - mn0));
                ts0 += p0 + p1;
                sv[ni][0] = p0; sv[ni][1] = p1;
            }
        }
        if (mn1 == -INFINITY) {
            af1 = 1.0f;
            #pragma unroll
            for (int ni = 0; ni < 8; ni++) { sv[ni][2] = 0.0f; sv[ni][3] = 0.0f; }
        } else {
            af1 = __expf(m1 - mn1);
            #pragma unroll
            for (int ni = 0; ni < 8; ni++) {
                float p2 = to_tf32(__expf(sv[ni][2] - mn1));
                float p3 = to_tf32(__expf(sv[ni][3] - mn1));
                ts1 += p2 + p3;
                sv[ni][2] = p2; sv[ni][3] = p3;
            }
        }
        ts0 += __shfl_xor_sync(0xffffffffu, ts0, 1);
        ts0 += __shfl_xor_sync(0xffffffffu, ts0, 2);
        ts1 += __shfl_xor_sync(0xffffffffu, ts1, 1);
        ts1 += __shfl_xor_sync(0xffffffffu, ts1, 2);
        l0 = l0 * af0 + ts0;  m0 = mn0;
        l1 = l1 * af1 + ts1;  m1 = mn1;

        // ---- rescale O, then O += P V  (P fed straight from sv registers)
        #pragma unroll
        for (int ni = 0; ni < 8; ni++) {
            o[ni][0] *= af0; o[ni][1] *= af0;
            o[ni][2] *= af1; o[ni][3] *= af1;
        }
        #pragma unroll
        for (int ks = 0; ks < 8; ks++) {
            uint32_t pa[4];
            pa[0] = __float_as_uint(sv[ks][0]);   // (r,   2k)
            pa[1] = __float_as_uint(sv[ks][2]);   // (r+8, 2k)
            pa[2] = __float_as_uint(sv[ks][1]);   // (r,   2k+1)
            pa[3] = __float_as_uint(sv[ks][3]);   // (r+8, 2k+1)
            const int vr0 = ks * 8 + 2 * qj;      // permuted V rows
            #pragma unroll
            for (int ni = 0; ni < 8; ni++) {
                const int dn = ni * 8 + rr;
                uint32_t bf[2];
                bf[0] = __float_as_uint(Vc[vr0 * KSTR + dn]);
                bf[1] = __float_as_uint(Vc[(vr0 + 1) * KSTR + dn]);
                mma8(o[ni], pa, bf);
            }
        }
    }

    // ---- epilogue: normalize and store
    const float inv0 = (l0 > 0.0f) ? (1.0f / l0) : 0.0f;
    const float inv1 = (l1 > 0.0f) ? (1.0f / l1) : 0.0f;
    float* __restrict__ out0 = &g_attn[br][(size_t)b * Lv + qrow0][h * 64];
    float* __restrict__ out1 = &g_attn[br][(size_t)b * Lv + qrow1][h * 64];
    #pragma unroll
    for (int ni = 0; ni < 8; ni++) {
        const int cc = ni * 8 + 2 * qj;
        float2 u;
        u.x = o[ni][0] * inv0; u.y = o[ni][1] * inv0;
        *(float2*)&out0[cc] = u;
        u.x = o[ni][2] * inv1; u.y = o[ni][3] * inv1;
        *(float2*)&out1[cc] = u;
    }
}

// ---------------- output GEMM (tf32): Y = (A0+A1) Wout^T + bout ------------
__global__ void __launch_bounds__(256) out_gemm(
    const float* __restrict__ W, const float* __restrict__ bias,
    float* __restrict__ Y)
{
    const int m0 = blockIdx.y * GBM;
    const int n0 = blockIdx.x * GBN;

    extern __shared__ __align__(16) float gsm[];
    float* As = gsm;
    float* Bs = gsm + 2 * GBM * GSTR;

    const int tid  = threadIdx.x;
    const int lane = tid & 31;
    const int wid  = tid >> 5;
    const int wm   = (wid >> 2) * 64;
    const int wn   = (wid & 3) * 32;

    const int lrow0 = tid >> 3;
    const int lc4   = (tid & 7) * 4;

    const float* A0 = &g_attn[0][0][0];
    const float* A1 = &g_attn[1][0][0];

    float4 ra[4], rb[4];
    #pragma unroll
    for (int it = 0; it < 4; it++) {
        const int row = lrow0 + it * 32;
        float4 x = *(const float4*)&A0[(size_t)(m0 + row) * Dv + lc4];
        float4 y = *(const float4*)&A1[(size_t)(m0 + row) * Dv + lc4];
        ra[it].x = x.x + y.x; ra[it].y = x.y + y.y;
        ra[it].z = x.z + y.z; ra[it].w = x.w + y.w;
        rb[it] = *(const float4*)&W[(size_t)(n0 + row) * Dv + lc4];
    }
    #pragma unroll
    for (int it = 0; it < 4; it++) {
        const int row = lrow0 + it * 32;
        float* a = &As[row * GSTR + lc4];
        a[0] = to_tf32(ra[it].x); a[1] = to_tf32(ra[it].y);
        a[2] = to_tf32(ra[it].z); a[3] = to_tf32(ra[it].w);
        float* bp = &Bs[row * GSTR + lc4];
        bp[0] = to_tf32(rb[it].x); bp[1] = to_tf32(rb[it].y);
        bp[2] = to_tf32(rb[it].z); bp[3] = to_tf32(rb[it].w);
    }
    __syncthreads();

    float acc[4][4][4];
    #pragma unroll
    for (int i = 0; i < 4; i++)
        #pragma unroll
        for (int j = 0; j < 4; j++)
            #pragma unroll
            for (int k = 0; k < 4; k++) acc[i][j][k] = 0.0f;

    int buf = 0;
    for (int kt = 0; kt < Dv; kt += GBK, buf ^= 1) {
        const bool more = (kt + GBK) < Dv;
        if (more) {
            #pragma unroll
            for (int it = 0; it < 4; it++) {
                const int row = lrow0 + it * 32;
                float4 x = *(const float4*)&A0[(size_t)(m0 + row) * Dv + kt + GBK + lc4];
                float4 y = *(const float4*)&A1[(size_t)(m0 + row) * Dv + kt + GBK + lc4];
                ra[it].x = x.x + y.x; ra[it].y = x.y + y.y;
                ra[it].z = x.z + y.z; ra[it].w = x.w + y.w;
                rb[it] = *(const float4*)&W[(size_t)(n0 + row) * Dv + kt + GBK + lc4];
            }
        }

        const float* Ac = As + buf * GBM * GSTR;
        const float* Bc = Bs + buf * GBN * GSTR;
        #pragma unroll
        for (int ks = 0; ks < 4; ks++) {
            const int kc = ks * 8 + (lane & 3);
            uint32_t af[4][4];
            #pragma unroll
            for (int mi = 0; mi < 4; mi++) {
                const int ar = wm + mi * 16 + (lane >> 2);
                af[mi][0] = __float_as_uint(Ac[ar * GSTR + kc]);
                af[mi][1] = __float_as_uint(Ac[(ar + 8) * GSTR + kc]);
                af[mi][2] = __float_as_uint(Ac[ar * GSTR + kc + 4]);
                af[mi][3] = __float_as_uint(Ac[(ar + 8) * GSTR + kc + 4]);
            }
            uint32_t bf[4][2];
            #pragma unroll
            for (int ni = 0; ni < 4; ni++) {
                const int brr = wn + ni * 8 + (lane >> 2);
                bf[ni][0] = __float_as_uint(Bc[brr * GSTR + kc]);
                bf[ni][1] = __float_as_uint(Bc[brr * GSTR + kc + 4]);
            }
            #pragma unroll
            for (int mi = 0; mi < 4; mi++)
                #pragma unroll
                for (int ni = 0; ni < 4; ni++)
                    mma8(acc[mi][ni], af[mi], bf[ni]);
        }

        if (more) {
            float* An = As + (buf ^ 1) * GBM * GSTR;
            float* Bn = Bs + (buf ^ 1) * GBN * GSTR;
            #pragma unroll
            for (int it = 0; it < 4; it++) {
                const int row = lrow0 + it * 32;
                float* a = &An[row * GSTR + lc4];
                a[0] = to_tf32(ra[it].x); a[1] = to_tf32(ra[it].y);
                a[2] = to_tf32(ra[it].z); a[3] = to_tf32(ra[it].w);
                float* bp = &Bn[row * GSTR + lc4];
                bp[0] = to_tf32(rb[it].x); bp[1] = to_tf32(rb[it].y);
                bp[2] = to_tf32(rb[it].z); bp[3] = to_tf32(rb[it].w);
            }
        }
        __syncthreads();
    }

    #pragma unroll
    for (int mi = 0; mi < 4; mi++)
        #pragma unroll
        for (int ni = 0; ni < 4; ni++) {
            const int r = m0 + wm + mi * 16 + (lane >> 2);
            const int c = n0 + wn + ni * 8 + 2 * (lane & 3);
            const float bx = bias[c], by = bias[c + 1];
            float2 v;
            v.x = acc[mi][ni][0] + bx; v.y = acc[mi][ni][1] + by;
            *(float2*)&Y[(size_t)r * Dv + c] = v;
            v.x = acc[mi][ni][2] + bx; v.y = acc[mi][ni][3] + by;
            *(float2*)&Y[(size_t)(r + 8) * Dv + c] = v;
        }
}

// ---------------- launcher --------------------------------------------------
extern "C" void kernel_launch(void* const* d_in, const int* in_sizes, int n_in,
                              void* d_out, int out_size)
{
    const float* hidden = (const float*)d_in[0];
    const void*  mask   = d_in[1];
    const float* Wi = (const float*)d_in[2];
    const float* bi = (const float*)d_in[3];
    const float* We = (const float*)d_in[4];
    const float* be = (const float*)d_in[5];
    const float* Wo = (const float*)d_in[6];
    const float* bo = (const float*)d_in[7];
    float* out = (float*)d_out;

    meta_kernel<<<Bv, 256>>>(mask);

    cudaFuncSetAttribute(qkv_gemm, cudaFuncAttributeMaxDynamicSharedMemorySize, GEMM_SMEM);
    dim3 g1(N3D / GBN, ML / GBM, 2);
    qkv_gemm<<<g1, 256, GEMM_SMEM>>>(hidden, Wi, bi, We, be);

    prep_kernel<<<4096, 1024>>>();

    cudaFuncSetAttribute(attn_kernel, cudaFuncAttributeMaxDynamicSharedMemorySize, ATTN_SMEM);
    dim3 g2(Lv / 128, Hv, 2 * Bv);
    attn_kernel<<<g2, 256, ATTN_SMEM>>>();

    cudaFuncSetAttribute(out_gemm, cudaFuncAttributeMaxDynamicSharedMemorySize, GEMM_SMEM);
    dim3 g3(Dv / GBN, ML / GBM);
    out_gemm<<<g3, 256, GEMM_SMEM>>>(Wo, bo, out);
}

// round 11
// speedup vs baseline: 3.4646x; 1.1263x over previous
#include <cuda_runtime.h>
#include <math.h>
#include <stdint.h>

#define Bv 2
#define Lv 2048
#define Dv 1024
#define Hv 16
#define HDv 64
#define ML (Bv*Lv)     // 4096
#define N3D (3*Dv)     // 3072

// ---------------- scratch (device globals; no allocation allowed) ----------
__device__ float g_qkv[2][ML][N3D];                 // un-roped qkv, both branches
__device__ float g_attn[2][ML][Dv];                 // attention outputs
__device__ __align__(16) float g_q[2*2*16*2048*64]; // roped+scaled tf32 [br][b][h][l][d]
__device__ __align__(16) float g_k[2*2*16*2048*64];
__device__ __align__(16) float g_v[2*2*16*2048*64];
__device__ float g_cos[Bv][Lv][32];
__device__ float g_sin[Bv][Lv][32];
__device__ int   g_lo[Bv][Lv];     // own-chain start col (== total for invalid pos)
__device__ int   g_hi[Bv][Lv];     // own-chain end col   (== total for invalid pos)
__device__ int   g_total[Bv];      // number of valid positions

// ---------------- helpers ---------------------------------------------------
__device__ __forceinline__ float to_tf32(float x) {
    uint32_t u;
    asm("cvt.rna.tf32.f32 %0, %1;" : "=r"(u) : "f"(x));
    return __uint_as_float(u);
}

__device__ __forceinline__ void mma8(float c[4], const uint32_t a[4], const uint32_t b[2]) {
    asm volatile(
        "mma.sync.aligned.m16n8k8.row.col.f32.tf32.tf32.f32 "
        "{%0,%1,%2,%3},{%4,%5,%6,%7},{%8,%9},{%0,%1,%2,%3};"
        : "+f"(c[0]), "+f"(c[1]), "+f"(c[2]), "+f"(c[3])
        : "r"(a[0]), "r"(a[1]), "r"(a[2]), "r"(a[3]), "r"(b[0]), "r"(b[1]));
}

__device__ __forceinline__ void cp16(void* s, const void* g) {
    uint32_t sa = (uint32_t)__cvta_generic_to_shared(s);
    asm volatile("cp.async.cg.shared.global [%0], [%1], 16;\n" :: "r"(sa), "l"(g));
}
#define CP_COMMIT() asm volatile("cp.async.commit_group;\n" ::: "memory")
#define CP_WAIT0()  asm volatile("cp.async.wait_group 0;\n" ::: "memory")

// ---------------- metadata: chain ranges, rope tables -----------------------
__global__ void meta_kernel(const void* __restrict__ maskraw)
{
    const int b   = blockIdx.x;
    const int tid = threadIdx.x;   // 256 threads

    __shared__ int slen[Lv];
    __shared__ int scs[Lv];
    __shared__ int spart[257];
    __shared__ int sis64;

    if (tid == 0) {
        const int* w = (const int*)maskraw;
        bool odd_zero = true, even_nz = false;
        for (int i = 0; i < 32; i++) {
            if (w[2*i+1] != 0) odd_zero = false;
            if (w[2*i]   != 0) even_nz  = true;
        }
        sis64 = (odd_zero && even_nz) ? 1 : 0;
    }
    __syncthreads();
    const int is64 = sis64;

    for (int i = tid; i < Lv; i += 256) {
        long long v;
        if (is64) v = ((const long long*)maskraw)[b*Lv + i];
        else      v = ((const int*)maskraw)[b*Lv + i];
        slen[i] = (int)v;
    }
    __syncthreads();

    int base = tid * 8;
    int s = 0, loc[8];
    #pragma unroll
    for (int k = 0; k < 8; k++) { s += slen[base + k]; loc[k] = s; }
    spart[tid] = s;
    __syncthreads();
    if (tid == 0) {
        int acc = 0;
        for (int i = 0; i < 256; i++) { int t = spart[i]; spart[i] = acc; acc += t; }
        spart[256] = acc;
    }
    __syncthreads();
    int off = spart[tid];
    #pragma unroll
    for (int k = 0; k < 8; k++) scs[base + k] = off + loc[k];
    __syncthreads();

    const int total = scs[Lv - 1];
    if (tid == 0) g_total[b] = total;

    for (int p = tid; p < Lv; p += 256) {
        int lo = 0, hi = Lv;
        while (lo < hi) { int mid = (lo + hi) >> 1; if (scs[mid] > p) hi = mid; else lo = mid + 1; }
        const int cid = lo;
        const bool valid = (p < total);
        const int prev = (cid > 0 && cid <= Lv) ? scs[(cid - 1 < Lv) ? cid - 1 : Lv - 1] : 0;
        const float pos = valid ? (float)(p - prev) : 0.0f;

        g_lo[b][p] = valid ? prev : total;        // empty range for invalid pos
        g_hi[b][p] = valid ? scs[cid] : total;

        for (int d2 = 0; d2 < 32; d2++) {
            float inv = powf(10000.0f, -((float)(2 * d2)) / 64.0f);
            float a = pos * inv;
            float sn, cs;
            sincosf(a, &sn, &cs);
            g_cos[b][p][d2] = cs;
            g_sin[b][p][d2] = sn;
        }
    }
}

// ---------------- QKV GEMM (tf32): 128x128, BK=32, double-buffered ----------
#define GBM 128
#define GBN 128
#define GBK 32
#define GSTR 36
#define GEMM_SMEM (2 * (GBM + GBN) * GSTR * 4)

__global__ void __launch_bounds__(256) qkv_gemm(
    const float* __restrict__ X,
    const float* __restrict__ W0, const float* __restrict__ b0,
    const float* __restrict__ W1, const float* __restrict__ b1)
{
    const int br = blockIdx.z;
    const float* __restrict__ W    = br ? W1 : W0;
    const float* __restrict__ bias = br ? b1 : b0;

    const int m0 = blockIdx.y * GBM;
    const int n0 = blockIdx.x * GBN;

    extern __shared__ __align__(16) float gsm[];
    float* As = gsm;                         // [2][GBM][GSTR]
    float* Bs = gsm + 2 * GBM * GSTR;        // [2][GBN][GSTR]

    const int tid  = threadIdx.x;
    const int lane = tid & 31;
    const int wid  = tid >> 5;
    const int wm   = (wid >> 2) * 64;
    const int wn   = (wid & 3) * 32;

    const int lrow0 = tid >> 3;
    const int lc4   = (tid & 7) * 4;

    float4 ra[4], rb[4];
    #pragma unroll
    for (int it = 0; it < 4; it++) {
        const int row = lrow0 + it * 32;
        ra[it] = *(const float4*)&X[(size_t)(m0 + row) * Dv + lc4];
        rb[it] = *(const float4*)&W[(size_t)(n0 + row) * Dv + lc4];
    }
    #pragma unroll
    for (int it = 0; it < 4; it++) {
        const int row = lrow0 + it * 32;
        float* a = &As[row * GSTR + lc4];
        a[0] = to_tf32(ra[it].x); a[1] = to_tf32(ra[it].y);
        a[2] = to_tf32(ra[it].z); a[3] = to_tf32(ra[it].w);
        float* bp = &Bs[row * GSTR + lc4];
        bp[0] = to_tf32(rb[it].x); bp[1] = to_tf32(rb[it].y);
        bp[2] = to_tf32(rb[it].z); bp[3] = to_tf32(rb[it].w);
    }
    __syncthreads();

    float acc[4][4][4];
    #pragma unroll
    for (int i = 0; i < 4; i++)
        #pragma unroll
        for (int j = 0; j < 4; j++)
            #pragma unroll
            for (int k = 0; k < 4; k++) acc[i][j][k] = 0.0f;

    int buf = 0;
    for (int kt = 0; kt < Dv; kt += GBK, buf ^= 1) {
        const bool more = (kt + GBK) < Dv;
        if (more) {
            #pragma unroll
            for (int it = 0; it < 4; it++) {
                const int row = lrow0 + it * 32;
                ra[it] = *(const float4*)&X[(size_t)(m0 + row) * Dv + kt + GBK + lc4];
                rb[it] = *(const float4*)&W[(size_t)(n0 + row) * Dv + kt + GBK + lc4];
            }
        }

        const float* Ac = As + buf * GBM * GSTR;
        const float* Bc = Bs + buf * GBN * GSTR;
        #pragma unroll
        for (int ks = 0; ks < 4; ks++) {
            const int kc = ks * 8 + (lane & 3);
            uint32_t af[4][4];
            #pragma unroll
            for (int mi = 0; mi < 4; mi++) {
                const int ar = wm + mi * 16 + (lane >> 2);
                af[mi][0] = __float_as_uint(Ac[ar * GSTR + kc]);
                af[mi][1] = __float_as_uint(Ac[(ar + 8) * GSTR + kc]);
                af[mi][2] = __float_as_uint(Ac[ar * GSTR + kc + 4]);
                af[mi][3] = __float_as_uint(Ac[(ar + 8) * GSTR + kc + 4]);
            }
            uint32_t bf[4][2];
            #pragma unroll
            for (int ni = 0; ni < 4; ni++) {
                const int brr = wn + ni * 8 + (lane >> 2);
                bf[ni][0] = __float_as_uint(Bc[brr * GSTR + kc]);
                bf[ni][1] = __float_as_uint(Bc[brr * GSTR + kc + 4]);
            }
            #pragma unroll
            for (int mi = 0; mi < 4; mi++)
                #pragma unroll
                for (int ni = 0; ni < 4; ni++)
                    mma8(acc[mi][ni], af[mi], bf[ni]);
        }

        if (more) {
            float* An = As + (buf ^ 1) * GBM * GSTR;
            float* Bn = Bs + (buf ^ 1) * GBN * GSTR;
            #pragma unroll
            for (int it = 0; it < 4; it++) {
                const int row = lrow0 + it * 32;
                float* a = &An[row * GSTR + lc4];
                a[0] = to_tf32(ra[it].x); a[1] = to_tf32(ra[it].y);
                a[2] = to_tf32(ra[it].z); a[3] = to_tf32(ra[it].w);
                float* bp = &Bn[row * GSTR + lc4];
                bp[0] = to_tf32(rb[it].x); bp[1] = to_tf32(rb[it].y);
                bp[2] = to_tf32(rb[it].z); bp[3] = to_tf32(rb[it].w);
            }
        }
        __syncthreads();
    }

    #pragma unroll
    for (int mi = 0; mi < 4; mi++)
        #pragma unroll
        for (int ni = 0; ni < 4; ni++) {
            const int r = m0 + wm + mi * 16 + (lane >> 2);
            const int c = n0 + wn + ni * 8 + 2 * (lane & 3);
            const float bx = bias[c], by = bias[c + 1];
            float2 v;
            v.x = acc[mi][ni][0] + bx; v.y = acc[mi][ni][1] + by;
            *(float2*)&g_qkv[br][r][c] = v;
            v.x = acc[mi][ni][2] + bx; v.y = acc[mi][ni][3] + by;
            *(float2*)&g_qkv[br][r + 8][c] = v;
        }
}

// ---------------- prep: rope + scale + dense [br][b][h][l][64] layout ------
__global__ void __launch_bounds__(1024) prep_kernel()
{
    const int idx = blockIdx.x * 1024 + threadIdx.x;   // 2^22 threads
    const int d  = idx & 31;
    const int l  = (idx >> 5) & 2047;
    const int h  = (idx >> 16) & 15;
    const int b  = (idx >> 20) & 1;
    const int br = (idx >> 21) & 1;

    const float* src = &g_qkv[br][(size_t)b * Lv + l][0];
    const float c = g_cos[b][l][d], s = g_sin[b][l][d];

    const float q1 = src[h * 64 + d],            q2 = src[h * 64 + d + 32];
    const float k1 = src[Dv + h * 64 + d],       k2 = src[Dv + h * 64 + d + 32];
    const float v1 = src[2 * Dv + h * 64 + d],   v2 = src[2 * Dv + h * 64 + d + 32];

    const size_t o = ((((size_t)(br * 2 + b) * 16 + h) * 2048) + l) * 64 + d;
    g_q[o]      = to_tf32((q1 * c - q2 * s) * 0.125f);
    g_q[o + 32] = to_tf32((q2 * c + q1 * s) * 0.125f);
    g_k[o]      = to_tf32(k1 * c - k2 * s);
    g_k[o + 32] = to_tf32(k2 * c + k1 * s);
    g_v[o]      = to_tf32(v1);
    g_v[o + 32] = to_tf32(v2);
}

// ---------------- attention: TQ=128, range masks + intra tile skipping ------
#define KSTR 68
#define TSZ (64 * KSTR)
#define ATTN_SMEM (4 * TSZ * 4)

__global__ void __launch_bounds__(256) attn_kernel()
{
    const int qt = blockIdx.x;       // 0..15 (128 q rows each)
    const int h  = blockIdx.y;
    const int z  = blockIdx.z;
    const int b  = z & 1;
    const int br = z >> 1;
    const bool intra = (br == 0);

    extern __shared__ __align__(16) float sm[];
    // layout: K0 | V0 | K1 | V1
    __shared__ int s_klo, s_khi;

    const int tid  = threadIdx.x;
    const int lane = tid & 31;
    const int wid  = tid >> 5;             // 0..7 : q-row group
    const int rr   = lane >> 2;            // 0..7
    const int qj   = lane & 3;             // 0..3

    const size_t hbase = (((size_t)(br * 2 + b) * 16 + h) * 2048) * 64;
    const float* __restrict__ qg = g_q + hbase + (size_t)qt * 128 * 64;
    const float* __restrict__ kg = g_k + hbase;
    const float* __restrict__ vg = g_v + hbase;

    const int li0 = tid * 4;

    if (tid == 0) { s_klo = 0x7fffffff; s_khi = 0; }

    // ---- stage Q tile (128x64), extract A fragments
    #pragma unroll
    for (int it = 0; it < 8; it++) {
        const int flat = it * 1024 + li0;
        const int i = flat >> 6, d = flat & 63;
        *(float4*)&sm[i * KSTR + d] = *(const float4*)(qg + flat);
    }

    const int rowa  = wid * 16 + rr;
    const int qrow0 = qt * 128 + rowa;
    const int qrow1 = qrow0 + 8;
    const int lo0 = g_lo[b][qrow0], hi0 = g_hi[b][qrow0];
    const int lo1 = g_lo[b][qrow1], hi1 = g_hi[b][qrow1];
    const unsigned rng0 = (unsigned)(hi0 - lo0);
    const unsigned rng1 = (unsigned)(hi1 - lo1);
    const int total = g_total[b];

    if (qj == 0) {           // one lane per row-pair updates the block range
        atomicMin(&s_klo, min(lo0, lo1));
        atomicMax(&s_khi, max(hi0, hi1));
    }
    __syncthreads();

    uint32_t qf[8][4];
    #pragma unroll
    for (int ks = 0; ks < 8; ks++) {
        const int c = ks * 8 + qj;
        qf[ks][0] = __float_as_uint(sm[rowa * KSTR + c]);
        qf[ks][1] = __float_as_uint(sm[(rowa + 8) * KSTR + c]);
        qf[ks][2] = __float_as_uint(sm[rowa * KSTR + c + 4]);
        qf[ks][3] = __float_as_uint(sm[(rowa + 8) * KSTR + c + 4]);
    }
    const int klo = s_klo, khi = s_khi;
    __syncthreads();

    // ---- tile range: intra scans only the block's own-chain union
    const int kt0 = intra ? (klo >> 6) : 0;
    const int kt1 = intra ? ((khi + 63) >> 6) : ((total + 63) >> 6);

    float o[8][4];
    #pragma unroll
    for (int i = 0; i < 8; i++)
        #pragma unroll
        for (int j = 0; j < 4; j++) o[i][j] = 0.0f;

    float m0 = -INFINITY, m1 = -INFINITY, l0 = 0.0f, l1 = 0.0f;

    if (kt0 < kt1) {
        // ---- prologue: async load first tile
        {
            const int pb = kt0 & 1;
            float* Kb = sm + (2 * pb) * TSZ;
            float* Vb = sm + (2 * pb + 1) * TSZ;
            #pragma unroll
            for (int it = 0; it < 4; it++) {
                const int flat = it * 1024 + li0;
                const int i = flat >> 6, d = flat & 63;
                cp16(&Kb[i * KSTR + d], kg + (size_t)kt0 * 4096 + flat);
                cp16(&Vb[i * KSTR + d], vg + (size_t)kt0 * 4096 + flat);
            }
            CP_COMMIT();
        }

        for (int kt = kt0; kt < kt1; kt++) {
            CP_WAIT0();
            __syncthreads();

            const int cur = kt & 1;
            if (kt + 1 < kt1) {
                const int nxt = cur ^ 1;
                float* Kb = sm + (2 * nxt) * TSZ;
                float* Vb = sm + (2 * nxt + 1) * TSZ;
                #pragma unroll
                for (int it = 0; it < 4; it++) {
                    const int flat = it * 1024 + li0;
                    const int i = flat >> 6, d = flat & 63;
                    cp16(&Kb[i * KSTR + d], kg + (size_t)(kt + 1) * 4096 + flat);
                    cp16(&Vb[i * KSTR + d], vg + (size_t)(kt + 1) * 4096 + flat);
                }
                CP_COMMIT();
            }

            const float* Kc = sm + (2 * cur) * TSZ;
            const float* Vc = sm + (2 * cur + 1) * TSZ;

            // ---- S = Q K^T  (16 x 64 per warp)
            float sv[8][4];
            #pragma unroll
            for (int i = 0; i < 8; i++)
                #pragma unroll
                for (int j = 0; j < 4; j++) sv[i][j] = 0.0f;

            #pragma unroll
            for (int ks = 0; ks < 8; ks++) {
                const int c = ks * 8 + qj;
                #pragma unroll
                for (int ni = 0; ni < 8; ni++) {
                    const int brr = ni * 8 + rr;
                    uint32_t bf[2];
                    bf[0] = __float_as_uint(Kc[brr * KSTR + c]);
                    bf[1] = __float_as_uint(Kc[brr * KSTR + c + 4]);
                    mma8(sv[ni], qf[ks], bf);
                }
            }

            // ---- mask via contiguous chain ranges
            const int colb = kt * 64 + 2 * qj;
            #pragma unroll
            for (int ni = 0; ni < 8; ni++) {
                const int c0 = colb + ni * 8;
                const int c1 = c0 + 1;
                const bool in00 = (unsigned)(c0 - lo0) < rng0;
                const bool in01 = (unsigned)(c1 - lo0) < rng0;
                const bool in10 = (unsigned)(c0 - lo1) < rng1;
                const bool in11 = (unsigned)(c1 - lo1) < rng1;
                bool a00, a01, a10, a11;
                if (intra) {
                    a00 = in00; a01 = in01; a10 = in10; a11 = in11;
                } else {
                    a00 = (c0 < total) && !in00;
                    a01 = (c1 < total) && !in01;
                    a10 = (c0 < total) && !in10;
                    a11 = (c1 < total) && !in11;
                }
                sv[ni][0] = a00 ? sv[ni][0] : -INFINITY;
                sv[ni][1] = a01 ? sv[ni][1] : -INFINITY;
                sv[ni][2] = a10 ? sv[ni][2] : -INFINITY;
                sv[ni][3] = a11 ? sv[ni][3] : -INFINITY;
            }

            // ---- register online softmax
            float tmax0 = -INFINITY, tmax1 = -INFINITY;
            #pragma unroll
            for (int ni = 0; ni < 8; ni++) {
                tmax0 = fmaxf(tmax0, fmaxf(sv[ni][0], sv[ni][1]));
                tmax1 = fmaxf(tmax1, fmaxf(sv[ni][2], sv[ni][3]));
            }
            tmax0 = fmaxf(tmax0, __shfl_xor_sync(0xffffffffu, tmax0, 1));
            tmax0 = fmaxf(tmax0, __shfl_xor_sync(0xffffffffu, tmax0, 2));
            tmax1 = fmaxf(tmax1, __shfl_xor_sync(0xffffffffu, tmax1, 1));
            tmax1 = fmaxf(tmax1, __shfl_xor_sync(0xffffffffu, tmax1, 2));

            const float mn0 = fmaxf(m0, tmax0);
            const float mn1 = fmaxf(m1, tmax1);
            float af0, af1, ts0 = 0.0f, ts1 = 0.0f;

            if (mn0 == -INFINITY) {
                af0 = 1.0f;
                #pragma unroll
                for (int ni = 0; ni < 8; ni++) { sv[ni][0] = 0.0f; sv[ni][1] = 0.0f; }
            } else {
                af0 = __expf(m0 - mn0);
                #pragma unroll
                for (int ni = 0; ni < 8; ni++) {
                    float p0 = to_tf32(__expf(sv[ni][0] - mn0));
                    float p1 = to_tf32(__expf(sv[ni][1] - mn0));
                    ts0 += p0 + p1;
                    sv[ni][0] = p0; sv[ni][1] = p1;
                }
            }
            if (mn1 == -INFINITY) {
                af1 = 1.0f;
                #pragma unroll
                for (int ni = 0; ni < 8; ni++) { sv[ni][2] = 0.0f; sv[ni][3] = 0.0f; }
            } else {
                af1 = __expf(m1 - mn1);
                #pragma unroll
                for (int ni = 0; ni < 8; ni++) {
                    float p2 = to_tf32(__expf(sv[ni][2] - mn1));
                    float p3 = to_tf32(__expf(sv[ni][3] - mn1));
                    ts1 += p2 + p3;
                    sv[ni][2] = p2; sv[ni][3] = p3;
                }
            }
            ts0 += __shfl_xor_sync(0xffffffffu, ts0, 1);
            ts0 += __shfl_xor_sync(0xffffffffu, ts0, 2);
            ts1 += __shfl_xor_sync(0xffffffffu, ts1, 1);
            ts1 += __shfl_xor_sync(0xffffffffu, ts1, 2);
            l0 = l0 * af0 + ts0;  m0 = mn0;
            l1 = l1 * af1 + ts1;  m1 = mn1;

            // ---- rescale O, then O += P V (P straight from sv registers)
            #pragma unroll
            for (int ni = 0; ni < 8; ni++) {
                o[ni][0] *= af0; o[ni][1] *= af0;
                o[ni][2] *= af1; o[ni][3] *= af1;
            }
            #pragma unroll
            for (int ks = 0; ks < 8; ks++) {
                uint32_t pa[4];
                pa[0] = __float_as_uint(sv[ks][0]);
                pa[1] = __float_as_uint(sv[ks][2]);
                pa[2] = __float_as_uint(sv[ks][1]);
                pa[3] = __float_as_uint(sv[ks][3]);
                const int vr0 = ks * 8 + 2 * qj;      // permuted V rows
                #pragma unroll
                for (int ni = 0; ni < 8; ni++) {
                    const int dn = ni * 8 + rr;
                    uint32_t bf[2];
                    bf[0] = __float_as_uint(Vc[vr0 * KSTR + dn]);
                    bf[1] = __float_as_uint(Vc[(vr0 + 1) * KSTR + dn]);
                    mma8(o[ni], pa, bf);
                }
            }
        }
    }

    // ---- epilogue: normalize and store
    const float inv0 = (l0 > 0.0f) ? (1.0f / l0) : 0.0f;
    const float inv1 = (l1 > 0.0f) ? (1.0f / l1) : 0.0f;
    float* __restrict__ out0 = &g_attn[br][(size_t)b * Lv + qrow0][h * 64];
    float* __restrict__ out1 = &g_attn[br][(size_t)b * Lv + qrow1][h * 64];
    #pragma unroll
    for (int ni = 0; ni < 8; ni++) {
        const int cc = ni * 8 + 2 * qj;
        float2 u;
        u.x = o[ni][0] * inv0; u.y = o[ni][1] * inv0;
        *(float2*)&out0[cc] = u;
        u.x = o[ni][2] * inv1; u.y = o[ni][3] * inv1;
        *(float2*)&out1[cc] = u;
    }
}

// ---------------- output GEMM (tf32): Y = (A0+A1) Wout^T + bout ------------
__global__ void __launch_bounds__(256) out_gemm(
    const float* __restrict__ W, const float* __restrict__ bias,
    float* __restrict__ Y)
{
    const int m0 = blockIdx.y * GBM;
    const int n0 = blockIdx.x * GBN;

    extern __shared__ __align__(16) float gsm[];
    float* As = gsm;
    float* Bs = gsm + 2 * GBM * GSTR;

    const int tid  = threadIdx.x;
    const int lane = tid & 31;
    const int wid  = tid >> 5;
    const int wm   = (wid >> 2) * 64;
    const int wn   = (wid & 3) * 32;

    const int lrow0 = tid >> 3;
    const int lc4   = (tid & 7) * 4;

    const float* A0 = &g_attn[0][0][0];
    const float* A1 = &g_attn[1][0][0];

    float4 ra[4], rb[4];
    #pragma unroll
    for (int it = 0; it < 4; it++) {
        const int row = lrow0 + it * 32;
        float4 x = *(const float4*)&A0[(size_t)(m0 + row) * Dv + lc4];
        float4 y = *(const float4*)&A1[(size_t)(m0 + row) * Dv + lc4];
        ra[it].x = x.x + y.x; ra[it].y = x.y + y.y;
        ra[it].z = x.z + y.z; ra[it].w = x.w + y.w;
        rb[it] = *(const float4*)&W[(size_t)(n0 + row) * Dv + lc4];
    }
    #pragma unroll
    for (int it = 0; it < 4; it++) {
        const int row = lrow0 + it * 32;
        float* a = &As[row * GSTR + lc4];
        a[0] = to_tf32(ra[it].x); a[1] = to_tf32(ra[it].y);
        a[2] = to_tf32(ra[it].z); a[3] = to_tf32(ra[it].w);
        float* bp = &Bs[row * GSTR + lc4];
        bp[0] = to_tf32(rb[it].x); bp[1] = to_tf32(rb[it].y);
        bp[2] = to_tf32(rb[it].z); bp[3] = to_tf32(rb[it].w);
    }
    __syncthreads();

    float acc[4][4][4];
    #pragma unroll
    for (int i = 0; i < 4; i++)
        #pragma unroll
        for (int j = 0; j < 4; j++)
            #pragma unroll
            for (int k = 0; k < 4; k++) acc[i][j][k] = 0.0f;

    int buf = 0;
    for (int kt = 0; kt < Dv; kt += GBK, buf ^= 1) {
        const bool more = (kt + GBK) < Dv;
        if (more) {
            #pragma unroll
            for (int it = 0; it < 4; it++) {
                const int row = lrow0 + it * 32;
                float4 x = *(const float4*)&A0[(size_t)(m0 + row) * Dv + kt + GBK + lc4];
                float4 y = *(const float4*)&A1[(size_t)(m0 + row) * Dv + kt + GBK + lc4];
                ra[it].x = x.x + y.x; ra[it].y = x.y + y.y;
                ra[it].z = x.z + y.z; ra[it].w = x.w + y.w;
                rb[it] = *(const float4*)&W[(size_t)(n0 + row) * Dv + kt + GBK + lc4];
            }
        }

        const float* Ac = As + buf * GBM * GSTR;
        const float* Bc = Bs + buf * GBN * GSTR;
        #pragma unroll
        for (int ks = 0; ks < 4; ks++) {
            const int kc = ks * 8 + (lane & 3);
            uint32_t af[4][4];
            #pragma unroll
            for (int mi = 0; mi < 4; mi++) {
                const int ar = wm + mi * 16 + (lane >> 2);
                af[mi][0] = __float_as_uint(Ac[ar * GSTR + kc]);
                af[mi][1] = __float_as_uint(Ac[(ar + 8) * GSTR + kc]);
                af[mi][2] = __float_as_uint(Ac[ar * GSTR + kc + 4]);
                af[mi][3] = __float_as_uint(Ac[(ar + 8) * GSTR + kc + 4]);
            }
            uint32_t bf[4][2];
            #pragma unroll
            for (int ni = 0; ni < 4; ni++) {
                const int brr = wn + ni * 8 + (lane >> 2);
                bf[ni][0] = __float_as_uint(Bc[brr * GSTR + kc]);
                bf[ni][1] = __float_as_uint(Bc[brr * GSTR + kc + 4]);
            }
            #pragma unroll
            for (int mi = 0; mi < 4; mi++)
                #pragma unroll
                for (int ni = 0; ni < 4; ni++)
                    mma8(acc[mi][ni], af[mi], bf[ni]);
        }

        if (more) {
            float* An = As + (buf ^ 1) * GBM * GSTR;
            float* Bn = Bs + (buf ^ 1) * GBN * GSTR;
            #pragma unroll
            for (int it = 0; it < 4; it++) {
                const int row = lrow0 + it * 32;
                float* a = &An[row * GSTR + lc4];
                a[0] = to_tf32(ra[it].x); a[1] = to_tf32(ra[it].y);
                a[2] = to_tf32(ra[it].z); a[3] = to_tf32(ra[it].w);
                float* bp = &Bn[row * GSTR + lc4];
                bp[0] = to_tf32(rb[it].x); bp[1] = to_tf32(rb[it].y);
                bp[2] = to_tf32(rb[it].z); bp[3] = to_tf32(rb[it].w);
            }
        }
        __syncthreads();
    }

    #pragma unroll
    for (int mi = 0; mi < 4; mi++)
        #pragma unroll
        for (int ni = 0; ni < 4; ni++) {
            const int r = m0 + wm + mi * 16 + (lane >> 2);
            const int c = n0 + wn + ni * 8 + 2 * (lane & 3);
            const float bx = bias[c], by = bias[c + 1];
            float2 v;
            v.x = acc[mi][ni][0] + bx; v.y = acc[mi][ni][1] + by;
            *(float2*)&Y[(size_t)r * Dv + c] = v;
            v.x = acc[mi][ni][2] + bx; v.y = acc[mi][ni][3] + by;
            *(float2*)&Y[(size_t)(r + 8) * Dv + c] = v;
        }
}

// ---------------- launcher --------------------------------------------------
extern "C" void kernel_launch(void* const* d_in, const int* in_sizes, int n_in,
                              void* d_out, int out_size)
{
    const float* hidden = (const float*)d_in[0];
    const void*  mask   = d_in[1];
    const float* Wi = (const float*)d_in[2];
    const float* bi = (const float*)d_in[3];
    const float* We = (const float*)d_in[4];
    const float* be = (const float*)d_in[5];
    const float* Wo = (const float*)d_in[6];
    const float* bo = (const float*)d_in[7];
    float* out = (float*)d_out;

    meta_kernel<<<Bv, 256>>>(mask);

    cudaFuncSetAttribute(qkv_gemm, cudaFuncAttributeMaxDynamicSharedMemorySize, GEMM_SMEM);
    dim3 g1(N3D / GBN, ML / GBM, 2);
    qkv_gemm<<<g1, 256, GEMM_SMEM>>>(hidden, Wi, bi, We, be);

    prep_kernel<<<4096, 1024>>>();

    cudaFuncSetAttribute(attn_kernel, cudaFuncAttributeMaxDynamicSharedMemorySize, ATTN_SMEM);
    dim3 g2(Lv / 128, Hv, 2 * Bv);
    attn_kernel<<<g2, 256, ATTN_SMEM>>>();

    cudaFuncSetAttribute(out_gemm, cudaFuncAttributeMaxDynamicSharedMemorySize, GEMM_SMEM);
    dim3 g3(Dv / GBN, ML / GBM);
    out_gemm<<<g3, 256, GEMM_SMEM>>>(Wo, bo, out);
}

// round 12
// speedup vs baseline: 3.6414x; 1.0510x over previous
#include <cuda_runtime.h>
#include <math.h>
#include <stdint.h>

#define Bv 2
#define Lv 2048
#define Dv 1024
#define Hv 16
#define HDv 64
#define ML (Bv*Lv)     // 4096
#define N3D (3*Dv)     // 3072

// ---------------- scratch (device globals; no allocation allowed) ----------
__device__ float g_qkv[2][ML][N3D];                 // un-roped qkv, both branches
__device__ float g_attn[2][ML][Dv];                 // attention outputs
__device__ __align__(16) float g_q[2*2*16*2048*64]; // roped+scaled tf32 [br][b][h][l][d]
__device__ __align__(16) float g_k[2*2*16*2048*64];
__device__ __align__(16) float g_v[2*2*16*2048*64];
__device__ float g_cos[Bv][Lv][32];
__device__ float g_sin[Bv][Lv][32];
__device__ int   g_lo[Bv][Lv];     // own-chain start col (== total for invalid pos)
__device__ int   g_hi[Bv][Lv];     // own-chain end col   (== total for invalid pos)
__device__ int   g_total[Bv];      // number of valid positions

// ---------------- helpers ---------------------------------------------------
__device__ __forceinline__ float to_tf32(float x) {
    uint32_t u;
    asm("cvt.rna.tf32.f32 %0, %1;" : "=r"(u) : "f"(x));
    return __uint_as_float(u);
}

__device__ __forceinline__ void mma8(float c[4], const uint32_t a[4], const uint32_t b[2]) {
    asm volatile(
        "mma.sync.aligned.m16n8k8.row.col.f32.tf32.tf32.f32 "
        "{%0,%1,%2,%3},{%4,%5,%6,%7},{%8,%9},{%0,%1,%2,%3};"
        : "+f"(c[0]), "+f"(c[1]), "+f"(c[2]), "+f"(c[3])
        : "r"(a[0]), "r"(a[1]), "r"(a[2]), "r"(a[3]), "r"(b[0]), "r"(b[1]));
}

__device__ __forceinline__ void cp16(void* s, const void* g) {
    uint32_t sa = (uint32_t)__cvta_generic_to_shared(s);
    asm volatile("cp.async.cg.shared.global [%0], [%1], 16;\n" :: "r"(sa), "l"(g));
}
#define CP_COMMIT() asm volatile("cp.async.commit_group;\n" ::: "memory")
#define CP_WAIT0()  asm volatile("cp.async.wait_group 0;\n" ::: "memory")

// ---------------- metadata: chain ranges, rope tables -----------------------
__global__ void meta_kernel(const void* __restrict__ maskraw)
{
    const int b   = blockIdx.x;
    const int tid = threadIdx.x;   // 256 threads

    __shared__ int slen[Lv];
    __shared__ int scs[Lv];
    __shared__ int spart[257];
    __shared__ int sis64;

    if (tid == 0) {
        const int* w = (const int*)maskraw;
        bool odd_zero = true, even_nz = false;
        for (int i = 0; i < 32; i++) {
            if (w[2*i+1] != 0) odd_zero = false;
            if (w[2*i]   != 0) even_nz  = true;
        }
        sis64 = (odd_zero && even_nz) ? 1 : 0;
    }
    __syncthreads();
    const int is64 = sis64;

    for (int i = tid; i < Lv; i += 256) {
        long long v;
        if (is64) v = ((const long long*)maskraw)[b*Lv + i];
        else      v = ((const int*)maskraw)[b*Lv + i];
        slen[i] = (int)v;
    }
    __syncthreads();

    int base = tid * 8;
    int s = 0, loc[8];
    #pragma unroll
    for (int k = 0; k < 8; k++) { s += slen[base + k]; loc[k] = s; }
    spart[tid] = s;
    __syncthreads();
    if (tid == 0) {
        int acc = 0;
        for (int i = 0; i < 256; i++) { int t = spart[i]; spart[i] = acc; acc += t; }
        spart[256] = acc;
    }
    __syncthreads();
    int off = spart[tid];
    #pragma unroll
    for (int k = 0; k < 8; k++) scs[base + k] = off + loc[k];
    __syncthreads();

    const int total = scs[Lv - 1];
    if (tid == 0) g_total[b] = total;

    for (int p = tid; p < Lv; p += 256) {
        int lo = 0, hi = Lv;
        while (lo < hi) { int mid = (lo + hi) >> 1; if (scs[mid] > p) hi = mid; else lo = mid + 1; }
        const int cid = lo;
        const bool valid = (p < total);
        const int prev = (cid > 0 && cid <= Lv) ? scs[(cid - 1 < Lv) ? cid - 1 : Lv - 1] : 0;
        const float pos = valid ? (float)(p - prev) : 0.0f;

        g_lo[b][p] = valid ? prev : total;        // empty range for invalid pos
        g_hi[b][p] = valid ? scs[cid] : total;

        for (int d2 = 0; d2 < 32; d2++) {
            float inv = powf(10000.0f, -((float)(2 * d2)) / 64.0f);
            float a = pos * inv;
            float sn, cs;
            sincosf(a, &sn, &cs);
            g_cos[b][p][d2] = cs;
            g_sin[b][p][d2] = sn;
        }
    }
}

// ---------------- QKV GEMM (tf32): 128x128, BK=32, double-buffered ----------
#define GBM 128
#define GBN 128
#define GBK 32
#define GSTR 36
#define GEMM_SMEM (2 * (GBM + GBN) * GSTR * 4)

__global__ void __launch_bounds__(256) qkv_gemm(
    const float* __restrict__ X,
    const float* __restrict__ W0, const float* __restrict__ b0,
    const float* __restrict__ W1, const float* __restrict__ b1)
{
    const int br = blockIdx.z;
    const float* __restrict__ W    = br ? W1 : W0;
    const float* __restrict__ bias = br ? b1 : b0;

    const int m0 = blockIdx.y * GBM;
    const int n0 = blockIdx.x * GBN;

    extern __shared__ __align__(16) float gsm[];
    float* As = gsm;                         // [2][GBM][GSTR]
    float* Bs = gsm + 2 * GBM * GSTR;        // [2][GBN][GSTR]

    const int tid  = threadIdx.x;
    const int lane = tid & 31;
    const int wid  = tid >> 5;
    const int wm   = (wid >> 2) * 64;
    const int wn   = (wid & 3) * 32;

    const int lrow0 = tid >> 3;
    const int lc4   = (tid & 7) * 4;

    float4 ra[4], rb[4];
    #pragma unroll
    for (int it = 0; it < 4; it++) {
        const int row = lrow0 + it * 32;
        ra[it] = *(const float4*)&X[(size_t)(m0 + row) * Dv + lc4];
        rb[it] = *(const float4*)&W[(size_t)(n0 + row) * Dv + lc4];
    }
    #pragma unroll
    for (int it = 0; it < 4; it++) {
        const int row = lrow0 + it * 32;
        float* a = &As[row * GSTR + lc4];
        a[0] = to_tf32(ra[it].x); a[1] = to_tf32(ra[it].y);
        a[2] = to_tf32(ra[it].z); a[3] = to_tf32(ra[it].w);
        float* bp = &Bs[row * GSTR + lc4];
        bp[0] = to_tf32(rb[it].x); bp[1] = to_tf32(rb[it].y);
        bp[2] = to_tf32(rb[it].z); bp[3] = to_tf32(rb[it].w);
    }
    __syncthreads();

    float acc[4][4][4];
    #pragma unroll
    for (int i = 0; i < 4; i++)
        #pragma unroll
        for (int j = 0; j < 4; j++)
            #pragma unroll
            for (int k = 0; k < 4; k++) acc[i][j][k] = 0.0f;

    int buf = 0;
    for (int kt = 0; kt < Dv; kt += GBK, buf ^= 1) {
        const bool more = (kt + GBK) < Dv;
        if (more) {
            #pragma unroll
            for (int it = 0; it < 4; it++) {
                const int row = lrow0 + it * 32;
                ra[it] = *(const float4*)&X[(size_t)(m0 + row) * Dv + kt + GBK + lc4];
                rb[it] = *(const float4*)&W[(size_t)(n0 + row) * Dv + kt + GBK + lc4];
            }
        }

        const float* Ac = As + buf * GBM * GSTR;
        const float* Bc = Bs + buf * GBN * GSTR;
        #pragma unroll
        for (int ks = 0; ks < 4; ks++) {
            const int kc = ks * 8 + (lane & 3);
            uint32_t af[4][4];
            #pragma unroll
            for (int mi = 0; mi < 4; mi++) {
                const int ar = wm + mi * 16 + (lane >> 2);
                af[mi][0] = __float_as_uint(Ac[ar * GSTR + kc]);
                af[mi][1] = __float_as_uint(Ac[(ar + 8) * GSTR + kc]);
                af[mi][2] = __float_as_uint(Ac[ar * GSTR + kc + 4]);
                af[mi][3] = __float_as_uint(Ac[(ar + 8) * GSTR + kc + 4]);
            }
            uint32_t bf[4][2];
            #pragma unroll
            for (int ni = 0; ni < 4; ni++) {
                const int brr = wn + ni * 8 + (lane >> 2);
                bf[ni][0] = __float_as_uint(Bc[brr * GSTR + kc]);
                bf[ni][1] = __float_as_uint(Bc[brr * GSTR + kc + 4]);
            }
            #pragma unroll
            for (int mi = 0; mi < 4; mi++)
                #pragma unroll
                for (int ni = 0; ni < 4; ni++)
                    mma8(acc[mi][ni], af[mi], bf[ni]);
        }

        if (more) {
            float* An = As + (buf ^ 1) * GBM * GSTR;
            float* Bn = Bs + (buf ^ 1) * GBN * GSTR;
            #pragma unroll
            for (int it = 0; it < 4; it++) {
                const int row = lrow0 + it * 32;
                float* a = &An[row * GSTR + lc4];
                a[0] = to_tf32(ra[it].x); a[1] = to_tf32(ra[it].y);
                a[2] = to_tf32(ra[it].z); a[3] = to_tf32(ra[it].w);
                float* bp = &Bn[row * GSTR + lc4];
                bp[0] = to_tf32(rb[it].x); bp[1] = to_tf32(rb[it].y);
                bp[2] = to_tf32(rb[it].z); bp[3] = to_tf32(rb[it].w);
            }
        }
        __syncthreads();
    }

    #pragma unroll
    for (int mi = 0; mi < 4; mi++)
        #pragma unroll
        for (int ni = 0; ni < 4; ni++) {
            const int r = m0 + wm + mi * 16 + (lane >> 2);
            const int c = n0 + wn + ni * 8 + 2 * (lane & 3);
            const float bx = bias[c], by = bias[c + 1];
            float2 v;
            v.x = acc[mi][ni][0] + bx; v.y = acc[mi][ni][1] + by;
            *(float2*)&g_qkv[br][r][c] = v;
            v.x = acc[mi][ni][2] + bx; v.y = acc[mi][ni][3] + by;
            *(float2*)&g_qkv[br][r + 8][c] = v;
        }
}

// ---------------- prep: rope + scale + dense [br][b][h][l][64] layout ------
__global__ void __launch_bounds__(1024) prep_kernel()
{
    const int idx = blockIdx.x * 1024 + threadIdx.x;   // 2^22 threads
    const int d  = idx & 31;
    const int l  = (idx >> 5) & 2047;
    const int h  = (idx >> 16) & 15;
    const int b  = (idx >> 20) & 1;
    const int br = (idx >> 21) & 1;

    const float* src = &g_qkv[br][(size_t)b * Lv + l][0];
    const float c = g_cos[b][l][d], s = g_sin[b][l][d];

    const float q1 = src[h * 64 + d],            q2 = src[h * 64 + d + 32];
    const float k1 = src[Dv + h * 64 + d],       k2 = src[Dv + h * 64 + d + 32];
    const float v1 = src[2 * Dv + h * 64 + d],   v2 = src[2 * Dv + h * 64 + d + 32];

    const size_t o = ((((size_t)(br * 2 + b) * 16 + h) * 2048) + l) * 64 + d;
    g_q[o]      = to_tf32((q1 * c - q2 * s) * 0.125f);
    g_q[o + 32] = to_tf32((q2 * c + q1 * s) * 0.125f);
    g_k[o]      = to_tf32(k1 * c - k2 * s);
    g_k[o + 32] = to_tf32(k2 * c + k1 * s);
    g_v[o]      = to_tf32(v1);
    g_v[o + 32] = to_tf32(v2);
}

// ---------------- attention: TQ=128, 2 CTAs/SM, Q in smem, tile skipping ----
#define QSTR 68
#define KSTR 68
#define QTSZ (128 * QSTR)
#define TSZ  (64 * KSTR)
#define ATTN_SMEM ((QTSZ + 4 * TSZ) * 4)

__global__ void __launch_bounds__(256, 2) attn_kernel()
{
    const int qt = blockIdx.x;       // 0..15 (128 q rows each)
    const int h  = blockIdx.y;
    const int z  = blockIdx.z;
    const int b  = z & 1;
    const int br = z >> 1;
    const bool intra = (br == 0);

    extern __shared__ __align__(16) float sm[];
    float* smQ  = sm;                 // [128][QSTR]
    float* smKV = sm + QTSZ;          // K0 | V0 | K1 | V1
    __shared__ int s_klo, s_khi, s_glo, s_ghi;

    const int tid  = threadIdx.x;
    const int lane = tid & 31;
    const int wid  = tid >> 5;             // 0..7 : q-row group
    const int rr   = lane >> 2;            // 0..7
    const int qj   = lane & 3;             // 0..3

    const size_t hbase = (((size_t)(br * 2 + b) * 16 + h) * 2048) * 64;
    const float* __restrict__ qg = g_q + hbase + (size_t)qt * 128 * 64;
    const float* __restrict__ kg = g_k + hbase;
    const float* __restrict__ vg = g_v + hbase;

    const int li0 = tid * 4;

    if (tid == 0) { s_klo = 0x7fffffff; s_khi = 0; s_glo = 0; s_ghi = 0x7fffffff; }

    // ---- stage Q tile (128x64) into its own smem region (persists)
    #pragma unroll
    for (int it = 0; it < 8; it++) {
        const int flat = it * 1024 + li0;
        const int i = flat >> 6, d = flat & 63;
        *(float4*)&smQ[i * QSTR + d] = *(const float4*)(qg + flat);
    }

    const int rowa  = wid * 16 + rr;
    const int qrow0 = qt * 128 + rowa;
    const int qrow1 = qrow0 + 8;
    const int lo0 = g_lo[b][qrow0], hi0 = g_hi[b][qrow0];
    const int lo1 = g_lo[b][qrow1], hi1 = g_hi[b][qrow1];
    const unsigned rng0 = (unsigned)(hi0 - lo0);
    const unsigned rng1 = (unsigned)(hi1 - lo1);
    const int total = g_total[b];

    if (qj == 0) {           // one lane per row-pair updates block ranges
        atomicMin(&s_klo, min(lo0, lo1));
        atomicMax(&s_khi, max(hi0, hi1));
        atomicMax(&s_glo, max(lo0, lo1));
        atomicMin(&s_ghi, min(hi0, hi1));
    }
    __syncthreads();

    const int ktEnd = (total + 63) >> 6;
    int kt0, kt1, skipA, skipB;
    if (intra) {
        kt0 = s_klo >> 6;
        kt1 = (s_khi + 63) >> 6;
        skipA = 0; skipB = 0;            // no skip window
    } else {
        kt0 = 0;
        kt1 = ktEnd;
        skipA = min((s_glo + 63) >> 6, kt1);   // tiles fully inside every row's own chain
        skipB = min(s_ghi >> 6, kt1);
        if (skipA >= skipB) { skipA = 0; skipB = 0; }
        if (kt0 >= skipA && kt0 < skipB && skipB > skipA) kt0 = skipB;
    }

    float o[8][4];
    #pragma unroll
    for (int i = 0; i < 8; i++)
        #pragma unroll
        for (int j = 0; j < 4; j++) o[i][j] = 0.0f;

    float m0 = -INFINITY, m1 = -INFINITY, l0 = 0.0f, l1 = 0.0f;

    if (kt0 < kt1) {
        // ---- prologue: async load first tile into buffer 0
        {
            float* Kb = smKV;
            float* Vb = smKV + TSZ;
            #pragma unroll
            for (int it = 0; it < 4; it++) {
                const int flat = it * 1024 + li0;
                const int i = flat >> 6, d = flat & 63;
                cp16(&Kb[i * KSTR + d], kg + (size_t)kt0 * 4096 + flat);
                cp16(&Vb[i * KSTR + d], vg + (size_t)kt0 * 4096 + flat);
            }
            CP_COMMIT();
        }

        int kt = kt0, ping = 0;
        while (kt < kt1) {
            CP_WAIT0();
            __syncthreads();

            int nkt = kt + 1;
            if (nkt >= skipA && nkt < skipB) nkt = skipB;   // exact: skipped tiles fully masked
            if (nkt < kt1) {
                float* Kb = smKV + (2 * (ping ^ 1)) * TSZ;
                float* Vb = smKV + (2 * (ping ^ 1) + 1) * TSZ;
                #pragma unroll
                for (int it = 0; it < 4; it++) {
                    const int flat = it * 1024 + li0;
                    const int i = flat >> 6, d = flat & 63;
                    cp16(&Kb[i * KSTR + d], kg + (size_t)nkt * 4096 + flat);
                    cp16(&Vb[i * KSTR + d], vg + (size_t)nkt * 4096 + flat);
                }
                CP_COMMIT();
            }

            const float* Kc = smKV + (2 * ping) * TSZ;
            const float* Vc = smKV + (2 * ping + 1) * TSZ;

            // ---- S = Q K^T  (16 x 64 per warp), Q fragment re-read from smem
            float sv[8][4];
            #pragma unroll
            for (int i = 0; i < 8; i++)
                #pragma unroll
                for (int j = 0; j < 4; j++) sv[i][j] = 0.0f;

            #pragma unroll
            for (int ks = 0; ks < 8; ks++) {
                const int c = ks * 8 + qj;
                uint32_t qf[4];
                qf[0] = __float_as_uint(smQ[rowa * QSTR + c]);
                qf[1] = __float_as_uint(smQ[(rowa + 8) * QSTR + c]);
                qf[2] = __float_as_uint(smQ[rowa * QSTR + c + 4]);
                qf[3] = __float_as_uint(smQ[(rowa + 8) * QSTR + c + 4]);
                #pragma unroll
                for (int ni = 0; ni < 8; ni++) {
                    const int brr = ni * 8 + rr;
                    uint32_t bf[2];
                    bf[0] = __float_as_uint(Kc[brr * KSTR + c]);
                    bf[1] = __float_as_uint(Kc[brr * KSTR + c + 4]);
                    mma8(sv[ni], qf, bf);
                }
            }

            // ---- mask via contiguous chain ranges
            const int colb = kt * 64 + 2 * qj;
            #pragma unroll
            for (int ni = 0; ni < 8; ni++) {
                const int c0 = colb + ni * 8;
                const int c1 = c0 + 1;
                const bool in00 = (unsigned)(c0 - lo0) < rng0;
                const bool in01 = (unsigned)(c1 - lo0) < rng0;
                const bool in10 = (unsigned)(c0 - lo1) < rng1;
                const bool in11 = (unsigned)(c1 - lo1) < rng1;
                bool a00, a01, a10, a11;
                if (intra) {
                    a00 = in00; a01 = in01; a10 = in10; a11 = in11;
                } else {
                    a00 = (c0 < total) && !in00;
                    a01 = (c1 < total) && !in01;
                    a10 = (c0 < total) && !in10;
                    a11 = (c1 < total) && !in11;
                }
                sv[ni][0] = a00 ? sv[ni][0] : -INFINITY;
                sv[ni][1] = a01 ? sv[ni][1] : -INFINITY;
                sv[ni][2] = a10 ? sv[ni][2] : -INFINITY;
                sv[ni][3] = a11 ? sv[ni][3] : -INFINITY;
            }

            // ---- register online softmax
            float tmax0 = -INFINITY, tmax1 = -INFINITY;
            #pragma unroll
            for (int ni = 0; ni < 8; ni++) {
                tmax0 = fmaxf(tmax0, fmaxf(sv[ni][0], sv[ni][1]));
                tmax1 = fmaxf(tmax1, fmaxf(sv[ni][2], sv[ni][3]));
            }
            tmax0 = fmaxf(tmax0, __shfl_xor_sync(0xffffffffu, tmax0, 1));
            tmax0 = fmaxf(tmax0, __shfl_xor_sync(0xffffffffu, tmax0, 2));
            tmax1 = fmaxf(tmax1, __shfl_xor_sync(0xffffffffu, tmax1, 1));
            tmax1 = fmaxf(tmax1, __shfl_xor_sync(0xffffffffu, tmax1, 2));

            const float mn0 = fmaxf(m0, tmax0);
            const float mn1 = fmaxf(m1, tmax1);
            float af0, af1, ts0 = 0.0f, ts1 = 0.0f;

            if (mn0 == -INFINITY) {
                af0 = 1.0f;
                #pragma unroll
                for (int ni = 0; ni < 8; ni++) { sv[ni][0] = 0.0f; sv[ni][1] = 0.0f; }
            } else {
                af0 = __expf(m0 - mn0);
                #pragma unroll
                for (int ni = 0; ni < 8; ni++) {
                    float p0 = to_tf32(__expf(sv[ni][0] - mn0));
                    float p1 = to_tf32(__expf(sv[ni][1] - mn0));
                    ts0 += p0 + p1;
                    sv[ni][0] = p0; sv[ni][1] = p1;
                }
            }
            if (mn1 == -INFINITY) {
                af1 = 1.0f;
                #pragma unroll
                for (int ni = 0; ni < 8; ni++) { sv[ni][2] = 0.0f; sv[ni][3] = 0.0f; }
            } else {
                af1 = __expf(m1 - mn1);
                #pragma unroll
                for (int ni = 0; ni < 8; ni++) {
                    float p2 = to_tf32(__expf(sv[ni][2] - mn1));
                    float p3 = to_tf32(__expf(sv[ni][3] - mn1));
                    ts1 += p2 + p3;
                    sv[ni][2] = p2; sv[ni][3] = p3;
                }
            }
            ts0 += __shfl_xor_sync(0xffffffffu, ts0, 1);
            ts0 += __shfl_xor_sync(0xffffffffu, ts0, 2);
            ts1 += __shfl_xor_sync(0xffffffffu, ts1, 1);
            ts1 += __shfl_xor_sync(0xffffffffu, ts1, 2);
            l0 = l0 * af0 + ts0;  m0 = mn0;
            l1 = l1 * af1 + ts1;  m1 = mn1;

            // ---- rescale O, then O += P V (P straight from sv registers)
            #pragma unroll
            for (int ni = 0; ni < 8; ni++) {
                o[ni][0] *= af0; o[ni][1] *= af0;
                o[ni][2] *= af1; o[ni][3] *= af1;
            }
            #pragma unroll
            for (int ks = 0; ks < 8; ks++) {
                uint32_t pa[4];
                pa[0] = __float_as_uint(sv[ks][0]);
                pa[1] = __float_as_uint(sv[ks][2]);
                pa[2] = __float_as_uint(sv[ks][1]);
                pa[3] = __float_as_uint(sv[ks][3]);
                const int vr0 = ks * 8 + 2 * qj;      // permuted V rows
                #pragma unroll
                for (int ni = 0; ni < 8; ni++) {
                    const int dn = ni * 8 + rr;
                    uint32_t bf[2];
                    bf[0] = __float_as_uint(Vc[vr0 * KSTR + dn]);
                    bf[1] = __float_as_uint(Vc[(vr0 + 1) * KSTR + dn]);
                    mma8(o[ni], pa, bf);
                }
            }

            kt = nkt;
            ping ^= 1;
        }
    }

    // ---- epilogue: normalize and store
    const float inv0 = (l0 > 0.0f) ? (1.0f / l0) : 0.0f;
    const float inv1 = (l1 > 0.0f) ? (1.0f / l1) : 0.0f;
    float* __restrict__ out0 = &g_attn[br][(size_t)b * Lv + qrow0][h * 64];
    float* __restrict__ out1 = &g_attn[br][(size_t)b * Lv + qrow1][h * 64];
    #pragma unroll
    for (int ni = 0; ni < 8; ni++) {
        const int cc = ni * 8 + 2 * qj;
        float2 u;
        u.x = o[ni][0] * inv0; u.y = o[ni][1] * inv0;
        *(float2*)&out0[cc] = u;
        u.x = o[ni][2] * inv1; u.y = o[ni][3] * inv1;
        *(float2*)&out1[cc] = u;
    }
}

// ---------------- output GEMM (tf32): Y = (A0+A1) Wout^T + bout ------------
__global__ void __launch_bounds__(256) out_gemm(
    const float* __restrict__ W, const float* __restrict__ bias,
    float* __restrict__ Y)
{
    const int m0 = blockIdx.y * GBM;
    const int n0 = blockIdx.x * GBN;

    extern __shared__ __align__(16) float gsm[];
    float* As = gsm;
    float* Bs = gsm + 2 * GBM * GSTR;

    const int tid  = threadIdx.x;
    const int lane = tid & 31;
    const int wid  = tid >> 5;
    const int wm   = (wid >> 2) * 64;
    const int wn   = (wid & 3) * 32;

    const int lrow0 = tid >> 3;
    const int lc4   = (tid & 7) * 4;

    const float* A0 = &g_attn[0][0][0];
    const float* A1 = &g_attn[1][0][0];

    float4 ra[4], rb[4];
    #pragma unroll
    for (int it = 0; it < 4; it++) {
        const int row = lrow0 + it * 32;
        float4 x = *(const float4*)&A0[(size_t)(m0 + row) * Dv + lc4];
        float4 y = *(const float4*)&A1[(size_t)(m0 + row) * Dv + lc4];
        ra[it].x = x.x + y.x; ra[it].y = x.y + y.y;
        ra[it].z = x.z + y.z; ra[it].w = x.w + y.w;
        rb[it] = *(const float4*)&W[(size_t)(n0 + row) * Dv + lc4];
    }
    #pragma unroll
    for (int it = 0; it < 4; it++) {
        const int row = lrow0 + it * 32;
        float* a = &As[row * GSTR + lc4];
        a[0] = to_tf32(ra[it].x); a[1] = to_tf32(ra[it].y);
        a[2] = to_tf32(ra[it].z); a[3] = to_tf32(ra[it].w);
        float* bp = &Bs[row * GSTR + lc4];
        bp[0] = to_tf32(rb[it].x); bp[1] = to_tf32(rb[it].y);
        bp[2] = to_tf32(rb[it].z); bp[3] = to_tf32(rb[it].w);
    }
    __syncthreads();

    float acc[4][4][4];
    #pragma unroll
    for (int i = 0; i < 4; i++)
        #pragma unroll
        for (int j = 0; j < 4; j++)
            #pragma unroll
            for (int k = 0; k < 4; k++) acc[i][j][k] = 0.0f;

    int buf = 0;
    for (int kt = 0; kt < Dv; kt += GBK, buf ^= 1) {
        const bool more = (kt + GBK) < Dv;
        if (more) {
            #pragma unroll
            for (int it = 0; it < 4; it++) {
                const int row = lrow0 + it * 32;
                float4 x = *(const float4*)&A0[(size_t)(m0 + row) * Dv + kt + GBK + lc4];
                float4 y = *(const float4*)&A1[(size_t)(m0 + row) * Dv + kt + GBK + lc4];
                ra[it].x = x.x + y.x; ra[it].y = x.y + y.y;
                ra[it].z = x.z + y.z; ra[it].w = x.w + y.w;
                rb[it] = *(const float4*)&W[(size_t)(n0 + row) * Dv + kt + GBK + lc4];
            }
        }

        const float* Ac = As + buf * GBM * GSTR;
        const float* Bc = Bs + buf * GBN * GSTR;
        #pragma unroll
        for (int ks = 0; ks < 4; ks++) {
            const int kc = ks * 8 + (lane & 3);
            uint32_t af[4][4];
            #pragma unroll
            for (int mi = 0; mi < 4; mi++) {
                const int ar = wm + mi * 16 + (lane >> 2);
                af[mi][0] = __float_as_uint(Ac[ar * GSTR + kc]);
                af[mi][1] = __float_as_uint(Ac[(ar + 8) * GSTR + kc]);
                af[mi][2] = __float_as_uint(Ac[ar * GSTR + kc + 4]);
                af[mi][3] = __float_as_uint(Ac[(ar + 8) * GSTR + kc + 4]);
            }
            uint32_t bf[4][2];
            #pragma unroll
            for (int ni = 0; ni < 4; ni++) {
                const int brr = wn + ni * 8 + (lane >> 2);
                bf[ni][0] = __float_as_uint(Bc[brr * GSTR + kc]);
                bf[ni][1] = __float_as_uint(Bc[brr * GSTR + kc + 4]);
            }
            #pragma unroll
            for (int mi = 0; mi < 4; mi++)
                #pragma unroll
                for (int ni = 0; ni < 4; ni++)
                    mma8(acc[mi][ni], af[mi], bf[ni]);
        }

        if (more) {
            float* An = As + (buf ^ 1) * GBM * GSTR;
            float* Bn = Bs + (buf ^ 1) * GBN * GSTR;
            #pragma unroll
            for (int it = 0; it < 4; it++) {
                const int row = lrow0 + it * 32;
                float* a = &An[row * GSTR + lc4];
                a[0] = to_tf32(ra[it].x); a[1] = to_tf32(ra[it].y);
                a[2] = to_tf32(ra[it].z); a[3] = to_tf32(ra[it].w);
                float* bp = &Bn[row * GSTR + lc4];
                bp[0] = to_tf32(rb[it].x); bp[1] = to_tf32(rb[it].y);
                bp[2] = to_tf32(rb[it].z); bp[3] = to_tf32(rb[it].w);
            }
        }
        __syncthreads();
    }

    #pragma unroll
    for (int mi = 0; mi < 4; mi++)
        #pragma unroll
        for (int ni = 0; ni < 4; ni++) {
            const int r = m0 + wm + mi * 16 + (lane >> 2);
            const int c = n0 + wn + ni * 8 + 2 * (lane & 3);
            const float bx = bias[c], by = bias[c + 1];
            float2 v;
            v.x = acc[mi][ni][0] + bx; v.y = acc[mi][ni][1] + by;
            *(float2*)&Y[(size_t)r * Dv + c] = v;
            v.x = acc[mi][ni][2] + bx; v.y = acc[mi][ni][3] + by;
            *(float2*)&Y[(size_t)(r + 8) * Dv + c] = v;
        }
}

// ---------------- launcher --------------------------------------------------
extern "C" void kernel_launch(void* const* d_in, const int* in_sizes, int n_in,
                              void* d_out, int out_size)
{
    const float* hidden = (const float*)d_in[0];
    const void*  mask   = d_in[1];
    const float* Wi = (const float*)d_in[2];
    const float* bi = (const float*)d_in[3];
    const float* We = (const float*)d_in[4];
    const float* be = (const float*)d_in[5];
    const float* Wo = (const float*)d_in[6];
    const float* bo = (const float*)d_in[7];
    float* out = (float*)d_out;

    meta_kernel<<<Bv, 256>>>(mask);

    cudaFuncSetAttribute(qkv_gemm, cudaFuncAttributeMaxDynamicSharedMemorySize, GEMM_SMEM);
    dim3 g1(N3D / GBN, ML / GBM, 2);
    qkv_gemm<<<g1, 256, GEMM_SMEM>>>(hidden, Wi, bi, We, be);

    prep_kernel<<<4096, 1024>>>();

    cudaFuncSetAttribute(attn_kernel, cudaFuncAttributeMaxDynamicSharedMemorySize, ATTN_SMEM);
    dim3 g2(Lv / 128, Hv, 2 * Bv);
    attn_kernel<<<g2, 256, ATTN_SMEM>>>();

    cudaFuncSetAttribute(out_gemm, cudaFuncAttributeMaxDynamicSharedMemorySize, GEMM_SMEM);
    dim3 g3(Dv / GBN, ML / GBM);
    out_gemm<<<g3, 256, GEMM_SMEM>>>(Wo, bo, out);
}

// round 14
// speedup vs baseline: 3.6777x; 1.0099x over previous
#include <cuda_runtime.h>
#include <math.h>
#include <stdint.h>

#define Bv 2
#define Lv 2048
#define Dv 1024
#define Hv 16
#define HDv 64
#define ML (Bv*Lv)     // 4096
#define N3D (3*Dv)     // 3072

// ---------------- scratch (device globals; no allocation allowed) ----------
__device__ float g_qkv[2][ML][N3D];                 // un-roped qkv, both branches
__device__ float g_attn[2][ML][Dv];                 // attention outputs
__device__ __align__(16) float g_q[2*2*16*2048*64]; // roped+scaled tf32 [br][b][h][l][d]
__device__ __align__(16) float g_k[2*2*16*2048*64];
__device__ __align__(16) float g_v[2*2*16*2048*64];
__device__ float g_cos[Bv][Lv][32];
__device__ float g_sin[Bv][Lv][32];
__device__ int   g_lo[Bv][Lv];     // own-chain start col (== total for invalid pos)
__device__ int   g_hi[Bv][Lv];     // own-chain end col   (== total for invalid pos)
__device__ int   g_total[Bv];      // number of valid positions

// ---------------- helpers ---------------------------------------------------
__device__ __forceinline__ float to_tf32(float x) {
    uint32_t u;
    asm("cvt.rna.tf32.f32 %0, %1;" : "=r"(u) : "f"(x));
    return __uint_as_float(u);
}

__device__ __forceinline__ void mma8(float c[4], const uint32_t a[4], const uint32_t b[2]) {
    asm volatile(
        "mma.sync.aligned.m16n8k8.row.col.f32.tf32.tf32.f32 "
        "{%0,%1,%2,%3},{%4,%5,%6,%7},{%8,%9},{%0,%1,%2,%3};"
        : "+f"(c[0]), "+f"(c[1]), "+f"(c[2]), "+f"(c[3])
        : "r"(a[0]), "r"(a[1]), "r"(a[2]), "r"(a[3]), "r"(b[0]), "r"(b[1]));
}

__device__ __forceinline__ void cp16(void* s, const void* g) {
    uint32_t sa = (uint32_t)__cvta_generic_to_shared(s);
    asm volatile("cp.async.cg.shared.global [%0], [%1], 16;\n" :: "r"(sa), "l"(g));
}
#define CP_COMMIT() asm volatile("cp.async.commit_group;\n" ::: "memory")
#define CP_WAIT0()  asm volatile("cp.async.wait_group 0;\n" ::: "memory")

// ---------------- metadata: chain ranges, rope tables (round-12 exact) ------
__global__ void meta_kernel(const void* __restrict__ maskraw)
{
    const int b   = blockIdx.x;
    const int tid = threadIdx.x;   // 256 threads

    __shared__ int slen[Lv];
    __shared__ int scs[Lv];
    __shared__ int spart[257];
    __shared__ int sis64;

    if (tid == 0) {
        const int* w = (const int*)maskraw;
        bool odd_zero = true, even_nz = false;
        for (int i = 0; i < 32; i++) {
            if (w[2*i+1] != 0) odd_zero = false;
            if (w[2*i]   != 0) even_nz  = true;
        }
        sis64 = (odd_zero && even_nz) ? 1 : 0;
    }
    __syncthreads();
    const int is64 = sis64;

    for (int i = tid; i < Lv; i += 256) {
        long long v;
        if (is64) v = ((const long long*)maskraw)[b*Lv + i];
        else      v = ((const int*)maskraw)[b*Lv + i];
        slen[i] = (int)v;
    }
    __syncthreads();

    int base = tid * 8;
    int s = 0, loc[8];
    #pragma unroll
    for (int k = 0; k < 8; k++) { s += slen[base + k]; loc[k] = s; }
    spart[tid] = s;
    __syncthreads();
    if (tid == 0) {
        int acc = 0;
        for (int i = 0; i < 256; i++) { int t = spart[i]; spart[i] = acc; acc += t; }
        spart[256] = acc;
    }
    __syncthreads();
    int off = spart[tid];
    #pragma unroll
    for (int k = 0; k < 8; k++) scs[base + k] = off + loc[k];
    __syncthreads();

    const int total = scs[Lv - 1];
    if (tid == 0) g_total[b] = total;

    for (int p = tid; p < Lv; p += 256) {
        int lo = 0, hi = Lv;
        while (lo < hi) { int mid = (lo + hi) >> 1; if (scs[mid] > p) hi = mid; else lo = mid + 1; }
        const int cid = lo;
        const bool valid = (p < total);
        const int prev = (cid > 0 && cid <= Lv) ? scs[(cid - 1 < Lv) ? cid - 1 : Lv - 1] : 0;
        const float pos = valid ? (float)(p - prev) : 0.0f;

        g_lo[b][p] = valid ? prev : total;        // empty range for invalid pos
        g_hi[b][p] = valid ? scs[cid] : total;

        for (int d2 = 0; d2 < 32; d2++) {
            float inv = powf(10000.0f, -((float)(2 * d2)) / 64.0f);
            float a = pos * inv;
            float sn, cs;
            sincosf(a, &sn, &cs);
            g_cos[b][p][d2] = cs;
            g_sin[b][p][d2] = sn;
        }
    }
}

// ---------------- QKV GEMM (tf32): 128x64, BK=32, double-buffered, 2 CTA/SM -
// K-loop structure (kt->ks->mma k8) and per-element to_tf32 identical to the
// 128x128 version -> per-output accumulation order unchanged (bitwise same).
#define GBM 128
#define GBN 64
#define GBK 32
#define GSTR 36
#define GEMM_SMEM (2 * (GBM + GBN) * GSTR * 4)

__global__ void __launch_bounds__(256, 2) qkv_gemm(
    const float* __restrict__ X,
    const float* __restrict__ W0, const float* __restrict__ b0,
    const float* __restrict__ W1, const float* __restrict__ b1)
{
    const int br = blockIdx.z;
    const float* __restrict__ W    = br ? W1 : W0;
    const float* __restrict__ bias = br ? b1 : b0;

    const int m0 = blockIdx.y * GBM;
    const int n0 = blockIdx.x * GBN;

    extern __shared__ __align__(16) float gsm[];
    float* As = gsm;                         // [2][GBM][GSTR]
    float* Bs = gsm + 2 * GBM * GSTR;        // [2][GBN][GSTR]

    const int tid  = threadIdx.x;
    const int lane = tid & 31;
    const int wid  = tid >> 5;
    const int wm   = (wid >> 1) * 32;        // 0,32,64,96
    const int wn   = (wid & 1) * 32;         // 0,32

    const int lrow0 = tid >> 3;              // 0..31
    const int lc4   = (tid & 7) * 4;

    float4 ra[4], rb[2];
    #pragma unroll
    for (int it = 0; it < 4; it++)
        ra[it] = *(const float4*)&X[(size_t)(m0 + lrow0 + it * 32) * Dv + lc4];
    #pragma unroll
    for (int it = 0; it < 2; it++)
        rb[it] = *(const float4*)&W[(size_t)(n0 + lrow0 + it * 32) * Dv + lc4];

    #pragma unroll
    for (int it = 0; it < 4; it++) {
        float* a = &As[(lrow0 + it * 32) * GSTR + lc4];
        a[0] = to_tf32(ra[it].x); a[1] = to_tf32(ra[it].y);
        a[2] = to_tf32(ra[it].z); a[3] = to_tf32(ra[it].w);
    }
    #pragma unroll
    for (int it = 0; it < 2; it++) {
        float* bp = &Bs[(lrow0 + it * 32) * GSTR + lc4];
        bp[0] = to_tf32(rb[it].x); bp[1] = to_tf32(rb[it].y);
        bp[2] = to_tf32(rb[it].z); bp[3] = to_tf32(rb[it].w);
    }
    __syncthreads();

    float acc[2][4][4];
    #pragma unroll
    for (int i = 0; i < 2; i++)
        #pragma unroll
        for (int j = 0; j < 4; j++)
            #pragma unroll
            for (int k = 0; k < 4; k++) acc[i][j][k] = 0.0f;

    int buf = 0;
    for (int kt = 0; kt < Dv; kt += GBK, buf ^= 1) {
        const bool more = (kt + GBK) < Dv;
        if (more) {
            #pragma unroll
            for (int it = 0; it < 4; it++)
                ra[it] = *(const float4*)&X[(size_t)(m0 + lrow0 + it * 32) * Dv + kt + GBK + lc4];
            #pragma unroll
            for (int it = 0; it < 2; it++)
                rb[it] = *(const float4*)&W[(size_t)(n0 + lrow0 + it * 32) * Dv + kt + GBK + lc4];
        }

        const float* Ac = As + buf * GBM * GSTR;
        const float* Bc = Bs + buf * GBN * GSTR;
        #pragma unroll
        for (int ks = 0; ks < 4; ks++) {
            const int kc = ks * 8 + (lane & 3);
            uint32_t af[2][4];
            #pragma unroll
            for (int mi = 0; mi < 2; mi++) {
                const int ar = wm + mi * 16 + (lane >> 2);
                af[mi][0] = __float_as_uint(Ac[ar * GSTR + kc]);
                af[mi][1] = __float_as_uint(Ac[(ar + 8) * GSTR + kc]);
                af[mi][2] = __float_as_uint(Ac[ar * GSTR + kc + 4]);
                af[mi][3] = __float_as_uint(Ac[(ar + 8) * GSTR + kc + 4]);
            }
            uint32_t bf[4][2];
            #pragma unroll
            for (int ni = 0; ni < 4; ni++) {
                const int brr = wn + ni * 8 + (lane >> 2);
                bf[ni][0] = __float_as_uint(Bc[brr * GSTR + kc]);
                bf[ni][1] = __float_as_uint(Bc[brr * GSTR + kc + 4]);
            }
            #pragma unroll
            for (int mi = 0; mi < 2; mi++)
                #pragma unroll
                for (int ni = 0; ni < 4; ni++)
                    mma8(acc[mi][ni], af[mi], bf[ni]);
        }

        if (more) {
            float* An = As + (buf ^ 1) * GBM * GSTR;
            float* Bn = Bs + (buf ^ 1) * GBN * GSTR;
            #pragma unroll
            for (int it = 0; it < 4; it++) {
                float* a = &An[(lrow0 + it * 32) * GSTR + lc4];
                a[0] = to_tf32(ra[it].x); a[1] = to_tf32(ra[it].y);
                a[2] = to_tf32(ra[it].z); a[3] = to_tf32(ra[it].w);
            }
            #pragma unroll
            for (int it = 0; it < 2; it++) {
                float* bp = &Bn[(lrow0 + it * 32) * GSTR + lc4];
                bp[0] = to_tf32(rb[it].x); bp[1] = to_tf32(rb[it].y);
                bp[2] = to_tf32(rb[it].z); bp[3] = to_tf32(rb[it].w);
            }
        }
        __syncthreads();
    }

    #pragma unroll
    for (int mi = 0; mi < 2; mi++)
        #pragma unroll
        for (int ni = 0; ni < 4; ni++) {
            const int r = m0 + wm + mi * 16 + (lane >> 2);
            const int c = n0 + wn + ni * 8 + 2 * (lane & 3);
            const float bx = bias[c], by = bias[c + 1];
            float2 v;
            v.x = acc[mi][ni][0] + bx; v.y = acc[mi][ni][1] + by;
            *(float2*)&g_qkv[br][r][c] = v;
            v.x = acc[mi][ni][2] + bx; v.y = acc[mi][ni][3] + by;
            *(float2*)&g_qkv[br][r + 8][c] = v;
        }
}

// ---------------- prep: rope + scale + dense [br][b][h][l][64] layout ------
__global__ void __launch_bounds__(1024) prep_kernel()
{
    const int idx = blockIdx.x * 1024 + threadIdx.x;   // 2^22 threads
    const int d  = idx & 31;
    const int l  = (idx >> 5) & 2047;
    const int h  = (idx >> 16) & 15;
    const int b  = (idx >> 20) & 1;
    const int br = (idx >> 21) & 1;

    const float* src = &g_qkv[br][(size_t)b * Lv + l][0];
    const float c = g_cos[b][l][d], s = g_sin[b][l][d];

    const float q1 = src[h * 64 + d],            q2 = src[h * 64 + d + 32];
    const float k1 = src[Dv + h * 64 + d],       k2 = src[Dv + h * 64 + d + 32];
    const float v1 = src[2 * Dv + h * 64 + d],   v2 = src[2 * Dv + h * 64 + d + 32];

    const size_t o = ((((size_t)(br * 2 + b) * 16 + h) * 2048) + l) * 64 + d;
    g_q[o]      = to_tf32((q1 * c - q2 * s) * 0.125f);
    g_q[o + 32] = to_tf32((q2 * c + q1 * s) * 0.125f);
    g_k[o]      = to_tf32(k1 * c - k2 * s);
    g_k[o + 32] = to_tf32(k2 * c + k1 * s);
    g_v[o]      = to_tf32(v1);
    g_v[o + 32] = to_tf32(v2);
}

// ---------------- attention: TQ=128, 2 CTAs/SM, Q in smem, tile skipping ----
#define QSTR 68
#define KSTR 68
#define QTSZ (128 * QSTR)
#define TSZ  (64 * KSTR)
#define ATTN_SMEM ((QTSZ + 4 * TSZ) * 4)

__global__ void __launch_bounds__(256, 2) attn_kernel()
{
    const int qt = blockIdx.x;       // 0..15 (128 q rows each)
    const int h  = blockIdx.y;
    const int z  = blockIdx.z;
    const int b  = z & 1;
    const int br = z >> 1;
    const bool intra = (br == 0);

    extern __shared__ __align__(16) float sm[];
    float* smQ  = sm;                 // [128][QSTR]
    float* smKV = sm + QTSZ;          // K0 | V0 | K1 | V1
    __shared__ int s_klo, s_khi, s_glo, s_ghi;

    const int tid  = threadIdx.x;
    const int lane = tid & 31;
    const int wid  = tid >> 5;             // 0..7 : q-row group
    const int rr   = lane >> 2;            // 0..7
    const int qj   = lane & 3;             // 0..3

    const size_t hbase = (((size_t)(br * 2 + b) * 16 + h) * 2048) * 64;
    const float* __restrict__ qg = g_q + hbase + (size_t)qt * 128 * 64;
    const float* __restrict__ kg = g_k + hbase;
    const float* __restrict__ vg = g_v + hbase;

    const int li0 = tid * 4;

    if (tid == 0) { s_klo = 0x7fffffff; s_khi = 0; s_glo = 0; s_ghi = 0x7fffffff; }

    // ---- stage Q tile (128x64) into its own smem region (persists)
    #pragma unroll
    for (int it = 0; it < 8; it++) {
        const int flat = it * 1024 + li0;
        const int i = flat >> 6, d = flat & 63;
        *(float4*)&smQ[i * QSTR + d] = *(const float4*)(qg + flat);
    }

    const int rowa  = wid * 16 + rr;
    const int qrow0 = qt * 128 + rowa;
    const int qrow1 = qrow0 + 8;
    const int lo0 = g_lo[b][qrow0], hi0 = g_hi[b][qrow0];
    const int lo1 = g_lo[b][qrow1], hi1 = g_hi[b][qrow1];
    const unsigned rng0 = (unsigned)(hi0 - lo0);
    const unsigned rng1 = (unsigned)(hi1 - lo1);
    const int total = g_total[b];

    if (qj == 0) {           // one lane per row-pair updates block ranges
        atomicMin(&s_klo, min(lo0, lo1));
        atomicMax(&s_khi, max(hi0, hi1));
        atomicMax(&s_glo, max(lo0, lo1));
        atomicMin(&s_ghi, min(hi0, hi1));
    }
    __syncthreads();

    const int ktEnd = (total + 63) >> 6;
    int kt0, kt1, skipA, skipB;
    if (intra) {
        kt0 = s_klo >> 6;
        kt1 = (s_khi + 63) >> 6;
        skipA = 0; skipB = 0;            // no skip window
    } else {
        kt0 = 0;
        kt1 = ktEnd;
        skipA = min((s_glo + 63) >> 6, kt1);   // tiles fully inside every row's own chain
        skipB = min(s_ghi >> 6, kt1);
        if (skipA >= skipB) { skipA = 0; skipB = 0; }
        if (kt0 >= skipA && kt0 < skipB && skipB > skipA) kt0 = skipB;
    }

    float o[8][4];
    #pragma unroll
    for (int i = 0; i < 8; i++)
        #pragma unroll
        for (int j = 0; j < 4; j++) o[i][j] = 0.0f;

    float m0 = -INFINITY, m1 = -INFINITY, l0 = 0.0f, l1 = 0.0f;

    if (kt0 < kt1) {
        // ---- prologue: async load first tile into buffer 0
        {
            float* Kb = smKV;
            float* Vb = smKV + TSZ;
            #pragma unroll
            for (int it = 0; it < 4; it++) {
                const int flat = it * 1024 + li0;
                const int i = flat >> 6, d = flat & 63;
                cp16(&Kb[i * KSTR + d], kg + (size_t)kt0 * 4096 + flat);
                cp16(&Vb[i * KSTR + d], vg + (size_t)kt0 * 4096 + flat);
            }
            CP_COMMIT();
        }

        int kt = kt0, ping = 0;
        while (kt < kt1) {
            CP_WAIT0();
            __syncthreads();

            int nkt = kt + 1;
            if (nkt >= skipA && nkt < skipB) nkt = skipB;   // exact: skipped tiles fully masked
            if (nkt < kt1) {
                float* Kb = smKV + (2 * (ping ^ 1)) * TSZ;
                float* Vb = smKV + (2 * (ping ^ 1) + 1) * TSZ;
                #pragma unroll
                for (int it = 0; it < 4; it++) {
                    const int flat = it * 1024 + li0;
                    const int i = flat >> 6, d = flat & 63;
                    cp16(&Kb[i * KSTR + d], kg + (size_t)nkt * 4096 + flat);
                    cp16(&Vb[i * KSTR + d], vg + (size_t)nkt * 4096 + flat);
                }
                CP_COMMIT();
            }

            const float* Kc = smKV + (2 * ping) * TSZ;
            const float* Vc = smKV + (2 * ping + 1) * TSZ;

            // ---- S = Q K^T  (16 x 64 per warp), Q fragment re-read from smem
            float sv[8][4];
            #pragma unroll
            for (int i = 0; i < 8; i++)
                #pragma unroll
                for (int j = 0; j < 4; j++) sv[i][j] = 0.0f;

            #pragma unroll
            for (int ks = 0; ks < 8; ks++) {
                const int c = ks * 8 + qj;
                uint32_t qf[4];
                qf[0] = __float_as_uint(smQ[rowa * QSTR + c]);
                qf[1] = __float_as_uint(smQ[(rowa + 8) * QSTR + c]);
                qf[2] = __float_as_uint(smQ[rowa * QSTR + c + 4]);
                qf[3] = __float_as_uint(smQ[(rowa + 8) * QSTR + c + 4]);
                #pragma unroll
                for (int ni = 0; ni < 8; ni++) {
                    const int brr = ni * 8 + rr;
                    uint32_t bf[2];
                    bf[0] = __float_as_uint(Kc[brr * KSTR + c]);
                    bf[1] = __float_as_uint(Kc[brr * KSTR + c + 4]);
                    mma8(sv[ni], qf, bf);
                }
            }

            // ---- mask via contiguous chain ranges
            const int colb = kt * 64 + 2 * qj;
            #pragma unroll
            for (int ni = 0; ni < 8; ni++) {
                const int c0 = colb + ni * 8;
                const int c1 = c0 + 1;
                const bool in00 = (unsigned)(c0 - lo0) < rng0;
                const bool in01 = (unsigned)(c1 - lo0) < rng0;
                const bool in10 = (unsigned)(c0 - lo1) < rng1;
                const bool in11 = (unsigned)(c1 - lo1) < rng1;
                bool a00, a01, a10, a11;
                if (intra) {
                    a00 = in00; a01 = in01; a10 = in10; a11 = in11;
                } else {
                    a00 = (c0 < total) && !in00;
                    a01 = (c1 < total) && !in01;
                    a10 = (c0 < total) && !in10;
                    a11 = (c1 < total) && !in11;
                }
                sv[ni][0] = a00 ? sv[ni][0] : -INFINITY;
                sv[ni][1] = a01 ? sv[ni][1] : -INFINITY;
                sv[ni][2] = a10 ? sv[ni][2] : -INFINITY;
                sv[ni][3] = a11 ? sv[ni][3] : -INFINITY;
            }

            // ---- register online softmax
            float tmax0 = -INFINITY, tmax1 = -INFINITY;
            #pragma unroll
            for (int ni = 0; ni < 8; ni++) {
                tmax0 = fmaxf(tmax0, fmaxf(sv[ni][0], sv[ni][1]));
                tmax1 = fmaxf(tmax1, fmaxf(sv[ni][2], sv[ni][3]));
            }
            tmax0 = fmaxf(tmax0, __shfl_xor_sync(0xffffffffu, tmax0, 1));
            tmax0 = fmaxf(tmax0, __shfl_xor_sync(0xffffffffu, tmax0, 2));
            tmax1 = fmaxf(tmax1, __shfl_xor_sync(0xffffffffu, tmax1, 1));
            tmax1 = fmaxf(tmax1, __shfl_xor_sync(0xffffffffu, tmax1, 2));

            const float mn0 = fmaxf(m0, tmax0);
            const float mn1 = fmaxf(m1, tmax1);
            float af0, af1, ts0 = 0.0f, ts1 = 0.0f;

            if (mn0 == -INFINITY) {
                af0 = 1.0f;
                #pragma unroll
                for (int ni = 0; ni < 8; ni++) { sv[ni][0] = 0.0f; sv[ni][1] = 0.0f; }
            } else {
                af0 = __expf(m0 - mn0);
                #pragma unroll
                for (int ni = 0; ni < 8; ni++) {
                    float p0 = to_tf32(__expf(sv[ni][0] - mn0));
                    float p1 = to_tf32(__expf(sv[ni][1] - mn0));
                    ts0 += p0 + p1;
                    sv[ni][0] = p0; sv[ni][1] = p1;
                }
            }
            if (mn1 == -INFINITY) {
                af1 = 1.0f;
                #pragma unroll
                for (int ni = 0; ni < 8; ni++) { sv[ni][2] = 0.0f; sv[ni][3] = 0.0f; }
            } else {
                af1 = __expf(m1 - mn1);
                #pragma unroll
                for (int ni = 0; ni < 8; ni++) {
                    float p2 = to_tf32(__expf(sv[ni][2] - mn1));
                    float p3 = to_tf32(__expf(sv[ni][3] - mn1));
                    ts1 += p2 + p3;
                    sv[ni][2] = p2; sv[ni][3] = p3;
                }
            }
            ts0 += __shfl_xor_sync(0xffffffffu, ts0, 1);
            ts0 += __shfl_xor_sync(0xffffffffu, ts0, 2);
            ts1 += __shfl_xor_sync(0xffffffffu, ts1, 1);
            ts1 += __shfl_xor_sync(0xffffffffu, ts1, 2);
            l0 = l0 * af0 + ts0;  m0 = mn0;
            l1 = l1 * af1 + ts1;  m1 = mn1;

            // ---- rescale O, then O += P V (P straight from sv registers)
            #pragma unroll
            for (int ni = 0; ni < 8; ni++) {
                o[ni][0] *= af0; o[ni][1] *= af0;
                o[ni][2] *= af1; o[ni][3] *= af1;
            }
            #pragma unroll
            for (int ks = 0; ks < 8; ks++) {
                uint32_t pa[4];
                pa[0] = __float_as_uint(sv[ks][0]);
                pa[1] = __float_as_uint(sv[ks][2]);
                pa[2] = __float_as_uint(sv[ks][1]);
                pa[3] = __float_as_uint(sv[ks][3]);
                const int vr0 = ks * 8 + 2 * qj;      // permuted V rows
                #pragma unroll
                for (int ni = 0; ni < 8; ni++) {
                    const int dn = ni * 8 + rr;
                    uint32_t bf[2];
                    bf[0] = __float_as_uint(Vc[vr0 * KSTR + dn]);
                    bf[1] = __float_as_uint(Vc[(vr0 + 1) * KSTR + dn]);
                    mma8(o[ni], pa, bf);
                }
            }

            kt = nkt;
            ping ^= 1;
        }
    }

    // ---- epilogue: normalize and store
    const float inv0 = (l0 > 0.0f) ? (1.0f / l0) : 0.0f;
    const float inv1 = (l1 > 0.0f) ? (1.0f / l1) : 0.0f;
    float* __restrict__ out0 = &g_attn[br][(size_t)b * Lv + qrow0][h * 64];
    float* __restrict__ out1 = &g_attn[br][(size_t)b * Lv + qrow1][h * 64];
    #pragma unroll
    for (int ni = 0; ni < 8; ni++) {
        const int cc = ni * 8 + 2 * qj;
        float2 u;
        u.x = o[ni][0] * inv0; u.y = o[ni][1] * inv0;
        *(float2*)&out0[cc] = u;
        u.x = o[ni][2] * inv1; u.y = o[ni][3] * inv1;
        *(float2*)&out1[cc] = u;
    }
}

// ---------------- output GEMM (tf32): 128x64, 2 CTA/SM ----------------------
__global__ void __launch_bounds__(256, 2) out_gemm(
    const float* __restrict__ W, const float* __restrict__ bias,
    float* __restrict__ Y)
{
    const int m0 = blockIdx.y * GBM;
    const int n0 = blockIdx.x * GBN;

    extern __shared__ __align__(16) float gsm[];
    float* As = gsm;
    float* Bs = gsm + 2 * GBM * GSTR;

    const int tid  = threadIdx.x;
    const int lane = tid & 31;
    const int wid  = tid >> 5;
    const int wm   = (wid >> 1) * 32;
    const int wn   = (wid & 1) * 32;

    const int lrow0 = tid >> 3;
    const int lc4   = (tid & 7) * 4;

    const float* A0 = &g_attn[0][0][0];
    const float* A1 = &g_attn[1][0][0];

    float4 ra[4], rb[2];
    #pragma unroll
    for (int it = 0; it < 4; it++) {
        const int row = lrow0 + it * 32;
        float4 x = *(const float4*)&A0[(size_t)(m0 + row) * Dv + lc4];
        float4 y = *(const float4*)&A1[(size_t)(m0 + row) * Dv + lc4];
        ra[it].x = x.x + y.x; ra[it].y = x.y + y.y;
        ra[it].z = x.z + y.z; ra[it].w = x.w + y.w;
    }
    #pragma unroll
    for (int it = 0; it < 2; it++)
        rb[it] = *(const float4*)&W[(size_t)(n0 + lrow0 + it * 32) * Dv + lc4];

    #pragma unroll
    for (int it = 0; it < 4; it++) {
        float* a = &As[(lrow0 + it * 32) * GSTR + lc4];
        a[0] = to_tf32(ra[it].x); a[1] = to_tf32(ra[it].y);
        a[2] = to_tf32(ra[it].z); a[3] = to_tf32(ra[it].w);
    }
    #pragma unroll
    for (int it = 0; it < 2; it++) {
        float* bp = &Bs[(lrow0 + it * 32) * GSTR + lc4];
        bp[0] = to_tf32(rb[it].x); bp[1] = to_tf32(rb[it].y);
        bp[2] = to_tf32(rb[it].z); bp[3] = to_tf32(rb[it].w);
    }
    __syncthreads();

    float acc[2][4][4];
    #pragma unroll
    for (int i = 0; i < 2; i++)
        #pragma unroll
        for (int j = 0; j < 4; j++)
            #pragma unroll
            for (int k = 0; k < 4; k++) acc[i][j][k] = 0.0f;

    int buf = 0;
    for (int kt = 0; kt < Dv; kt += GBK, buf ^= 1) {
        const bool more = (kt + GBK) < Dv;
        if (more) {
            #pragma unroll
            for (int it = 0; it < 4; it++) {
                const int row = lrow0 + it * 32;
                float4 x = *(const float4*)&A0[(size_t)(m0 + row) * Dv + kt + GBK + lc4];
                float4 y = *(const float4*)&A1[(size_t)(m0 + row) * Dv + kt + GBK + lc4];
                ra[it].x = x.x + y.x; ra[it].y = x.y + y.y;
                ra[it].z = x.z + y.z; ra[it].w = x.w + y.w;
            }
            #pragma unroll
            for (int it = 0; it < 2; it++)
                rb[it] = *(const float4*)&W[(size_t)(n0 + lrow0 + it * 32) * Dv + kt + GBK + lc4];
        }

        const float* Ac = As + buf * GBM * GSTR;
        const float* Bc = Bs + buf * GBN * GSTR;
        #pragma unroll
        for (int ks = 0; ks < 4; ks++) {
            const int kc = ks * 8 + (lane & 3);
            uint32_t af[2][4];
            #pragma unroll
            for (int mi = 0; mi < 2; mi++) {
                const int ar = wm + mi * 16 + (lane >> 2);
                af[mi][0] = __float_as_uint(Ac[ar * GSTR + kc]);
                af[mi][1] = __float_as_uint(Ac[(ar + 8) * GSTR + kc]);
                af[mi][2] = __float_as_uint(Ac[ar * GSTR + kc + 4]);
                af[mi][3] = __float_as_uint(Ac[(ar + 8) * GSTR + kc + 4]);
            }
            uint32_t bf[4][2];
            #pragma unroll
            for (int ni = 0; ni < 4; ni++) {
                const int brr = wn + ni * 8 + (lane >> 2);
                bf[ni][0] = __float_as_uint(Bc[brr * GSTR + kc]);
                bf[ni][1] = __float_as_uint(Bc[brr * GSTR + kc + 4]);
            }
            #pragma unroll
            for (int mi = 0; mi < 2; mi++)
                #pragma unroll
                for (int ni = 0; ni < 4; ni++)
                    mma8(acc[mi][ni], af[mi], bf[ni]);
        }

        if (more) {
            float* An = As + (buf ^ 1) * GBM * GSTR;
            float* Bn = Bs + (buf ^ 1) * GBN * GSTR;
            #pragma unroll
            for (int it = 0; it < 4; it++) {
                float* a = &An[(lrow0 + it * 32) * GSTR + lc4];
                a[0] = to_tf32(ra[it].x); a[1] = to_tf32(ra[it].y);
                a[2] = to_tf32(ra[it].z); a[3] = to_tf32(ra[it].w);
            }
            #pragma unroll
            for (int it = 0; it < 2; it++) {
                float* bp = &Bn[(lrow0 + it * 32) * GSTR + lc4];
                bp[0] = to_tf32(rb[it].x); bp[1] = to_tf32(rb[it].y);
                bp[2] = to_tf32(rb[it].z); bp[3] = to_tf32(rb[it].w);
            }
        }
        __syncthreads();
    }

    #pragma unroll
    for (int mi = 0; mi < 2; mi++)
        #pragma unroll
        for (int ni = 0; ni < 4; ni++) {
            const int r = m0 + wm + mi * 16 + (lane >> 2);
            const int c = n0 + wn + ni * 8 + 2 * (lane & 3);
            const float bx = bias[c], by = bias[c + 1];
            float2 v;
            v.x = acc[mi][ni][0] + bx; v.y = acc[mi][ni][1] + by;
            *(float2*)&Y[(size_t)r * Dv + c] = v;
            v.x = acc[mi][ni][2] + bx; v.y = acc[mi][ni][3] + by;
            *(float2*)&Y[(size_t)(r + 8) * Dv + c] = v;
        }
}

// ---------------- launcher --------------------------------------------------
extern "C" void kernel_launch(void* const* d_in, const int* in_sizes, int n_in,
                              void* d_out, int out_size)
{
    const float* hidden = (const float*)d_in[0];
    const void*  mask   = d_in[1];
    const float* Wi = (const float*)d_in[2];
    const float* bi = (const float*)d_in[3];
    const float* We = (const float*)d_in[4];
    const float* be = (const float*)d_in[5];
    const float* Wo = (const float*)d_in[6];
    const float* bo = (const float*)d_in[7];
    float* out = (float*)d_out;

    meta_kernel<<<Bv, 256>>>(mask);

    cudaFuncSetAttribute(qkv_gemm, cudaFuncAttributeMaxDynamicSharedMemorySize, GEMM_SMEM);
    dim3 g1(N3D / GBN, ML / GBM, 2);
    qkv_gemm<<<g1, 256, GEMM_SMEM>>>(hidden, Wi, bi, We, be);

    prep_kernel<<<4096, 1024>>>();

    cudaFuncSetAttribute(attn_kernel, cudaFuncAttributeMaxDynamicSharedMemorySize, ATTN_SMEM);
    dim3 g2(Lv / 128, Hv, 2 * Bv);
    attn_kernel<<<g2, 256, ATTN_SMEM>>>();

    cudaFuncSetAttribute(out_gemm, cudaFuncAttributeMaxDynamicSharedMemorySize, GEMM_SMEM);
    dim3 g3(Dv / GBN, ML / GBM);
    out_gemm<<<g3, 256, GEMM_SMEM>>>(Wo, bo, out);
}

// round 16
// speedup vs baseline: 3.7922x; 1.0311x over previous
#include <cuda_runtime.h>
#include <math.h>
#include <stdint.h>

#define Bv 2
#define Lv 2048
#define Dv 1024
#define Hv 16
#define HDv 64
#define ML (Bv*Lv)     // 4096
#define N3D (3*Dv)     // 3072

// packed layout constants
#define QKSTR 72                 // Q/K row stride (floats), 72%32==8 -> conflict-free float2
#define HBQK (2048*QKSTR)        // 147456 floats per (br,b,h)
#define KSPAN (64*QKSTR)         // 4608 floats per 64-token K tile
#define VSPAN 4352               // 32*136 floats per 64-token V tile
#define HBV (32*VSPAN)           // 139264 floats per (br,b,h)

// ---------------- scratch (device globals; no allocation allowed) ----------
__device__ float g_qkv[2][ML][N3D];                 // un-roped qkv, both branches
__device__ float g_attn[2][ML][Dv];                 // attention outputs
__device__ __align__(16) float g_q[64*HBQK];        // packed-col, roped+scaled tf32
__device__ __align__(16) float g_k[64*HBQK];        // packed-col tf32
__device__ __align__(16) float g_v[64*HBV];         // row-pair-interleaved tf32
__device__ float g_cos[Bv][Lv][32];
__device__ float g_sin[Bv][Lv][32];
__device__ int   g_lo[Bv][Lv];     // own-chain start col (== total for invalid pos)
__device__ int   g_hi[Bv][Lv];     // own-chain end col   (== total for invalid pos)
__device__ int   g_total[Bv];      // number of valid positions

// ---------------- helpers ---------------------------------------------------
__device__ __forceinline__ float to_tf32(float x) {
    uint32_t u;
    asm("cvt.rna.tf32.f32 %0, %1;" : "=r"(u) : "f"(x));
    return __uint_as_float(u);
}

__device__ __forceinline__ void mma8(float c[4], const uint32_t a[4], const uint32_t b[2]) {
    asm volatile(
        "mma.sync.aligned.m16n8k8.row.col.f32.tf32.tf32.f32 "
        "{%0,%1,%2,%3},{%4,%5,%6,%7},{%8,%9},{%0,%1,%2,%3};"
        : "+f"(c[0]), "+f"(c[1]), "+f"(c[2]), "+f"(c[3])
        : "r"(a[0]), "r"(a[1]), "r"(a[2]), "r"(a[3]), "r"(b[0]), "r"(b[1]));
}

__device__ __forceinline__ void cp16(void* s, const void* g) {
    uint32_t sa = (uint32_t)__cvta_generic_to_shared(s);
    asm volatile("cp.async.cg.shared.global [%0], [%1], 16;\n" :: "r"(sa), "l"(g));
}
#define CP_COMMIT() asm volatile("cp.async.commit_group;\n" ::: "memory")
#define CP_WAIT0()  asm volatile("cp.async.wait_group 0;\n" ::: "memory")

// ---------------- metadata: chain ranges, rope tables (round-12 exact) ------
__global__ void meta_kernel(const void* __restrict__ maskraw)
{
    const int b   = blockIdx.x;
    const int tid = threadIdx.x;   // 256 threads

    __shared__ int slen[Lv];
    __shared__ int scs[Lv];
    __shared__ int spart[257];
    __shared__ int sis64;

    if (tid == 0) {
        const int* w = (const int*)maskraw;
        bool odd_zero = true, even_nz = false;
        for (int i = 0; i < 32; i++) {
            if (w[2*i+1] != 0) odd_zero = false;
            if (w[2*i]   != 0) even_nz  = true;
        }
        sis64 = (odd_zero && even_nz) ? 1 : 0;
    }
    __syncthreads();
    const int is64 = sis64;

    for (int i = tid; i < Lv; i += 256) {
        long long v;
        if (is64) v = ((const long long*)maskraw)[b*Lv + i];
        else      v = ((const int*)maskraw)[b*Lv + i];
        slen[i] = (int)v;
    }
    __syncthreads();

    int base = tid * 8;
    int s = 0, loc[8];
    #pragma unroll
    for (int k = 0; k < 8; k++) { s += slen[base + k]; loc[k] = s; }
    spart[tid] = s;
    __syncthreads();
    if (tid == 0) {
        int acc = 0;
        for (int i = 0; i < 256; i++) { int t = spart[i]; spart[i] = acc; acc += t; }
        spart[256] = acc;
    }
    __syncthreads();
    int off = spart[tid];
    #pragma unroll
    for (int k = 0; k < 8; k++) scs[base + k] = off + loc[k];
    __syncthreads();

    const int total = scs[Lv - 1];
    if (tid == 0) g_total[b] = total;

    for (int p = tid; p < Lv; p += 256) {
        int lo = 0, hi = Lv;
        while (lo < hi) { int mid = (lo + hi) >> 1; if (scs[mid] > p) hi = mid; else lo = mid + 1; }
        const int cid = lo;
        const bool valid = (p < total);
        const int prev = (cid > 0 && cid <= Lv) ? scs[(cid - 1 < Lv) ? cid - 1 : Lv - 1] : 0;
        const float pos = valid ? (float)(p - prev) : 0.0f;

        g_lo[b][p] = valid ? prev : total;        // empty range for invalid pos
        g_hi[b][p] = valid ? scs[cid] : total;

        for (int d2 = 0; d2 < 32; d2++) {
            float inv = powf(10000.0f, -((float)(2 * d2)) / 64.0f);
            float a = pos * inv;
            float sn, cs;
            sincosf(a, &sn, &cs);
            g_cos[b][p][d2] = cs;
            g_sin[b][p][d2] = sn;
        }
    }
}

// ---------------- QKV GEMM (tf32): 128x64, BK=32, double-buffered, 2 CTA/SM -
#define GBM 128
#define GBN 64
#define GBK 32
#define GSTR 36
#define GEMM_SMEM (2 * (GBM + GBN) * GSTR * 4)

__global__ void __launch_bounds__(256, 2) qkv_gemm(
    const float* __restrict__ X,
    const float* __restrict__ W0, const float* __restrict__ b0,
    const float* __restrict__ W1, const float* __restrict__ b1)
{
    const int br = blockIdx.z;
    const float* __restrict__ W    = br ? W1 : W0;
    const float* __restrict__ bias = br ? b1 : b0;

    const int m0 = blockIdx.y * GBM;
    const int n0 = blockIdx.x * GBN;

    extern __shared__ __align__(16) float gsm[];
    float* As = gsm;                         // [2][GBM][GSTR]
    float* Bs = gsm + 2 * GBM * GSTR;        // [2][GBN][GSTR]

    const int tid  = threadIdx.x;
    const int lane = tid & 31;
    const int wid  = tid >> 5;
    const int wm   = (wid >> 1) * 32;        // 0,32,64,96
    const int wn   = (wid & 1) * 32;         // 0,32

    const int lrow0 = tid >> 3;              // 0..31
    const int lc4   = (tid & 7) * 4;

    float4 ra[4], rb[2];
    #pragma unroll
    for (int it = 0; it < 4; it++)
        ra[it] = *(const float4*)&X[(size_t)(m0 + lrow0 + it * 32) * Dv + lc4];
    #pragma unroll
    for (int it = 0; it < 2; it++)
        rb[it] = *(const float4*)&W[(size_t)(n0 + lrow0 + it * 32) * Dv + lc4];

    #pragma unroll
    for (int it = 0; it < 4; it++) {
        float* a = &As[(lrow0 + it * 32) * GSTR + lc4];
        a[0] = to_tf32(ra[it].x); a[1] = to_tf32(ra[it].y);
        a[2] = to_tf32(ra[it].z); a[3] = to_tf32(ra[it].w);
    }
    #pragma unroll
    for (int it = 0; it < 2; it++) {
        float* bp = &Bs[(lrow0 + it * 32) * GSTR + lc4];
        bp[0] = to_tf32(rb[it].x); bp[1] = to_tf32(rb[it].y);
        bp[2] = to_tf32(rb[it].z); bp[3] = to_tf32(rb[it].w);
    }
    __syncthreads();

    float acc[2][4][4];
    #pragma unroll
    for (int i = 0; i < 2; i++)
        #pragma unroll
        for (int j = 0; j < 4; j++)
            #pragma unroll
            for (int k = 0; k < 4; k++) acc[i][j][k] = 0.0f;

    int buf = 0;
    for (int kt = 0; kt < Dv; kt += GBK, buf ^= 1) {
        const bool more = (kt + GBK) < Dv;
        if (more) {
            #pragma unroll
            for (int it = 0; it < 4; it++)
                ra[it] = *(const float4*)&X[(size_t)(m0 + lrow0 + it * 32) * Dv + kt + GBK + lc4];
            #pragma unroll
            for (int it = 0; it < 2; it++)
                rb[it] = *(const float4*)&W[(size_t)(n0 + lrow0 + it * 32) * Dv + kt + GBK + lc4];
        }

        const float* Ac = As + buf * GBM * GSTR;
        const float* Bc = Bs + buf * GBN * GSTR;
        #pragma unroll
        for (int ks = 0; ks < 4; ks++) {
            const int kc = ks * 8 + (lane & 3);
            uint32_t af[2][4];
            #pragma unroll
            for (int mi = 0; mi < 2; mi++) {
                const int ar = wm + mi * 16 + (lane >> 2);
                af[mi][0] = __float_as_uint(Ac[ar * GSTR + kc]);
                af[mi][1] = __float_as_uint(Ac[(ar + 8) * GSTR + kc]);
                af[mi][2] = __float_as_uint(Ac[ar * GSTR + kc + 4]);
                af[mi][3] = __float_as_uint(Ac[(ar + 8) * GSTR + kc + 4]);
            }
            uint32_t bf[4][2];
            #pragma unroll
            for (int ni = 0; ni < 4; ni++) {
                const int brr = wn + ni * 8 + (lane >> 2);
                bf[ni][0] = __float_as_uint(Bc[brr * GSTR + kc]);
                bf[ni][1] = __float_as_uint(Bc[brr * GSTR + kc + 4]);
            }
            #pragma unroll
            for (int mi = 0; mi < 2; mi++)
                #pragma unroll
                for (int ni = 0; ni < 4; ni++)
                    mma8(acc[mi][ni], af[mi], bf[ni]);
        }

        if (more) {
            float* An = As + (buf ^ 1) * GBM * GSTR;
            float* Bn = Bs + (buf ^ 1) * GBN * GSTR;
            #pragma unroll
            for (int it = 0; it < 4; it++) {
                float* a = &An[(lrow0 + it * 32) * GSTR + lc4];
                a[0] = to_tf32(ra[it].x); a[1] = to_tf32(ra[it].y);
                a[2] = to_tf32(ra[it].z); a[3] = to_tf32(ra[it].w);
            }
            #pragma unroll
            for (int it = 0; it < 2; it++) {
                float* bp = &Bn[(lrow0 + it * 32) * GSTR + lc4];
                bp[0] = to_tf32(rb[it].x); bp[1] = to_tf32(rb[it].y);
                bp[2] = to_tf32(rb[it].z); bp[3] = to_tf32(rb[it].w);
            }
        }
        __syncthreads();
    }

    #pragma unroll
    for (int mi = 0; mi < 2; mi++)
        #pragma unroll
        for (int ni = 0; ni < 4; ni++) {
            const int r = m0 + wm + mi * 16 + (lane >> 2);
            const int c = n0 + wn + ni * 8 + 2 * (lane & 3);
            const float bx = bias[c], by = bias[c + 1];
            float2 v;
            v.x = acc[mi][ni][0] + bx; v.y = acc[mi][ni][1] + by;
            *(float2*)&g_qkv[br][r][c] = v;
            v.x = acc[mi][ni][2] + bx; v.y = acc[mi][ni][3] + by;
            *(float2*)&g_qkv[br][r + 8][c] = v;
        }
}

// ---------------- prep: rope + scale + FRAGMENT-PACKED layouts --------------
// Same FP statements as round 14 (bitwise-identical values); only index maps:
//   Q/K: row-major stride 72, columns permuted p(d)=8(d>>3)+2(d&3)+((d>>2)&1)
//   V:   per-64-token tile, offset (vr>>1)*136 + 2*dn + (vr&1)
__global__ void __launch_bounds__(1024) prep_kernel()
{
    const int idx = blockIdx.x * 1024 + threadIdx.x;   // 2^22 threads
    const int d  = idx & 31;
    const int l  = (idx >> 5) & 2047;
    const int h  = (idx >> 16) & 15;
    const int b  = (idx >> 20) & 1;
    const int br = (idx >> 21) & 1;

    const float* src = &g_qkv[br][(size_t)b * Lv + l][0];
    const float c = g_cos[b][l][d], s = g_sin[b][l][d];

    const float q1 = src[h * 64 + d],            q2 = src[h * 64 + d + 32];
    const float k1 = src[Dv + h * 64 + d],       k2 = src[Dv + h * 64 + d + 32];
    const float v1 = src[2 * Dv + h * 64 + d],   v2 = src[2 * Dv + h * 64 + d + 32];

    const int hb = (br * 2 + b) * 16 + h;
    const int pd = (d >> 3) * 8 + ((d & 3) << 1) + ((d >> 2) & 1);
    const size_t oq = (size_t)hb * HBQK + l * QKSTR + pd;
    g_q[oq]      = to_tf32((q1 * c - q2 * s) * 0.125f);
    g_q[oq + 32] = to_tf32((q2 * c + q1 * s) * 0.125f);
    g_k[oq]      = to_tf32(k1 * c - k2 * s);
    g_k[oq + 32] = to_tf32(k2 * c + k1 * s);

    const int vr = l & 63;
    const size_t ov = (size_t)hb * HBV + (l >> 6) * VSPAN + (vr >> 1) * 136 + 2 * d + (vr & 1);
    g_v[ov]      = to_tf32(v1);
    g_v[ov + 64] = to_tf32(v2);
}

// ---------------- attention: packed-fragment LDS.64, race-free ranges -------
#define QTSZ (128 * QKSTR)        // 9216
#define KVSPAN (KSPAN + VSPAN)    // 8960
#define ATTN_SMEM ((QTSZ + 2 * KVSPAN) * 4)   // 108544 B

__global__ void __launch_bounds__(256, 2) attn_kernel()
{
    // interleaved dispatch: x = qt*4 + (b<<1) + br
    const int br = blockIdx.x & 1;
    const int b  = (blockIdx.x >> 1) & 1;
    const int qt = blockIdx.x >> 2;        // 0..15
    const int h  = blockIdx.y;
    const bool intra = (br == 0);

    extern __shared__ __align__(16) float sm[];
    float* smQ  = sm;                 // [128][QKSTR]
    float* smKV = sm + QTSZ;          // (K|V) x2 ping-pong
    __shared__ int red[4][8];         // per-warp range reduction slots

    const int tid  = threadIdx.x;
    const int lane = tid & 31;
    const int wid  = tid >> 5;             // 0..7 : q-row group
    const int rr   = lane >> 2;            // 0..7
    const int qj   = lane & 3;             // 0..3

    const int hb = (br * 2 + b) * 16 + h;
    const float* __restrict__ qg = g_q + (size_t)hb * HBQK + (size_t)qt * QTSZ;
    const float* __restrict__ kg = g_k + (size_t)hb * HBQK;
    const float* __restrict__ vg = g_v + (size_t)hb * HBV;

    // ---- stage Q tile (packed layout mirrors gmem: straight copy)
    #pragma unroll
    for (int it = 0; it < 9; it++) {
        const int flat = it * 1024 + tid * 4;
        *(float4*)&smQ[flat] = *(const float4*)(qg + flat);
    }

    const int rowa  = wid * 16 + rr;
    const int qrow0 = qt * 128 + rowa;
    const int qrow1 = qrow0 + 8;
    const int lo0 = g_lo[b][qrow0], hi0 = g_hi[b][qrow0];
    const int lo1 = g_lo[b][qrow1], hi1 = g_hi[b][qrow1];
    const unsigned rng0 = (unsigned)(hi0 - lo0);
    const unsigned rng1 = (unsigned)(hi1 - lo1);
    const int total = g_total[b];

    // ---- deterministic block-range reduction (NO init/atomic race):
    // shfl warp-reduce, lane0 -> shared slot, syncthreads, scalar combine.
    int tmin = min(lo0, lo1);
    int tmax = max(hi0, hi1);
    int tglo = max(lo0, lo1);
    int tghi = min(hi0, hi1);
    #pragma unroll
    for (int off = 16; off > 0; off >>= 1) {
        tmin = min(tmin, __shfl_xor_sync(0xffffffffu, tmin, off));
        tmax = max(tmax, __shfl_xor_sync(0xffffffffu, tmax, off));
        tglo = max(tglo, __shfl_xor_sync(0xffffffffu, tglo, off));
        tghi = min(tghi, __shfl_xor_sync(0xffffffffu, tghi, off));
    }
    if (lane == 0) {
        red[0][wid] = tmin; red[1][wid] = tmax;
        red[2][wid] = tglo; red[3][wid] = tghi;
    }
    __syncthreads();   // also makes smQ staging visible before fragment reads
    int klo = red[0][0], khi = red[1][0], glo = red[2][0], ghi = red[3][0];
    #pragma unroll
    for (int w = 1; w < 8; w++) {
        klo = min(klo, red[0][w]); khi = max(khi, red[1][w]);
        glo = max(glo, red[2][w]); ghi = min(ghi, red[3][w]);
    }

    const int ktEnd = (total + 63) >> 6;
    int kt0, kt1, skipA, skipB;
    if (intra) {
        kt0 = klo >> 6;
        kt1 = (khi + 63) >> 6;
        skipA = 0; skipB = 0;
    } else {
        kt0 = 0;
        kt1 = ktEnd;
        skipA = min((glo + 63) >> 6, kt1);   // tiles fully inside every row's own chain
        skipB = min(ghi >> 6, kt1);
        if (skipA >= skipB) { skipA = 0; skipB = 0; }
        if (kt0 >= skipA && kt0 < skipB && skipB > skipA) kt0 = skipB;
    }

    float o[8][4];
    #pragma unroll
    for (int i = 0; i < 8; i++)
        #pragma unroll
        for (int j = 0; j < 4; j++) o[i][j] = 0.0f;

    float m0 = -INFINITY, m1 = -INFINITY, l0 = 0.0f, l1 = 0.0f;

    if (kt0 < kt1) {
        // ---- prologue: async load first tile (K span 4608, V span 4352)
        {
            float* Kb = smKV;
            float* Vb = smKV + KSPAN;
            const float* kgt = kg + (size_t)kt0 * KSPAN;
            const float* vgt = vg + (size_t)kt0 * VSPAN;
            #pragma unroll
            for (int it = 0; it < 5; it++) {
                const int ch = it * 256 + tid;
                if (ch < KSPAN / 4) cp16(&Kb[ch * 4], kgt + ch * 4);
                if (ch < VSPAN / 4) cp16(&Vb[ch * 4], vgt + ch * 4);
            }
            CP_COMMIT();
        }

        int kt = kt0, ping = 0;
        while (kt < kt1) {
            CP_WAIT0();
            __syncthreads();

            int nkt = kt + 1;
            if (nkt >= skipA && nkt < skipB) nkt = skipB;
            if (nkt < kt1) {
                float* Kb = smKV + (ping ^ 1) * KVSPAN;
                float* Vb = Kb + KSPAN;
                const float* kgt = kg + (size_t)nkt * KSPAN;
                const float* vgt = vg + (size_t)nkt * VSPAN;
                #pragma unroll
                for (int it = 0; it < 5; it++) {
                    const int ch = it * 256 + tid;
                    if (ch < KSPAN / 4) cp16(&Kb[ch * 4], kgt + ch * 4);
                    if (ch < VSPAN / 4) cp16(&Vb[ch * 4], vgt + ch * 4);
                }
                CP_COMMIT();
            }

            const float* Kc = smKV + ping * KVSPAN;
            const float* Vc = Kc + KSPAN;

            // ---- S = Q K^T : packed fragments, all LDS.64, conflict-free
            float sv[8][4];
            #pragma unroll
            for (int i = 0; i < 8; i++)
                #pragma unroll
                for (int j = 0; j < 4; j++) sv[i][j] = 0.0f;

            #pragma unroll
            for (int ks = 0; ks < 8; ks++) {
                const int cbase = ks * 8 + 2 * qj;
                const float2 qlo = *(const float2*)&smQ[rowa * QKSTR + cbase];
                const float2 qhi = *(const float2*)&smQ[(rowa + 8) * QKSTR + cbase];
                uint32_t qf[4];
                qf[0] = __float_as_uint(qlo.x);
                qf[1] = __float_as_uint(qhi.x);
                qf[2] = __float_as_uint(qlo.y);
                qf[3] = __float_as_uint(qhi.y);
                #pragma unroll
                for (int ni = 0; ni < 8; ni++) {
                    const float2 kk = *(const float2*)&Kc[(ni * 8 + rr) * QKSTR + cbase];
                    uint32_t bf[2];
                    bf[0] = __float_as_uint(kk.x);
                    bf[1] = __float_as_uint(kk.y);
                    mma8(sv[ni], qf, bf);
                }
            }

            // ---- mask via contiguous chain ranges
            const int colb = kt * 64 + 2 * qj;
            #pragma unroll
            for (int ni = 0; ni < 8; ni++) {
                const int c0 = colb + ni * 8;
                const int c1 = c0 + 1;
                const bool in00 = (unsigned)(c0 - lo0) < rng0;
                const bool in01 = (unsigned)(c1 - lo0) < rng0;
                const bool in10 = (unsigned)(c0 - lo1) < rng1;
                const bool in11 = (unsigned)(c1 - lo1) < rng1;
                bool a00, a01, a10, a11;
                if (intra) {
                    a00 = in00; a01 = in01; a10 = in10; a11 = in11;
                } else {
                    a00 = (c0 < total) && !in00;
                    a01 = (c1 < total) && !in01;
                    a10 = (c0 < total) && !in10;
                    a11 = (c1 < total) && !in11;
                }
                sv[ni][0] = a00 ? sv[ni][0] : -INFINITY;
                sv[ni][1] = a01 ? sv[ni][1] : -INFINITY;
                sv[ni][2] = a10 ? sv[ni][2] : -INFINITY;
                sv[ni][3] = a11 ? sv[ni][3] : -INFINITY;
            }

            // ---- register online softmax
            float tmax0 = -INFINITY, tmax1 = -INFINITY;
            #pragma unroll
            for (int ni = 0; ni < 8; ni++) {
                tmax0 = fmaxf(tmax0, fmaxf(sv[ni][0], sv[ni][1]));
                tmax1 = fmaxf(tmax1, fmaxf(sv[ni][2], sv[ni][3]));
            }
            tmax0 = fmaxf(tmax0, __shfl_xor_sync(0xffffffffu, tmax0, 1));
            tmax0 = fmaxf(tmax0, __shfl_xor_sync(0xffffffffu, tmax0, 2));
            tmax1 = fmaxf(tmax1, __shfl_xor_sync(0xffffffffu, tmax1, 1));
            tmax1 = fmaxf(tmax1, __shfl_xor_sync(0xffffffffu, tmax1, 2));

            const float mn0 = fmaxf(m0, tmax0);
            const float mn1 = fmaxf(m1, tmax1);
            float af0, af1, ts0 = 0.0f, ts1 = 0.0f;

            if (mn0 == -INFINITY) {
                af0 = 1.0f;
                #pragma unroll
                for (int ni = 0; ni < 8; ni++) { sv[ni][0] = 0.0f; sv[ni][1] = 0.0f; }
            } else {
                af0 = __expf(m0 - mn0);
                #pragma unroll
                for (int ni = 0; ni < 8; ni++) {
                    float p0 = to_tf32(__expf(sv[ni][0] - mn0));
                    float p1 = to_tf32(__expf(sv[ni][1] - mn0));
                    ts0 += p0 + p1;
                    sv[ni][0] = p0; sv[ni][1] = p1;
                }
            }
            if (mn1 == -INFINITY) {
                af1 = 1.0f;
                #pragma unroll
                for (int ni = 0; ni < 8; ni++) { sv[ni][2] = 0.0f; sv[ni][3] = 0.0f; }
            } else {
                af1 = __expf(m1 - mn1);
                #pragma unroll
                for (int ni = 0; ni < 8; ni++) {
                    float p2 = to_tf32(__expf(sv[ni][2] - mn1));
                    float p3 = to_tf32(__expf(sv[ni][3] - mn1));
                    ts1 += p2 + p3;
                    sv[ni][2] = p2; sv[ni][3] = p3;
                }
            }
            ts0 += __shfl_xor_sync(0xffffffffu, ts0, 1);
            ts0 += __shfl_xor_sync(0xffffffffu, ts0, 2);
            ts1 += __shfl_xor_sync(0xffffffffu, ts1, 1);
            ts1 += __shfl_xor_sync(0xffffffffu, ts1, 2);
            l0 = l0 * af0 + ts0;  m0 = mn0;
            l1 = l1 * af1 + ts1;  m1 = mn1;

            // ---- rescale O, then O += P V (V row-pair packed -> float2)
            #pragma unroll
            for (int ni = 0; ni < 8; ni++) {
                o[ni][0] *= af0; o[ni][1] *= af0;
                o[ni][2] *= af1; o[ni][3] *= af1;
            }
            #pragma unroll
            for (int ks = 0; ks < 8; ks++) {
                uint32_t pa[4];
                pa[0] = __float_as_uint(sv[ks][0]);
                pa[1] = __float_as_uint(sv[ks][2]);
                pa[2] = __float_as_uint(sv[ks][1]);
                pa[3] = __float_as_uint(sv[ks][3]);
                const int vbase = (ks * 4 + qj) * 136;    // rows (8ks+2qj, +1)
                #pragma unroll
                for (int ni = 0; ni < 8; ni++) {
                    const float2 vv = *(const float2*)&Vc[vbase + 2 * (ni * 8 + rr)];
                    uint32_t bf[2];
                    bf[0] = __float_as_uint(vv.x);
                    bf[1] = __float_as_uint(vv.y);
                    mma8(o[ni], pa, bf);
                }
            }

            kt = nkt;
            ping ^= 1;
        }
    }

    // ---- epilogue: normalize and store
    const float inv0 = (l0 > 0.0f) ? (1.0f / l0) : 0.0f;
    const float inv1 = (l1 > 0.0f) ? (1.0f / l1) : 0.0f;
    float* __restrict__ out0 = &g_attn[br][(size_t)b * Lv + qrow0][h * 64];
    float* __restrict__ out1 = &g_attn[br][(size_t)b * Lv + qrow1][h * 64];
    #pragma unroll
    for (int ni = 0; ni < 8; ni++) {
        const int cc = ni * 8 + 2 * qj;
        float2 u;
        u.x = o[ni][0] * inv0; u.y = o[ni][1] * inv0;
        *(float2*)&out0[cc] = u;
        u.x = o[ni][2] * inv1; u.y = o[ni][3] * inv1;
        *(float2*)&out1[cc] = u;
    }
}

// ---------------- output GEMM (tf32): 128x64, 2 CTA/SM ----------------------
__global__ void __launch_bounds__(256, 2) out_gemm(
    const float* __restrict__ W, const float* __restrict__ bias,
    float* __restrict__ Y)
{
    const int m0 = blockIdx.y * GBM;
    const int n0 = blockIdx.x * GBN;

    extern __shared__ __align__(16) float gsm[];
    float* As = gsm;
    float* Bs = gsm + 2 * GBM * GSTR;

    const int tid  = threadIdx.x;
    const int lane = tid & 31;
    const int wid  = tid >> 5;
    const int wm   = (wid >> 1) * 32;
    const int wn   = (wid & 1) * 32;

    const int lrow0 = tid >> 3;
    const int lc4   = (tid & 7) * 4;

    const float* A0 = &g_attn[0][0][0];
    const float* A1 = &g_attn[1][0][0];

    float4 ra[4], rb[2];
    #pragma unroll
    for (int it = 0; it < 4; it++) {
        const int row = lrow0 + it * 32;
        float4 x = *(const float4*)&A0[(size_t)(m0 + row) * Dv + lc4];
        float4 y = *(const float4*)&A1[(size_t)(m0 + row) * Dv + lc4];
        ra[it].x = x.x + y.x; ra[it].y = x.y + y.y;
        ra[it].z = x.z + y.z; ra[it].w = x.w + y.w;
    }
    #pragma unroll
    for (int it = 0; it < 2; it++)
        rb[it] = *(const float4*)&W[(size_t)(n0 + lrow0 + it * 32) * Dv + lc4];

    #pragma unroll
    for (int it = 0; it < 4; it++) {
        float* a = &As[(lrow0 + it * 32) * GSTR + lc4];
        a[0] = to_tf32(ra[it].x); a[1] = to_tf32(ra[it].y);
        a[2] = to_tf32(ra[it].z); a[3] = to_tf32(ra[it].w);
    }
    #pragma unroll
    for (int it = 0; it < 2; it++) {
        float* bp = &Bs[(lrow0 + it * 32) * GSTR + lc4];
        bp[0] = to_tf32(rb[it].x); bp[1] = to_tf32(rb[it].y);
        bp[2] = to_tf32(rb[it].z); bp[3] = to_tf32(rb[it].w);
    }
    __syncthreads();

    float acc[2][4][4];
    #pragma unroll
    for (int i = 0; i < 2; i++)
        #pragma unroll
        for (int j = 0; j < 4; j++)
            #pragma unroll
            for (int k = 0; k < 4; k++) acc[i][j][k] = 0.0f;

    int buf = 0;
    for (int kt = 0; kt < Dv; kt += GBK, buf ^= 1) {
        const bool more = (kt + GBK) < Dv;
        if (more) {
            #pragma unroll
            for (int it = 0; it < 4; it++) {
                const int row = lrow0 + it * 32;
                float4 x = *(const float4*)&A0[(size_t)(m0 + row) * Dv + kt + GBK + lc4];
                float4 y = *(const float4*)&A1[(size_t)(m0 + row) * Dv + kt + GBK + lc4];
                ra[it].x = x.x + y.x; ra[it].y = x.y + y.y;
                ra[it].z = x.z + y.z; ra[it].w = x.w + y.w;
            }
            #pragma unroll
            for (int it = 0; it < 2; it++)
                rb[it] = *(const float4*)&W[(size_t)(n0 + lrow0 + it * 32) * Dv + kt + GBK + lc4];
        }

        const float* Ac = As + buf * GBM * GSTR;
        const float* Bc = Bs + buf * GBN * GSTR;
        #pragma unroll
        for (int ks = 0; ks < 4; ks++) {
            const int kc = ks * 8 + (lane & 3);
            uint32_t af[2][4];
            #pragma unroll
            for (int mi = 0; mi < 2; mi++) {
                const int ar = wm + mi * 16 + (lane >> 2);
                af[mi][0] = __float_as_uint(Ac[ar * GSTR + kc]);
                af[mi][1] = __float_as_uint(Ac[(ar + 8) * GSTR + kc]);
                af[mi][2] = __float_as_uint(Ac[ar * GSTR + kc + 4]);
                af[mi][3] = __float_as_uint(Ac[(ar + 8) * GSTR + kc + 4]);
            }
            uint32_t bf[4][2];
            #pragma unroll
            for (int ni = 0; ni < 4; ni++) {
                const int brr = wn + ni * 8 + (lane >> 2);
                bf[ni][0] = __float_as_uint(Bc[brr * GSTR + kc]);
                bf[ni][1] = __float_as_uint(Bc[brr * GSTR + kc + 4]);
            }
            #pragma unroll
            for (int mi = 0; mi < 2; mi++)
                #pragma unroll
                for (int ni = 0; ni < 4; ni++)
                    mma8(acc[mi][ni], af[mi], bf[ni]);
        }

        if (more) {
            float* An = As + (buf ^ 1) * GBM * GSTR;
            float* Bn = Bs + (buf ^ 1) * GBN * GSTR;
            #pragma unroll
            for (int it = 0; it < 4; it++) {
                float* a = &An[(lrow0 + it * 32) * GSTR + lc4];
                a[0] = to_tf32(ra[it].x); a[1] = to_tf32(ra[it].y);
                a[2] = to_tf32(ra[it].z); a[3] = to_tf32(ra[it].w);
            }
            #pragma unroll
            for (int it = 0; it < 2; it++) {
                float* bp = &Bn[(lrow0 + it * 32) * GSTR + lc4];
                bp[0] = to_tf32(rb[it].x); bp[1] = to_tf32(rb[it].y);
                bp[2] = to_tf32(rb[it].z); bp[3] = to_tf32(rb[it].w);
            }
        }
        __syncthreads();
    }

    #pragma unroll
    for (int mi = 0; mi < 2; mi++)
        #pragma unroll
        for (int ni = 0; ni < 4; ni++) {
            const int r = m0 + wm + mi * 16 + (lane >> 2);
            const int c = n0 + wn + ni * 8 + 2 * (lane & 3);
            const float bx = bias[c], by = bias[c + 1];
            float2 v;
            v.x = acc[mi][ni][0] + bx; v.y = acc[mi][ni][1] + by;
            *(float2*)&Y[(size_t)r * Dv + c] = v;
            v.x = acc[mi][ni][2] + bx; v.y = acc[mi][ni][3] + by;
            *(float2*)&Y[(size_t)(r + 8) * Dv + c] = v;
        }
}

// ---------------- launcher --------------------------------------------------
extern "C" void kernel_launch(void* const* d_in, const int* in_sizes, int n_in,
                              void* d_out, int out_size)
{
    const float* hidden = (const float*)d_in[0];
    const void*  mask   = d_in[1];
    const float* Wi = (const float*)d_in[2];
    const float* bi = (const float*)d_in[3];
    const float* We = (const float*)d_in[4];
    const float* be = (const float*)d_in[5];
    const float* Wo = (const float*)d_in[6];
    const float* bo = (const float*)d_in[7];
    float* out = (float*)d_out;

    meta_kernel<<<Bv, 256>>>(mask);

    cudaFuncSetAttribute(qkv_gemm, cudaFuncAttributeMaxDynamicSharedMemorySize, GEMM_SMEM);
    dim3 g1(N3D / GBN, ML / GBM, 2);
    qkv_gemm<<<g1, 256, GEMM_SMEM>>>(hidden, Wi, bi, We, be);

    prep_kernel<<<4096, 1024>>>();

    cudaFuncSetAttribute(attn_kernel, cudaFuncAttributeMaxDynamicSharedMemorySize, ATTN_SMEM);
    dim3 g2(64, Hv);   // x = qt*4 + b*2 + br (interleaved long/short blocks)
    attn_kernel<<<g2, 256, ATTN_SMEM>>>();

    cudaFuncSetAttribute(out_gemm, cudaFuncAttributeMaxDynamicSharedMemorySize, GEMM_SMEM);
    dim3 g3(Dv / GBN, ML / GBM);
    out_gemm<<<g3, 256, GEMM_SMEM>>>(Wo, bo, out);
}